// round 11
// baseline (speedup 1.0000x reference)
#include <cuda_runtime.h>
#include <cuda_bf16.h>
#include <math.h>
#include <stdint.h>

// Problem dims (fixed by the dataset)
constexpr int Nn  = 4000;
constexpr int Ee  = 50000;
constexpr int NGg = 12;
constexpr int Hh  = 128;
constexpr int BDd = 128;
constexpr int Ll  = 2;
constexpr int Bb  = 100;

constexpr int EROWS = Ee * NGg;     // 600000
constexpr int NROWS = Nn * NGg;     // 48000

// ---------------- scratch (device globals; no cudaMalloc allowed) -------------
__device__ __align__(16) float g_grid_node[Nn * NGg * 3];
__device__ __align__(16) float g_eipoly[EROWS * 12];
__device__ __align__(16) __nv_bfloat16 g_bufA_hi[(size_t)EROWS * Hh];  // h1 split
__device__ __align__(16) __nv_bfloat16 g_bufA_lo[(size_t)EROWS * Hh];
__device__ __align__(16) __nv_bfloat16 g_basis_hi[(size_t)EROWS * Hh];
__device__ __align__(16) __nv_bfloat16 g_basis_lo[(size_t)EROWS * Hh];
__device__ __align__(16) float g_kern[(size_t)EROWS * Hh];             // per-layer kern
__device__ __align__(16) float g_x  [NROWS * Hh];
__device__ __align__(16) float g_x2 [NROWS * Hh];
__device__ __align__(16) float g_ro [NROWS * Hh];                      // readout hidden
__device__ __align__(16) __nv_bfloat16 g_ffh_hi[(size_t)NROWS * 4 * Hh];
__device__ __align__(16) __nv_bfloat16 g_ffh_lo[(size_t)NROWS * 4 * Hh];
__device__ __align__(16) float g_fipoly[NGg * NGg * 2];
__device__ __align__(16) float g_fh1   [NGg * NGg * Hh];
__device__ __align__(16) float g_fbasis[NGg * NGg * BDd];
__device__ __align__(16) float g_fk    [NGg * NGg * Hh];
__device__ float g_gsum[Bb * 4];   // per-graph: sum_x, sum_y, sum_z, count
// CSR by destination
__device__ int g_deg[Nn];
__device__ int g_off[Nn + 1];
__device__ int g_cur[Nn];
__device__ int g_csr[Ee];

__device__ __forceinline__ float gelu_f(float x) {
    return 0.5f * x * (1.0f + erff(x * 0.70710678118654752f));
}

// ---------------- tiny kernels -------------------------------------------------
__global__ void k_zero_int(int* p, int n) {
    int i = blockIdx.x * blockDim.x + threadIdx.x;
    if (i < n) p[i] = 0;
}

__global__ void k_zero(float* p, int n) {
    int i = blockIdx.x * blockDim.x + threadIdx.x;
    if (i < n) p[i] = 0.f;
}

__global__ void k_gsum(const float* __restrict__ pos, const int* __restrict__ batch) {
    int n = blockIdx.x * blockDim.x + threadIdx.x;
    if (n >= Nn) return;
    int b = batch[n];
    atomicAdd(&g_gsum[b * 4 + 0], pos[n * 3 + 0]);
    atomicAdd(&g_gsum[b * 4 + 1], pos[n * 3 + 1]);
    atomicAdd(&g_gsum[b * 4 + 2], pos[n * 3 + 2]);
    atomicAdd(&g_gsum[b * 4 + 3], 1.f);
}

__global__ void k_grid_node(const int* __restrict__ batch,
                            const float* __restrict__ grid0,
                            const float* __restrict__ R) {
    int idx = blockIdx.x * blockDim.x + threadIdx.x;  // n*NG + k
    if (idx >= Nn * NGg) return;
    int n = idx / NGg, k = idx % NGg;
    const float* Rb = R + batch[n] * 9;
    float gx = grid0[k * 3 + 0], gy = grid0[k * 3 + 1], gz = grid0[k * 3 + 2];
    float* o = g_grid_node + idx * 3;
    o[0] = Rb[0] * gx + Rb[1] * gy + Rb[2] * gz;
    o[1] = Rb[3] * gx + Rb[4] * gy + Rb[5] * gz;
    o[2] = Rb[6] * gx + Rb[7] * gy + Rb[8] * gz;
}

__global__ void k_eipoly(const float* __restrict__ pos,
                         const float* __restrict__ charges,
                         const int* __restrict__ eidx) {
    int idx = blockIdx.x * blockDim.x + threadIdx.x;  // e*NG + k
    if (idx >= EROWS) return;
    int e = idx / NGg, k = idx % NGg;
    int s = eidx[e], d = eidx[Ee + e];
    float rx = pos[s * 3 + 0] - pos[d * 3 + 0];
    float ry = pos[s * 3 + 1] - pos[d * 3 + 1];
    float rz = pos[s * 3 + 2] - pos[d * 3 + 2];
    const float* g = g_grid_node + (s * NGg + k) * 3;
    float inv1 = rx * g[0] + ry * g[1] + rz * g[2];
    float vx = rx - inv1 * g[0], vy = ry - inv1 * g[1], vz = rz - inv1 * g[2];
    float inv2 = sqrtf(vx * vx + vy * vy + vz * vz);
    float cp = charges[s] * charges[d];
    float e0 = inv1, e1 = inv2, e2 = cp;
    float* o = g_eipoly + (size_t)idx * 12;
    o[0] = e0;  o[1] = e1;  o[2] = e2;
    o[3] = e0 * e0; o[4]  = e0 * e1; o[5]  = e0 * e2;
    o[6] = e1 * e0; o[7]  = e1 * e1; o[8]  = e1 * e2;
    o[9] = e2 * e0; o[10] = e2 * e1; o[11] = e2 * e2;
}

__global__ void k_fipoly(const float* __restrict__ grid0) {
    int idx = threadIdx.x;
    if (idx >= NGg * NGg) return;
    int p = idx / NGg, o = idx % NGg;
    float fi = grid0[p * 3 + 0] * grid0[o * 3 + 0] +
               grid0[p * 3 + 1] * grid0[o * 3 + 1] +
               grid0[p * 3 + 2] * grid0[o * 3 + 2];
    g_fipoly[idx * 2 + 0] = fi;
    g_fipoly[idx * 2 + 1] = fi * fi;
}

// naive GEMM for tiny fiber matrices (M=144) — fp32, negligible time
__global__ void k_small_gemm(const float* __restrict__ A, const float* __restrict__ W,
                             const float* __restrict__ bias, float* __restrict__ C,
                             int M, int N, int K, int act) {
    int idx = blockIdx.x * blockDim.x + threadIdx.x;
    if (idx >= M * N) return;
    int r = idx / N, c = idx % N;
    float acc = bias ? bias[c] : 0.f;
    for (int k = 0; k < K; k++) acc = fmaf(A[r * K + k], W[k * N + c], acc);
    C[idx] = act ? gelu_f(acc) : acc;
}

__global__ void k_embed(const float* __restrict__ pos, const float* __restrict__ vel,
                        const float* __restrict__ charges, const int* __restrict__ batch,
                        const float* __restrict__ We) {
    int nk = blockIdx.x;           // n*NG + k
    int h = threadIdx.x;           // 0..127
    int n = nk / NGg;
    const float* g = g_grid_node + nk * 3;
    float vx = vel[n * 3 + 0], vy = vel[n * 3 + 1], vz = vel[n * 3 + 2];
    int b = batch[n];
    float cnt = fmaxf(g_gsum[b * 4 + 3], 1.f);
    float rpx = pos[n * 3 + 0] - g_gsum[b * 4 + 0] / cnt;
    float rpy = pos[n * 3 + 1] - g_gsum[b * 4 + 1] / cnt;
    float rpz = pos[n * 3 + 2] - g_gsum[b * 4 + 2] / cnt;
    float f0 = vx * g[0] + vy * g[1] + vz * g[2];
    float f1 = rpx * g[0] + rpy * g[1] + rpz * g[2];
    float f2 = charges[n];
    float f3 = sqrtf(vx * vx + vy * vy + vz * vz);
    g_x[(size_t)nk * Hh + h] =
        f0 * We[h] + f1 * We[Hh + h] + f2 * We[2 * Hh + h] + f3 * We[3 * Hh + h];
}

// ---------------- CSR build (by destination) ------------------------------------
__global__ void k_count(const int* __restrict__ eidx) {
    int e = blockIdx.x * blockDim.x + threadIdx.x;
    if (e >= Ee) return;
    atomicAdd(&g_deg[eidx[Ee + e]], 1);
}

// single-block exclusive scan of g_deg[0..Nn) -> g_off
__global__ void k_scan() {
    __shared__ int sh[1024];
    int tid = threadIdx.x;
    int base = tid * 4;
    int v[4];
    int s0 = 0;
#pragma unroll
    for (int i = 0; i < 4; i++) {
        int idx = base + i;
        v[i] = (idx < Nn) ? g_deg[idx] : 0;
        s0 += v[i];
    }
    sh[tid] = s0;
    __syncthreads();
    for (int off = 1; off < 1024; off <<= 1) {
        int t = (tid >= off) ? sh[tid - off] : 0;
        __syncthreads();
        sh[tid] += t;
        __syncthreads();
    }
    int ex = sh[tid] - s0;   // exclusive prefix for this thread's chunk
#pragma unroll
    for (int i = 0; i < 4; i++) {
        int idx = base + i;
        if (idx < Nn) { g_off[idx] = ex; ex += v[i]; }
    }
    if (tid == 1023) g_off[Nn] = sh[1023];
}

__global__ void k_fill(const int* __restrict__ eidx) {
    int e = blockIdx.x * blockDim.x + threadIdx.x;
    if (e >= Ee) return;
    int d = eidx[Ee + e];
    int pos = g_off[d] + atomicAdd(&g_cur[d], 1);
    g_csr[pos] = e;
}

// ---------------- fused gather + fiber contraction + LayerNorm ------------------
// block = node n, thread = channel c.
__global__ void __launch_bounds__(128) k_gather_fiber_ln(
    const int* __restrict__ eidx,
    const float* __restrict__ bconv, const float* __restrict__ gamma,
    const float* __restrict__ beta) {
    int n = blockIdx.x;
    int c = threadIdx.x;
    float acc[NGg];
#pragma unroll
    for (int o = 0; o < NGg; o++) acc[o] = 0.f;

    const int beg = g_off[n], end = g_off[n + 1];
    for (int j = beg; j < end; j++) {
        int e = g_csr[j];
        int s = eidx[e];
        const float* kr = &g_kern[(size_t)e * NGg * Hh + c];
        const float* xr = &g_x[(size_t)s * NGg * Hh + c];
#pragma unroll
        for (int o = 0; o < NGg; o++)
            acc[o] = fmaf(kr[o * Hh], xr[o * Hh], acc[o]);
    }

    __shared__ float red[4];
    for (int p = 0; p < NGg; p++) {
        float v = 0.f;
        const float* fkp = &g_fk[(size_t)p * NGg * Hh + c];
#pragma unroll
        for (int o = 0; o < NGg; o++)
            v = fmaf(acc[o], fkp[o * Hh], v);
        v = v * (1.0f / NGg) + bconv[c];

        float s = v;
#pragma unroll
        for (int off = 16; off > 0; off >>= 1) s += __shfl_down_sync(0xffffffffu, s, off);
        if ((c & 31) == 0) red[c >> 5] = s;
        __syncthreads();
        float mean = (red[0] + red[1] + red[2] + red[3]) * (1.f / Hh);
        __syncthreads();
        float dd = v - mean;
        s = dd * dd;
#pragma unroll
        for (int off = 16; off > 0; off >>= 1) s += __shfl_down_sync(0xffffffffu, s, off);
        if ((c & 31) == 0) red[c >> 5] = s;
        __syncthreads();
        float var = (red[0] + red[1] + red[2] + red[3]) * (1.f / Hh);
        g_x2[((size_t)n * NGg + p) * Hh + c] = dd * rsqrtf(var + 1e-5f) * gamma[c] + beta[c];
        __syncthreads();
    }
}

// out[n,d] = (1/NG) sum_k grid_node[n,k,d] * (t[n,k,:]·W_ro2 + b_ro2)
__global__ void k_output(const float* __restrict__ Wro2, const float* __restrict__ bro2,
                         float* __restrict__ out) {
    int n = blockIdx.x;
    int h = threadIdx.x;
    __shared__ float red[4];
    __shared__ float ybc;
    float a0 = 0.f, a1 = 0.f, a2 = 0.f;
    for (int k = 0; k < NGg; k++) {
        float s = g_ro[((size_t)(n * NGg + k)) * Hh + h] * Wro2[h];
#pragma unroll
        for (int off = 16; off > 0; off >>= 1) s += __shfl_down_sync(0xffffffffu, s, off);
        if ((h & 31) == 0) red[h >> 5] = s;
        __syncthreads();
        if (h == 0) ybc = red[0] + red[1] + red[2] + red[3] + bro2[0];
        __syncthreads();
        float y = ybc;
        a0 += g_grid_node[(n * NGg + k) * 3 + 0] * y;
        a1 += g_grid_node[(n * NGg + k) * 3 + 1] * y;
        a2 += g_grid_node[(n * NGg + k) * 3 + 2] * y;
        __syncthreads();
    }
    if (h == 0) {
        out[n * 3 + 0] = a0 * (1.f / NGg);
        out[n * 3 + 1] = a1 * (1.f / NGg);
        out[n * 3 + 2] = a2 * (1.f / NGg);
    }
}

// ---------------- bf16x3 tensor-core GEMM (≈fp32 accuracy) ---------------------
// C = [act](A @ Bw + bias) [+= if ACCUM]
// ASPLIT: A supplied as pre-split bf16 hi/lo arrays (no convert in loader).
// OSPLIT: epilogue writes hi/lo bf16 arrays (for the next GEMM's ASPLIT input).
// A: MxK row-major (K % 4 == 0), Bw: KxN row-major, N % 128 == 0.
// Block 128x128, BK=32, 8 warps, warp tile 64x32 via mma.m16n8k16.bf16.
// Split x = hi + lo (hi = bf16(x), lo = bf16(x - hi)); D += hh + hl + lh.
constexpr int BM = 128, BN = 128, BK = 32;
constexpr int ASTRIDE = BK + 8;      // 40 bf16 per row -> conflict-free ldmatrix
constexpr int BSTRIDE = BN + 8;      // 136 bf16 per row -> conflict-free ldmatrix.trans

__device__ __forceinline__ void mma_bf16(float* d, const uint32_t* a, const uint32_t* b) {
    asm volatile(
        "mma.sync.aligned.m16n8k16.row.col.f32.bf16.bf16.f32 "
        "{%0,%1,%2,%3}, {%4,%5,%6,%7}, {%8,%9}, {%0,%1,%2,%3};\n"
        : "+f"(d[0]), "+f"(d[1]), "+f"(d[2]), "+f"(d[3])
        : "r"(a[0]), "r"(a[1]), "r"(a[2]), "r"(a[3]), "r"(b[0]), "r"(b[1]));
}

__device__ __forceinline__ void ldm_x4(uint32_t* r, const __nv_bfloat16* p) {
    uint32_t addr = (uint32_t)__cvta_generic_to_shared(p);
    asm volatile("ldmatrix.sync.aligned.m8n8.x4.shared.b16 {%0,%1,%2,%3}, [%4];"
                 : "=r"(r[0]), "=r"(r[1]), "=r"(r[2]), "=r"(r[3]) : "r"(addr));
}

__device__ __forceinline__ void ldm_x2t(uint32_t* r, const __nv_bfloat16* p) {
    uint32_t addr = (uint32_t)__cvta_generic_to_shared(p);
    asm volatile("ldmatrix.sync.aligned.m8n8.x2.trans.shared.b16 {%0,%1}, [%2];"
                 : "=r"(r[0]), "=r"(r[1]) : "r"(addr));
}

__device__ __forceinline__ void split_bf16(float v, __nv_bfloat16& hi, __nv_bfloat16& lo) {
    hi = __float2bfloat16_rn(v);
    lo = __float2bfloat16_rn(v - __bfloat162float(hi));
}

template <bool GELU, bool ACCUM, bool ASPLIT, bool OSPLIT>
__global__ void __launch_bounds__(256, 2) gemm_bf16x3(
    const float* __restrict__ A,
    const __nv_bfloat16* __restrict__ Ahi, const __nv_bfloat16* __restrict__ Alo,
    const float* __restrict__ Bw, const float* __restrict__ bias,
    float* __restrict__ C,
    __nv_bfloat16* __restrict__ Chi, __nv_bfloat16* __restrict__ Clo,
    int M, int N, int K) {
    __shared__ __nv_bfloat16 As1[BM][ASTRIDE];   // A hi
    __shared__ __nv_bfloat16 As2[BM][ASTRIDE];   // A lo
    __shared__ __nv_bfloat16 Bs1[BK][BSTRIDE];   // B hi (layout [k][n])
    __shared__ __nv_bfloat16 Bs2[BK][BSTRIDE];   // B lo

    const int tid  = threadIdx.x;
    const int lane = tid & 31;
    const int warp = tid >> 5;
    const int wm = warp & 1;             // 2 warps along M (64 rows each)
    const int wn = warp >> 1;            // 4 warps along N (32 cols each)
    const int br = blockIdx.x * BM;
    const int bc = blockIdx.y * BN;
    const int gid = lane >> 2;           // 0..7
    const int qid = lane & 3;            // 0..3

    float acc[4][4][4];
#pragma unroll
    for (int mt = 0; mt < 4; mt++)
#pragma unroll
        for (int nt = 0; nt < 4; nt++)
#pragma unroll
            for (int j = 0; j < 4; j++) acc[mt][nt][j] = 0.f;

    // ldmatrix per-thread source coordinates
    const int aRow = ((lane >> 3) & 1) * 8 + (lane & 7);  // within 16-row A tile
    const int aKof = (lane >> 4) * 8;                     // 0 or 8
    const int bK   = lane & 15;                           // 0..15 (k within 16-k step)

    const int ktiles = (K + BK - 1) / BK;
    for (int kt = 0; kt < ktiles; kt++) {
        const int k0 = kt * BK;
        // ---- load A tile: 128 rows x 32 k ----
#pragma unroll
        for (int it = 0; it < 4; it++) {
            int f = it * 256 + tid;
            int row = f >> 3, kq = (f & 7) * 4;
            int gr = br + row;
            bool ok = (gr < M) && ((k0 + kq) < K);
            if (ASPLIT) {
                uint2 hv = make_uint2(0u, 0u), lv = make_uint2(0u, 0u);
                if (ok) {
                    size_t idx = (size_t)gr * K + k0 + kq;
                    hv = *reinterpret_cast<const uint2*>(&Ahi[idx]);
                    lv = *reinterpret_cast<const uint2*>(&Alo[idx]);
                }
                *reinterpret_cast<uint2*>(&As1[row][kq]) = hv;
                *reinterpret_cast<uint2*>(&As2[row][kq]) = lv;
            } else {
                float4 v = make_float4(0.f, 0.f, 0.f, 0.f);
                if (ok)
                    v = *reinterpret_cast<const float4*>(&A[(size_t)gr * K + k0 + kq]);
                __nv_bfloat16 h0, h1, h2, h3, l0, l1, l2, l3;
                split_bf16(v.x, h0, l0); split_bf16(v.y, h1, l1);
                split_bf16(v.z, h2, l2); split_bf16(v.w, h3, l3);
                *reinterpret_cast<__nv_bfloat162*>(&As1[row][kq])     = __nv_bfloat162(h0, h1);
                *reinterpret_cast<__nv_bfloat162*>(&As1[row][kq + 2]) = __nv_bfloat162(h2, h3);
                *reinterpret_cast<__nv_bfloat162*>(&As2[row][kq])     = __nv_bfloat162(l0, l1);
                *reinterpret_cast<__nv_bfloat162*>(&As2[row][kq + 2]) = __nv_bfloat162(l2, l3);
            }
        }
        // ---- load + split B tile: 32 k x 128 n (weights, fp32) ----
#pragma unroll
        for (int it = 0; it < 4; it++) {
            int f = it * 256 + tid;
            int krow = f >> 5, n4 = (f & 31) * 4;
            float4 v = make_float4(0.f, 0.f, 0.f, 0.f);
            if ((k0 + krow) < K)
                v = *reinterpret_cast<const float4*>(&Bw[(size_t)(k0 + krow) * N + bc + n4]);
            __nv_bfloat16 h0, h1, h2, h3, l0, l1, l2, l3;
            split_bf16(v.x, h0, l0); split_bf16(v.y, h1, l1);
            split_bf16(v.z, h2, l2); split_bf16(v.w, h3, l3);
            *reinterpret_cast<__nv_bfloat162*>(&Bs1[krow][n4])     = __nv_bfloat162(h0, h1);
            *reinterpret_cast<__nv_bfloat162*>(&Bs1[krow][n4 + 2]) = __nv_bfloat162(h2, h3);
            *reinterpret_cast<__nv_bfloat162*>(&Bs2[krow][n4])     = __nv_bfloat162(l0, l1);
            *reinterpret_cast<__nv_bfloat162*>(&Bs2[krow][n4 + 2]) = __nv_bfloat162(l2, l3);
        }
        __syncthreads();

#pragma unroll
        for (int ks = 0; ks < 2; ks++) {
            const int kk = ks * 16;
            // B fragments for all 4 n-tiles (hi & lo)
            uint32_t bb[4][2], bs[4][2];
#pragma unroll
            for (int nt = 0; nt < 4; nt++) {
                const int n0 = wn * 32 + nt * 8;
                ldm_x2t(bb[nt], &Bs1[kk + bK][n0]);
                ldm_x2t(bs[nt], &Bs2[kk + bK][n0]);
            }
            // per m-tile: load a-frags, 3-term MMAs
#pragma unroll
            for (int mt = 0; mt < 4; mt++) {
                const int r0 = wm * 64 + mt * 16 + aRow;
                uint32_t ah[4], al[4];
                ldm_x4(ah, &As1[r0][kk + aKof]);
                ldm_x4(al, &As2[r0][kk + aKof]);
#pragma unroll
                for (int nt = 0; nt < 4; nt++) {
                    mma_bf16(acc[mt][nt], al, bb[nt]);   // lo·hi
                    mma_bf16(acc[mt][nt], ah, bs[nt]);   // hi·lo
                    mma_bf16(acc[mt][nt], ah, bb[nt]);   // hi·hi (largest last)
                }
            }
        }
        __syncthreads();
    }

    // epilogue: frag c0,c1 -> (row r0, cols c,c+1); c2,c3 -> (row r0+8)
#pragma unroll
    for (int nt = 0; nt < 4; nt++) {
        const int c = bc + wn * 32 + nt * 8 + qid * 2;
        float b0 = 0.f, b1 = 0.f;
        if (bias) { b0 = bias[c]; b1 = bias[c + 1]; }
#pragma unroll
        for (int mt = 0; mt < 4; mt++) {
            int r0 = br + wm * 64 + mt * 16 + gid;
#pragma unroll
            for (int half = 0; half < 2; half++) {
                int r = r0 + half * 8;
                if (r >= M) continue;
                float v0 = acc[mt][nt][half * 2 + 0] + b0;
                float v1 = acc[mt][nt][half * 2 + 1] + b1;
                if (GELU) { v0 = gelu_f(v0); v1 = gelu_f(v1); }
                if (OSPLIT) {
                    __nv_bfloat16 h0, l0, h1, l1;
                    split_bf16(v0, h0, l0);
                    split_bf16(v1, h1, l1);
                    *reinterpret_cast<__nv_bfloat162*>(&Chi[(size_t)r * N + c]) =
                        __nv_bfloat162(h0, h1);
                    *reinterpret_cast<__nv_bfloat162*>(&Clo[(size_t)r * N + c]) =
                        __nv_bfloat162(l0, l1);
                } else if (ACCUM) {
                    float2* p = reinterpret_cast<float2*>(&C[(size_t)r * N + c]);
                    float2 o = *p;
                    o.x += v0; o.y += v1;
                    *p = o;
                } else {
                    *reinterpret_cast<float2*>(&C[(size_t)r * N + c]) =
                        make_float2(v0, v1);
                }
            }
        }
    }
}

// ---------------- host launch wrappers --------------------------------------------
// fp32 A in, GELU, split bf16 out (basis1, FF1)
static void gemm_f32_gelu_osplit(const float* A, const float* W, const float* bias,
                                 __nv_bfloat16* Chi, __nv_bfloat16* Clo,
                                 int M, int N, int K) {
    dim3 grid((M + BM - 1) / BM, N / BN);
    gemm_bf16x3<true, false, false, true><<<grid, 256>>>(
        A, nullptr, nullptr, W, bias, nullptr, Chi, Clo, M, N, K);
}
// split A in, GELU, split out (basis2)
static void gemm_split_gelu_osplit(const __nv_bfloat16* Ahi, const __nv_bfloat16* Alo,
                                   const float* W, const float* bias,
                                   __nv_bfloat16* Chi, __nv_bfloat16* Clo,
                                   int M, int N, int K) {
    dim3 grid((M + BM - 1) / BM, N / BN);
    gemm_bf16x3<true, false, true, true><<<grid, 256>>>(
        nullptr, Ahi, Alo, W, bias, nullptr, Chi, Clo, M, N, K);
}
// split A in, plain fp32 out (kern)
static void gemm_split_plain(const __nv_bfloat16* Ahi, const __nv_bfloat16* Alo,
                             const float* W, float* C, int M, int N, int K) {
    dim3 grid((M + BM - 1) / BM, N / BN);
    gemm_bf16x3<false, false, true, false><<<grid, 256>>>(
        nullptr, Ahi, Alo, W, nullptr, C, nullptr, nullptr, M, N, K);
}
// split A in, accumulate into fp32 C (FF2)
static void gemm_split_accum(const __nv_bfloat16* Ahi, const __nv_bfloat16* Alo,
                             const float* W, const float* bias, float* C,
                             int M, int N, int K) {
    dim3 grid((M + BM - 1) / BM, N / BN);
    gemm_bf16x3<false, true, true, false><<<grid, 256>>>(
        nullptr, Ahi, Alo, W, bias, C, nullptr, nullptr, M, N, K);
}
// fp32 A in, GELU, fp32 out (ro1)
static void gemm_f32_gelu(const float* A, const float* W, const float* bias, float* C,
                          int M, int N, int K) {
    dim3 grid((M + BM - 1) / BM, N / BN);
    gemm_bf16x3<true, false, false, false><<<grid, 256>>>(
        A, nullptr, nullptr, W, bias, C, nullptr, nullptr, M, N, K);
}

extern "C" void kernel_launch(void* const* d_in, const int* in_sizes, int n_in,
                              void* d_out, int out_size) {
    const float* pos      = (const float*)d_in[0];
    const float* vel      = (const float*)d_in[1];
    const float* charges  = (const float*)d_in[2];
    const int*   batch    = (const int*)d_in[3];
    const int*   eidx     = (const int*)d_in[4];
    const float* grid0    = (const float*)d_in[5];
    const float* R        = (const float*)d_in[6];
    const float* W_basis1 = (const float*)d_in[7];
    const float* b_basis1 = (const float*)d_in[8];
    const float* W_basis2 = (const float*)d_in[9];
    const float* b_basis2 = (const float*)d_in[10];
    const float* W_fbasis1 = (const float*)d_in[11];
    const float* b_fbasis1 = (const float*)d_in[12];
    const float* W_fbasis2 = (const float*)d_in[13];
    const float* b_fbasis2 = (const float*)d_in[14];
    const float* W_embed  = (const float*)d_in[15];
    const float* W_conv   = (const float*)d_in[16];
    const float* W_fiber  = (const float*)d_in[17];
    const float* b_conv   = (const float*)d_in[18];
    const float* ln_gamma = (const float*)d_in[19];
    const float* ln_beta  = (const float*)d_in[20];
    const float* W_ff1    = (const float*)d_in[21];
    const float* b_ff1    = (const float*)d_in[22];
    const float* W_ff2    = (const float*)d_in[23];
    const float* b_ff2    = (const float*)d_in[24];
    const float* W_ro1    = (const float*)d_in[25];
    const float* b_ro1    = (const float*)d_in[26];
    const float* W_ro2    = (const float*)d_in[27];
    const float* b_ro2    = (const float*)d_in[28];
    float* out = (float*)d_out;

    float *kern, *x, *x2, *ro, *eip, *fip, *fh1, *fbasis, *fk, *gsum;
    __nv_bfloat16 *bufAhi, *bufAlo, *basishi, *basislo, *ffhhi, *ffhlo;
    int *deg, *cur;
    cudaGetSymbolAddress((void**)&bufAhi,  g_bufA_hi);
    cudaGetSymbolAddress((void**)&bufAlo,  g_bufA_lo);
    cudaGetSymbolAddress((void**)&basishi, g_basis_hi);
    cudaGetSymbolAddress((void**)&basislo, g_basis_lo);
    cudaGetSymbolAddress((void**)&kern,    g_kern);
    cudaGetSymbolAddress((void**)&x,       g_x);
    cudaGetSymbolAddress((void**)&x2,      g_x2);
    cudaGetSymbolAddress((void**)&ro,      g_ro);
    cudaGetSymbolAddress((void**)&ffhhi,   g_ffh_hi);
    cudaGetSymbolAddress((void**)&ffhlo,   g_ffh_lo);
    cudaGetSymbolAddress((void**)&eip,     g_eipoly);
    cudaGetSymbolAddress((void**)&fip,     g_fipoly);
    cudaGetSymbolAddress((void**)&fh1,     g_fh1);
    cudaGetSymbolAddress((void**)&fbasis,  g_fbasis);
    cudaGetSymbolAddress((void**)&fk,      g_fk);
    cudaGetSymbolAddress((void**)&gsum,    g_gsum);
    cudaGetSymbolAddress((void**)&deg,     g_deg);
    cudaGetSymbolAddress((void**)&cur,     g_cur);

    // graph statistics + rotated grids
    k_zero<<<(Bb * 4 + 255) / 256, 256>>>(gsum, Bb * 4);
    k_gsum<<<(Nn + 255) / 256, 256>>>(pos, batch);
    k_grid_node<<<(Nn * NGg + 255) / 256, 256>>>(batch, grid0, R);

    // CSR by destination (built once, reused by both layers)
    k_zero_int<<<(Nn + 255) / 256, 256>>>(deg, Nn);
    k_zero_int<<<(Nn + 255) / 256, 256>>>(cur, Nn);
    k_count<<<(Ee + 255) / 256, 256>>>(eidx);
    k_scan<<<1, 1024>>>();
    k_fill<<<(Ee + 255) / 256, 256>>>(eidx);

    // edge basis MLP: 600k rows (hidden + basis stored pre-split bf16)
    k_eipoly<<<(EROWS + 255) / 256, 256>>>(pos, charges, eidx);
    gemm_f32_gelu_osplit(eip, W_basis1, b_basis1, bufAhi, bufAlo, EROWS, Hh, 12);
    gemm_split_gelu_osplit(bufAhi, bufAlo, W_basis2, b_basis2, basishi, basislo,
                           EROWS, BDd, Hh);

    // fiber basis MLP: 144 rows
    k_fipoly<<<1, 256>>>(grid0);
    k_small_gemm<<<(NGg * NGg * Hh + 255) / 256, 256>>>(fip, W_fbasis1, b_fbasis1, fh1,
                                                        NGg * NGg, Hh, 2, 1);
    k_small_gemm<<<(NGg * NGg * BDd + 255) / 256, 256>>>(fh1, W_fbasis2, b_fbasis2, fbasis,
                                                         NGg * NGg, BDd, Hh, 1);

    // node embedding
    k_embed<<<NROWS, Hh>>>(pos, vel, charges, batch, W_embed);

    for (int l = 0; l < Ll; l++) {
        // kern = basis @ W_conv[l]  (600k x 128 x 128, split-A input)
        gemm_split_plain(basishi, basislo, W_conv + (size_t)l * BDd * Hh, kern,
                         EROWS, Hh, BDd);
        // fk = fiber_basis @ W_fiber[l]
        k_small_gemm<<<(NGg * NGg * Hh + 255) / 256, 256>>>(
            fbasis, W_fiber + (size_t)l * BDd * Hh, nullptr, fk, NGg * NGg, Hh, BDd, 0);
        // fused: x1 = gather-sum(kern * x[src] -> dst); x2 = LN(fiber(x1))
        k_gather_fiber_ln<<<Nn, Hh>>>(eidx, b_conv + l * Hh, ln_gamma + l * Hh,
                                      ln_beta + l * Hh);
        // FF: x += W_ff2 @ gelu(W_ff1 @ h)   (hidden stored pre-split bf16)
        gemm_f32_gelu_osplit(x2, W_ff1 + (size_t)l * Hh * 4 * Hh, b_ff1 + l * 4 * Hh,
                             ffhhi, ffhlo, NROWS, 4 * Hh, Hh);
        gemm_split_accum(ffhhi, ffhlo, W_ff2 + (size_t)l * 4 * Hh * Hh, b_ff2 + l * Hh,
                         x, NROWS, Hh, 4 * Hh);
    }

    // readout
    gemm_f32_gelu(x, W_ro1, b_ro1, ro, NROWS, Hh, Hh);
    k_output<<<Nn, Hh>>>(W_ro2, b_ro2, out);
}

// round 12
// speedup vs baseline: 1.1066x; 1.1066x over previous
#include <cuda_runtime.h>
#include <cuda_bf16.h>
#include <math.h>
#include <stdint.h>

// Problem dims (fixed by the dataset)
constexpr int Nn  = 4000;
constexpr int Ee  = 50000;
constexpr int NGg = 12;
constexpr int Hh  = 128;
constexpr int BDd = 128;
constexpr int Ll  = 2;
constexpr int Bb  = 100;

constexpr int EROWS = Ee * NGg;     // 600000
constexpr int NROWS = Nn * NGg;     // 48000

// ---------------- scratch (device globals; no cudaMalloc allowed) -------------
__device__ __align__(16) float g_grid_node[Nn * NGg * 3];
__device__ __align__(16) float g_eipoly[EROWS * 12];
__device__ __align__(16) float g_bufA[EROWS * BDd];      // kern (per layer)
__device__ __align__(16) float g_basis[EROWS * BDd];
__device__ __align__(16) float g_x  [NROWS * Hh];
__device__ __align__(16) float g_x2 [NROWS * Hh];
__device__ __align__(16) float g_ffh[NROWS * 4 * Hh];
__device__ __align__(16) float g_fipoly[NGg * NGg * 2];
__device__ __align__(16) float g_fh1   [NGg * NGg * Hh];
__device__ __align__(16) float g_fbasis[NGg * NGg * BDd];
__device__ __align__(16) float g_fk    [NGg * NGg * Hh];
__device__ float g_gsum[Bb * 4];   // per-graph: sum_x, sum_y, sum_z, count
// CSR by destination
__device__ int g_deg[Nn];
__device__ int g_off[Nn + 1];
__device__ int g_cur[Nn];
__device__ int g_csr[Ee];

__device__ __forceinline__ float gelu_f(float x) {
    return 0.5f * x * (1.0f + erff(x * 0.70710678118654752f));
}

// ---------------- tiny kernels -------------------------------------------------
__global__ void k_zero(float* p, int n) {
    int i = blockIdx.x * blockDim.x + threadIdx.x;
    if (i < n) p[i] = 0.f;
}

__global__ void k_zero_int(int* p, int n) {
    int i = blockIdx.x * blockDim.x + threadIdx.x;
    if (i < n) p[i] = 0;
}

__global__ void k_gsum(const float* __restrict__ pos, const int* __restrict__ batch) {
    int n = blockIdx.x * blockDim.x + threadIdx.x;
    if (n >= Nn) return;
    int b = batch[n];
    atomicAdd(&g_gsum[b * 4 + 0], pos[n * 3 + 0]);
    atomicAdd(&g_gsum[b * 4 + 1], pos[n * 3 + 1]);
    atomicAdd(&g_gsum[b * 4 + 2], pos[n * 3 + 2]);
    atomicAdd(&g_gsum[b * 4 + 3], 1.f);
}

__global__ void k_grid_node(const int* __restrict__ batch,
                            const float* __restrict__ grid0,
                            const float* __restrict__ R) {
    int idx = blockIdx.x * blockDim.x + threadIdx.x;  // n*NG + k
    if (idx >= Nn * NGg) return;
    int n = idx / NGg, k = idx % NGg;
    const float* Rb = R + batch[n] * 9;
    float gx = grid0[k * 3 + 0], gy = grid0[k * 3 + 1], gz = grid0[k * 3 + 2];
    float* o = g_grid_node + idx * 3;
    o[0] = Rb[0] * gx + Rb[1] * gy + Rb[2] * gz;
    o[1] = Rb[3] * gx + Rb[4] * gy + Rb[5] * gz;
    o[2] = Rb[6] * gx + Rb[7] * gy + Rb[8] * gz;
}

__global__ void k_eipoly(const float* __restrict__ pos,
                         const float* __restrict__ charges,
                         const int* __restrict__ eidx) {
    int idx = blockIdx.x * blockDim.x + threadIdx.x;  // e*NG + k
    if (idx >= EROWS) return;
    int e = idx / NGg, k = idx % NGg;
    int s = eidx[e], d = eidx[Ee + e];
    float rx = pos[s * 3 + 0] - pos[d * 3 + 0];
    float ry = pos[s * 3 + 1] - pos[d * 3 + 1];
    float rz = pos[s * 3 + 2] - pos[d * 3 + 2];
    const float* g = g_grid_node + (s * NGg + k) * 3;
    float inv1 = rx * g[0] + ry * g[1] + rz * g[2];
    float vx = rx - inv1 * g[0], vy = ry - inv1 * g[1], vz = rz - inv1 * g[2];
    float inv2 = sqrtf(vx * vx + vy * vy + vz * vz);
    float cp = charges[s] * charges[d];
    float e0 = inv1, e1 = inv2, e2 = cp;
    float* o = g_eipoly + (size_t)idx * 12;
    o[0] = e0;  o[1] = e1;  o[2] = e2;
    o[3] = e0 * e0; o[4]  = e0 * e1; o[5]  = e0 * e2;
    o[6] = e1 * e0; o[7]  = e1 * e1; o[8]  = e1 * e2;
    o[9] = e2 * e0; o[10] = e2 * e1; o[11] = e2 * e2;
}

__global__ void k_fipoly(const float* __restrict__ grid0) {
    int idx = threadIdx.x;
    if (idx >= NGg * NGg) return;
    int p = idx / NGg, o = idx % NGg;
    float fi = grid0[p * 3 + 0] * grid0[o * 3 + 0] +
               grid0[p * 3 + 1] * grid0[o * 3 + 1] +
               grid0[p * 3 + 2] * grid0[o * 3 + 2];
    g_fipoly[idx * 2 + 0] = fi;
    g_fipoly[idx * 2 + 1] = fi * fi;
}

// naive GEMM for tiny fiber matrices (M=144) — fp32, negligible time
__global__ void k_small_gemm(const float* __restrict__ A, const float* __restrict__ W,
                             const float* __restrict__ bias, float* __restrict__ C,
                             int M, int N, int K, int act) {
    int idx = blockIdx.x * blockDim.x + threadIdx.x;
    if (idx >= M * N) return;
    int r = idx / N, c = idx % N;
    float acc = bias ? bias[c] : 0.f;
    for (int k = 0; k < K; k++) acc = fmaf(A[r * K + k], W[k * N + c], acc);
    C[idx] = act ? gelu_f(acc) : acc;
}

__global__ void k_embed(const float* __restrict__ pos, const float* __restrict__ vel,
                        const float* __restrict__ charges, const int* __restrict__ batch,
                        const float* __restrict__ We) {
    int nk = blockIdx.x;           // n*NG + k
    int h = threadIdx.x;           // 0..127
    int n = nk / NGg;
    const float* g = g_grid_node + nk * 3;
    float vx = vel[n * 3 + 0], vy = vel[n * 3 + 1], vz = vel[n * 3 + 2];
    int b = batch[n];
    float cnt = fmaxf(g_gsum[b * 4 + 3], 1.f);
    float rpx = pos[n * 3 + 0] - g_gsum[b * 4 + 0] / cnt;
    float rpy = pos[n * 3 + 1] - g_gsum[b * 4 + 1] / cnt;
    float rpz = pos[n * 3 + 2] - g_gsum[b * 4 + 2] / cnt;
    float f0 = vx * g[0] + vy * g[1] + vz * g[2];
    float f1 = rpx * g[0] + rpy * g[1] + rpz * g[2];
    float f2 = charges[n];
    float f3 = sqrtf(vx * vx + vy * vy + vz * vz);
    g_x[(size_t)nk * Hh + h] =
        f0 * We[h] + f1 * We[Hh + h] + f2 * We[2 * Hh + h] + f3 * We[3 * Hh + h];
}

// ---------------- CSR build (by destination) ------------------------------------
__global__ void k_count(const int* __restrict__ eidx) {
    int e = blockIdx.x * blockDim.x + threadIdx.x;
    if (e >= Ee) return;
    atomicAdd(&g_deg[eidx[Ee + e]], 1);
}

__global__ void k_scan() {
    __shared__ int sh[1024];
    int tid = threadIdx.x;
    int base = tid * 4;
    int v[4];
    int s0 = 0;
#pragma unroll
    for (int i = 0; i < 4; i++) {
        int idx = base + i;
        v[i] = (idx < Nn) ? g_deg[idx] : 0;
        s0 += v[i];
    }
    sh[tid] = s0;
    __syncthreads();
    for (int off = 1; off < 1024; off <<= 1) {
        int t = (tid >= off) ? sh[tid - off] : 0;
        __syncthreads();
        sh[tid] += t;
        __syncthreads();
    }
    int ex = sh[tid] - s0;
#pragma unroll
    for (int i = 0; i < 4; i++) {
        int idx = base + i;
        if (idx < Nn) { g_off[idx] = ex; ex += v[i]; }
    }
    if (tid == 1023) g_off[Nn] = sh[1023];
}

__global__ void k_fill(const int* __restrict__ eidx) {
    int e = blockIdx.x * blockDim.x + threadIdx.x;
    if (e >= Ee) return;
    int d = eidx[Ee + e];
    int pos = g_off[d] + atomicAdd(&g_cur[d], 1);
    g_csr[pos] = e;
}

// ---------------- fused gather + fiber contraction + LayerNorm ------------------
__global__ void __launch_bounds__(128) k_gather_fiber_ln(
    const int* __restrict__ eidx,
    const float* __restrict__ bconv, const float* __restrict__ gamma,
    const float* __restrict__ beta) {
    int n = blockIdx.x;
    int c = threadIdx.x;
    float acc[NGg];
#pragma unroll
    for (int o = 0; o < NGg; o++) acc[o] = 0.f;

    const int beg = g_off[n], end = g_off[n + 1];
    for (int j = beg; j < end; j++) {
        int e = g_csr[j];
        int s = eidx[e];
        const float* kr = &g_bufA[(size_t)e * NGg * Hh + c];
        const float* xr = &g_x[(size_t)s * NGg * Hh + c];
#pragma unroll
        for (int o = 0; o < NGg; o++)
            acc[o] = fmaf(kr[o * Hh], xr[o * Hh], acc[o]);
    }

    __shared__ float red[4];
    for (int p = 0; p < NGg; p++) {
        float v = 0.f;
        const float* fkp = &g_fk[(size_t)p * NGg * Hh + c];
#pragma unroll
        for (int o = 0; o < NGg; o++)
            v = fmaf(acc[o], fkp[o * Hh], v);
        v = v * (1.0f / NGg) + bconv[c];

        float s = v;
#pragma unroll
        for (int off = 16; off > 0; off >>= 1) s += __shfl_down_sync(0xffffffffu, s, off);
        if ((c & 31) == 0) red[c >> 5] = s;
        __syncthreads();
        float mean = (red[0] + red[1] + red[2] + red[3]) * (1.f / Hh);
        __syncthreads();
        float dd = v - mean;
        s = dd * dd;
#pragma unroll
        for (int off = 16; off > 0; off >>= 1) s += __shfl_down_sync(0xffffffffu, s, off);
        if ((c & 31) == 0) red[c >> 5] = s;
        __syncthreads();
        float var = (red[0] + red[1] + red[2] + red[3]) * (1.f / Hh);
        g_x2[((size_t)n * NGg + p) * Hh + c] = dd * rsqrtf(var + 1e-5f) * gamma[c] + beta[c];
        __syncthreads();
    }
}

// out[n,d] = (1/NG) sum_k grid_node[n,k,d] * (t[n,k,:]·W_ro2 + b_ro2)
__global__ void k_output(const float* __restrict__ Wro2, const float* __restrict__ bro2,
                         float* __restrict__ out) {
    int n = blockIdx.x;
    int h = threadIdx.x;
    __shared__ float red[4];
    __shared__ float ybc;
    float a0 = 0.f, a1 = 0.f, a2 = 0.f;
    for (int k = 0; k < NGg; k++) {
        float s = g_ffh[((size_t)(n * NGg + k)) * Hh + h] * Wro2[h];
#pragma unroll
        for (int off = 16; off > 0; off >>= 1) s += __shfl_down_sync(0xffffffffu, s, off);
        if ((h & 31) == 0) red[h >> 5] = s;
        __syncthreads();
        if (h == 0) ybc = red[0] + red[1] + red[2] + red[3] + bro2[0];
        __syncthreads();
        float y = ybc;
        a0 += g_grid_node[(n * NGg + k) * 3 + 0] * y;
        a1 += g_grid_node[(n * NGg + k) * 3 + 1] * y;
        a2 += g_grid_node[(n * NGg + k) * 3 + 2] * y;
        __syncthreads();
    }
    if (h == 0) {
        out[n * 3 + 0] = a0 * (1.f / NGg);
        out[n * 3 + 1] = a1 * (1.f / NGg);
        out[n * 3 + 2] = a2 * (1.f / NGg);
    }
}

// ---------------- bf16x3 tensor-core GEMM (≈fp32 accuracy) ---------------------
constexpr int BM = 128, BN = 128, BK = 32;
constexpr int ASTRIDE = BK + 8;      // 40 bf16/row -> conflict-free ldmatrix
constexpr int BSTRIDE = BN + 8;      // 136 bf16/row -> conflict-free ldmatrix(.trans)

__device__ __forceinline__ void mma_bf16(float* d, const uint32_t* a, const uint32_t* b) {
    asm volatile(
        "mma.sync.aligned.m16n8k16.row.col.f32.bf16.bf16.f32 "
        "{%0,%1,%2,%3}, {%4,%5,%6,%7}, {%8,%9}, {%0,%1,%2,%3};\n"
        : "+f"(d[0]), "+f"(d[1]), "+f"(d[2]), "+f"(d[3])
        : "r"(a[0]), "r"(a[1]), "r"(a[2]), "r"(a[3]), "r"(b[0]), "r"(b[1]));
}

__device__ __forceinline__ void ldm_x4(uint32_t* r, const __nv_bfloat16* p) {
    uint32_t addr = (uint32_t)__cvta_generic_to_shared(p);
    asm volatile("ldmatrix.sync.aligned.m8n8.x4.shared.b16 {%0,%1,%2,%3}, [%4];"
                 : "=r"(r[0]), "=r"(r[1]), "=r"(r[2]), "=r"(r[3]) : "r"(addr));
}

__device__ __forceinline__ void ldm_x2t(uint32_t* r, const __nv_bfloat16* p) {
    uint32_t addr = (uint32_t)__cvta_generic_to_shared(p);
    asm volatile("ldmatrix.sync.aligned.m8n8.x2.trans.shared.b16 {%0,%1}, [%2];"
                 : "=r"(r[0]), "=r"(r[1]) : "r"(addr));
}

__device__ __forceinline__ void split_bf16(float v, __nv_bfloat16& hi, __nv_bfloat16& lo) {
    hi = __float2bfloat16_rn(v);
    lo = __float2bfloat16_rn(v - __bfloat162float(hi));
}

template <bool GELU, bool ACCUM>
__global__ void __launch_bounds__(256, 2) gemm_bf16x3(
    const float* __restrict__ A, const float* __restrict__ Bw,
    const float* __restrict__ bias, float* __restrict__ C,
    int M, int N, int K) {
    __shared__ __nv_bfloat16 As1[BM][ASTRIDE];
    __shared__ __nv_bfloat16 As2[BM][ASTRIDE];
    __shared__ __nv_bfloat16 Bs1[BK][BSTRIDE];
    __shared__ __nv_bfloat16 Bs2[BK][BSTRIDE];

    const int tid  = threadIdx.x;
    const int lane = tid & 31;
    const int warp = tid >> 5;
    const int wm = warp & 1;
    const int wn = warp >> 1;
    const int br = blockIdx.x * BM;
    const int bc = blockIdx.y * BN;
    const int gid = lane >> 2;
    const int qid = lane & 3;

    float acc[4][4][4];
#pragma unroll
    for (int mt = 0; mt < 4; mt++)
#pragma unroll
        for (int nt = 0; nt < 4; nt++)
#pragma unroll
            for (int j = 0; j < 4; j++) acc[mt][nt][j] = 0.f;

    const int aRow = ((lane >> 3) & 1) * 8 + (lane & 7);
    const int aKof = (lane >> 4) * 8;
    const int bK   = lane & 15;

    const int ktiles = (K + BK - 1) / BK;
    for (int kt = 0; kt < ktiles; kt++) {
        const int k0 = kt * BK;
#pragma unroll
        for (int it = 0; it < 4; it++) {
            int f = it * 256 + tid;
            int row = f >> 3, kq = (f & 7) * 4;
            float4 v = make_float4(0.f, 0.f, 0.f, 0.f);
            int gr = br + row;
            if (gr < M && (k0 + kq) < K)
                v = *reinterpret_cast<const float4*>(&A[(size_t)gr * K + k0 + kq]);
            __nv_bfloat16 h0, h1, h2, h3, l0, l1, l2, l3;
            split_bf16(v.x, h0, l0); split_bf16(v.y, h1, l1);
            split_bf16(v.z, h2, l2); split_bf16(v.w, h3, l3);
            *reinterpret_cast<__nv_bfloat162*>(&As1[row][kq])     = __nv_bfloat162(h0, h1);
            *reinterpret_cast<__nv_bfloat162*>(&As1[row][kq + 2]) = __nv_bfloat162(h2, h3);
            *reinterpret_cast<__nv_bfloat162*>(&As2[row][kq])     = __nv_bfloat162(l0, l1);
            *reinterpret_cast<__nv_bfloat162*>(&As2[row][kq + 2]) = __nv_bfloat162(l2, l3);
        }
#pragma unroll
        for (int it = 0; it < 4; it++) {
            int f = it * 256 + tid;
            int krow = f >> 5, n4 = (f & 31) * 4;
            float4 v = make_float4(0.f, 0.f, 0.f, 0.f);
            if ((k0 + krow) < K)
                v = *reinterpret_cast<const float4*>(&Bw[(size_t)(k0 + krow) * N + bc + n4]);
            __nv_bfloat16 h0, h1, h2, h3, l0, l1, l2, l3;
            split_bf16(v.x, h0, l0); split_bf16(v.y, h1, l1);
            split_bf16(v.z, h2, l2); split_bf16(v.w, h3, l3);
            *reinterpret_cast<__nv_bfloat162*>(&Bs1[krow][n4])     = __nv_bfloat162(h0, h1);
            *reinterpret_cast<__nv_bfloat162*>(&Bs1[krow][n4 + 2]) = __nv_bfloat162(h2, h3);
            *reinterpret_cast<__nv_bfloat162*>(&Bs2[krow][n4])     = __nv_bfloat162(l0, l1);
            *reinterpret_cast<__nv_bfloat162*>(&Bs2[krow][n4 + 2]) = __nv_bfloat162(l2, l3);
        }
        __syncthreads();

#pragma unroll
        for (int ks = 0; ks < 2; ks++) {
            const int kk = ks * 16;
            uint32_t bb[4][2], bs[4][2];
#pragma unroll
            for (int nt = 0; nt < 4; nt++) {
                const int n0 = wn * 32 + nt * 8;
                ldm_x2t(bb[nt], &Bs1[kk + bK][n0]);
                ldm_x2t(bs[nt], &Bs2[kk + bK][n0]);
            }
#pragma unroll
            for (int mt = 0; mt < 4; mt++) {
                const int r0 = wm * 64 + mt * 16 + aRow;
                uint32_t ah[4], al[4];
                ldm_x4(ah, &As1[r0][kk + aKof]);
                ldm_x4(al, &As2[r0][kk + aKof]);
#pragma unroll
                for (int nt = 0; nt < 4; nt++) {
                    mma_bf16(acc[mt][nt], al, bb[nt]);
                    mma_bf16(acc[mt][nt], ah, bs[nt]);
                    mma_bf16(acc[mt][nt], ah, bb[nt]);
                }
            }
        }
        __syncthreads();
    }

#pragma unroll
    for (int nt = 0; nt < 4; nt++) {
        const int c = bc + wn * 32 + nt * 8 + qid * 2;
        float b0 = 0.f, b1 = 0.f;
        if (bias) { b0 = bias[c]; b1 = bias[c + 1]; }
#pragma unroll
        for (int mt = 0; mt < 4; mt++) {
            int r0 = br + wm * 64 + mt * 16 + gid;
#pragma unroll
            for (int half = 0; half < 2; half++) {
                int r = r0 + half * 8;
                if (r >= M) continue;
                float v0 = acc[mt][nt][half * 2 + 0] + b0;
                float v1 = acc[mt][nt][half * 2 + 1] + b1;
                if (GELU) { v0 = gelu_f(v0); v1 = gelu_f(v1); }
                float2* p = reinterpret_cast<float2*>(&C[(size_t)r * N + c]);
                if (ACCUM) {
                    float2 o = *p;
                    o.x += v0; o.y += v1;
                    *p = o;
                } else {
                    *p = make_float2(v0, v1);
                }
            }
        }
    }
}

// ---------------- fused basis MLP: basis = gelu(gelu(eip@W1+b1)@W2+b2) ----------
// h1 (128x128) never leaves smem. A-tile stride 136 bf16 (272B = 68 u32 ≡ 4 mod 32
// -> 8-row ldmatrix hits banks {0,4,...,28}: conflict-free).
constexpr int A2S = 136;
constexpr size_t F_OFF_A1 = 0;
constexpr size_t F_OFF_A2 = F_OFF_A1 + (size_t)BM * A2S * 2;   // 34816
constexpr size_t F_OFF_B1 = F_OFF_A2 + (size_t)BM * A2S * 2;   // 69632
constexpr size_t F_OFF_B2 = F_OFF_B1 + (size_t)BK * BSTRIDE * 2; // 78336
constexpr size_t F_OFF_EI = F_OFF_B2 + (size_t)BK * BSTRIDE * 2; // 87040
constexpr size_t F_OFF_W1 = F_OFF_EI + (size_t)BM * 12 * 4;      // 93184
constexpr size_t F_OFF_BB = F_OFF_W1 + (size_t)12 * Hh * 4;      // 99328
constexpr size_t F_SMEM   = F_OFF_BB + (size_t)Hh * 4;           // 99840

__global__ void __launch_bounds__(256, 2) k_basis12(
    const float* __restrict__ eip,
    const float* __restrict__ W1, const float* __restrict__ b1,
    const float* __restrict__ W2, const float* __restrict__ b2,
    float* __restrict__ Cout, int M) {
    extern __shared__ char smraw[];
    __nv_bfloat16* As1 = reinterpret_cast<__nv_bfloat16*>(smraw + F_OFF_A1); // [128][136]
    __nv_bfloat16* As2 = reinterpret_cast<__nv_bfloat16*>(smraw + F_OFF_A2);
    __nv_bfloat16* Bs1 = reinterpret_cast<__nv_bfloat16*>(smraw + F_OFF_B1); // [32][136]
    __nv_bfloat16* Bs2 = reinterpret_cast<__nv_bfloat16*>(smraw + F_OFF_B2);
    float* EIP = reinterpret_cast<float*>(smraw + F_OFF_EI);                 // [128*12]
    float* W1s = reinterpret_cast<float*>(smraw + F_OFF_W1);                 // [12*128]
    float* b1s = reinterpret_cast<float*>(smraw + F_OFF_BB);                 // [128]

    const int tid  = threadIdx.x;
    const int lane = tid & 31;
    const int warp = tid >> 5;
    const int wm = warp & 1;
    const int wn = warp >> 1;
    const int br = blockIdx.x * BM;
    const int gid = lane >> 2;
    const int qid = lane & 3;

    // stage W1 (1536 fp32), b1 (128), eipoly tile (1536 fp32, contiguous range)
    for (int f = tid; f < 12 * Hh; f += 256) W1s[f] = W1[f];
    if (tid < Hh) b1s[tid] = b1[tid];
    {
        const int total4 = (EROWS * 12) / 4;       // global float4 count (divisible)
        const int base4 = br * 3;                   // 12 floats/row = 3 float4
#pragma unroll
        for (int it = 0; it < 2; it++) {
            int f = it * 256 + tid;
            if (f < 384) {
                float4 v = make_float4(0.f, 0.f, 0.f, 0.f);
                if (base4 + f < total4)
                    v = *reinterpret_cast<const float4*>(&eip[(size_t)(base4 + f) * 4]);
                *reinterpret_cast<float4*>(&EIP[f * 4]) = v;
            }
        }
    }
    __syncthreads();

    // compute h1 = gelu(eip@W1 + b1) into split-bf16 A tiles (persistent)
    {
        const int r  = tid >> 1;             // 0..127
        const int cb = (tid & 1) * 64;       // 0 or 64
        float e[12];
#pragma unroll
        for (int k = 0; k < 12; k++) e[k] = EIP[r * 12 + k];
#pragma unroll
        for (int c2 = 0; c2 < 64; c2 += 2) {
            int c = cb + c2;
            float a0 = b1s[c], a1 = b1s[c + 1];
#pragma unroll
            for (int k = 0; k < 12; k++) {
                a0 = fmaf(e[k], W1s[k * Hh + c], a0);
                a1 = fmaf(e[k], W1s[k * Hh + c + 1], a1);
            }
            a0 = gelu_f(a0); a1 = gelu_f(a1);
            __nv_bfloat16 h0, l0, h1, l1;
            split_bf16(a0, h0, l0);
            split_bf16(a1, h1, l1);
            *reinterpret_cast<__nv_bfloat162*>(&As1[r * A2S + c]) = __nv_bfloat162(h0, h1);
            *reinterpret_cast<__nv_bfloat162*>(&As2[r * A2S + c]) = __nv_bfloat162(l0, l1);
        }
    }
    __syncthreads();

    float acc[4][4][4];
#pragma unroll
    for (int mt = 0; mt < 4; mt++)
#pragma unroll
        for (int nt = 0; nt < 4; nt++)
#pragma unroll
            for (int j = 0; j < 4; j++) acc[mt][nt][j] = 0.f;

    const int aRow = ((lane >> 3) & 1) * 8 + (lane & 7);
    const int aKof = (lane >> 4) * 8;
    const int bK   = lane & 15;

    // mainloop over K=128 (4 k-tiles); A persistent in smem, B = W2 streamed
#pragma unroll
    for (int kt = 0; kt < 4; kt++) {
        const int k0 = kt * BK;
#pragma unroll
        for (int it = 0; it < 4; it++) {
            int f = it * 256 + tid;
            int krow = f >> 5, n4 = (f & 31) * 4;
            float4 v = *reinterpret_cast<const float4*>(&W2[(size_t)(k0 + krow) * Hh + n4]);
            __nv_bfloat16 h0, h1, h2, h3, l0, l1, l2, l3;
            split_bf16(v.x, h0, l0); split_bf16(v.y, h1, l1);
            split_bf16(v.z, h2, l2); split_bf16(v.w, h3, l3);
            *reinterpret_cast<__nv_bfloat162*>(&Bs1[krow * BSTRIDE + n4])     = __nv_bfloat162(h0, h1);
            *reinterpret_cast<__nv_bfloat162*>(&Bs1[krow * BSTRIDE + n4 + 2]) = __nv_bfloat162(h2, h3);
            *reinterpret_cast<__nv_bfloat162*>(&Bs2[krow * BSTRIDE + n4])     = __nv_bfloat162(l0, l1);
            *reinterpret_cast<__nv_bfloat162*>(&Bs2[krow * BSTRIDE + n4 + 2]) = __nv_bfloat162(l2, l3);
        }
        __syncthreads();

#pragma unroll
        for (int ks = 0; ks < 2; ks++) {
            const int kk = ks * 16;
            uint32_t bb[4][2], bs[4][2];
#pragma unroll
            for (int nt = 0; nt < 4; nt++) {
                const int n0 = wn * 32 + nt * 8;
                ldm_x2t(bb[nt], &Bs1[(kk + bK) * BSTRIDE + n0]);
                ldm_x2t(bs[nt], &Bs2[(kk + bK) * BSTRIDE + n0]);
            }
#pragma unroll
            for (int mt = 0; mt < 4; mt++) {
                const int r0 = wm * 64 + mt * 16 + aRow;
                uint32_t ah[4], al[4];
                ldm_x4(ah, &As1[r0 * A2S + k0 + kk + aKof]);
                ldm_x4(al, &As2[r0 * A2S + k0 + kk + aKof]);
#pragma unroll
                for (int nt = 0; nt < 4; nt++) {
                    mma_bf16(acc[mt][nt], al, bb[nt]);
                    mma_bf16(acc[mt][nt], ah, bs[nt]);
                    mma_bf16(acc[mt][nt], ah, bb[nt]);
                }
            }
        }
        __syncthreads();
    }

    // epilogue: gelu -> basis fp32
#pragma unroll
    for (int nt = 0; nt < 4; nt++) {
        const int c = wn * 32 + nt * 8 + qid * 2;
        float bb0 = b2[c], bb1 = b2[c + 1];
#pragma unroll
        for (int mt = 0; mt < 4; mt++) {
            int r0 = br + wm * 64 + mt * 16 + gid;
#pragma unroll
            for (int half = 0; half < 2; half++) {
                int r = r0 + half * 8;
                if (r >= M) continue;
                float v0 = gelu_f(acc[mt][nt][half * 2 + 0] + bb0);
                float v1 = gelu_f(acc[mt][nt][half * 2 + 1] + bb1);
                *reinterpret_cast<float2*>(&Cout[(size_t)r * Hh + c]) = make_float2(v0, v1);
            }
        }
    }
}

// ---------------- host launch ----------------------------------------------------
static void launch_gemm(const float* A, const float* W, const float* bias, float* C,
                        int M, int N, int K, bool gelu_act, bool accum) {
    dim3 grid((M + BM - 1) / BM, N / BN);
    if (gelu_act)   gemm_bf16x3<true, false><<<grid, 256>>>(A, W, bias, C, M, N, K);
    else if (accum) gemm_bf16x3<false, true><<<grid, 256>>>(A, W, bias, C, M, N, K);
    else            gemm_bf16x3<false, false><<<grid, 256>>>(A, W, bias, C, M, N, K);
}

extern "C" void kernel_launch(void* const* d_in, const int* in_sizes, int n_in,
                              void* d_out, int out_size) {
    const float* pos      = (const float*)d_in[0];
    const float* vel      = (const float*)d_in[1];
    const float* charges  = (const float*)d_in[2];
    const int*   batch    = (const int*)d_in[3];
    const int*   eidx     = (const int*)d_in[4];
    const float* grid0    = (const float*)d_in[5];
    const float* R        = (const float*)d_in[6];
    const float* W_basis1 = (const float*)d_in[7];
    const float* b_basis1 = (const float*)d_in[8];
    const float* W_basis2 = (const float*)d_in[9];
    const float* b_basis2 = (const float*)d_in[10];
    const float* W_fbasis1 = (const float*)d_in[11];
    const float* b_fbasis1 = (const float*)d_in[12];
    const float* W_fbasis2 = (const float*)d_in[13];
    const float* b_fbasis2 = (const float*)d_in[14];
    const float* W_embed  = (const float*)d_in[15];
    const float* W_conv   = (const float*)d_in[16];
    const float* W_fiber  = (const float*)d_in[17];
    const float* b_conv   = (const float*)d_in[18];
    const float* ln_gamma = (const float*)d_in[19];
    const float* ln_beta  = (const float*)d_in[20];
    const float* W_ff1    = (const float*)d_in[21];
    const float* b_ff1    = (const float*)d_in[22];
    const float* W_ff2    = (const float*)d_in[23];
    const float* b_ff2    = (const float*)d_in[24];
    const float* W_ro1    = (const float*)d_in[25];
    const float* b_ro1    = (const float*)d_in[26];
    const float* W_ro2    = (const float*)d_in[27];
    const float* b_ro2    = (const float*)d_in[28];
    float* out = (float*)d_out;

    float *bufA, *basis, *x, *x2, *ffh, *eip, *fip, *fh1, *fbasis, *fk, *gsum;
    int *deg, *cur;
    cudaGetSymbolAddress((void**)&bufA,  g_bufA);
    cudaGetSymbolAddress((void**)&basis, g_basis);
    cudaGetSymbolAddress((void**)&x,     g_x);
    cudaGetSymbolAddress((void**)&x2,    g_x2);
    cudaGetSymbolAddress((void**)&ffh,   g_ffh);
    cudaGetSymbolAddress((void**)&eip,   g_eipoly);
    cudaGetSymbolAddress((void**)&fip,   g_fipoly);
    cudaGetSymbolAddress((void**)&fh1,   g_fh1);
    cudaGetSymbolAddress((void**)&fbasis,g_fbasis);
    cudaGetSymbolAddress((void**)&fk,    g_fk);
    cudaGetSymbolAddress((void**)&gsum,  g_gsum);
    cudaGetSymbolAddress((void**)&deg,   g_deg);
    cudaGetSymbolAddress((void**)&cur,   g_cur);

    static bool attr_done = false;
    if (!attr_done) {
        cudaFuncSetAttribute(k_basis12, cudaFuncAttributeMaxDynamicSharedMemorySize,
                             (int)F_SMEM);
        attr_done = true;
    }

    // graph statistics + rotated grids
    k_zero<<<(Bb * 4 + 255) / 256, 256>>>(gsum, Bb * 4);
    k_gsum<<<(Nn + 255) / 256, 256>>>(pos, batch);
    k_grid_node<<<(Nn * NGg + 255) / 256, 256>>>(batch, grid0, R);

    // CSR by destination (built once, reused by both layers)
    k_zero_int<<<(Nn + 255) / 256, 256>>>(deg, Nn);
    k_zero_int<<<(Nn + 255) / 256, 256>>>(cur, Nn);
    k_count<<<(Ee + 255) / 256, 256>>>(eidx);
    k_scan<<<1, 1024>>>();
    k_fill<<<(Ee + 255) / 256, 256>>>(eidx);

    // edge basis MLP: fused (h1 never leaves smem)
    k_eipoly<<<(EROWS + 255) / 256, 256>>>(pos, charges, eidx);
    k_basis12<<<(EROWS + BM - 1) / BM, 256, F_SMEM>>>(
        eip, W_basis1, b_basis1, W_basis2, b_basis2, basis, EROWS);

    // fiber basis MLP: 144 rows
    k_fipoly<<<1, 256>>>(grid0);
    k_small_gemm<<<(NGg * NGg * Hh + 255) / 256, 256>>>(fip, W_fbasis1, b_fbasis1, fh1,
                                                        NGg * NGg, Hh, 2, 1);
    k_small_gemm<<<(NGg * NGg * BDd + 255) / 256, 256>>>(fh1, W_fbasis2, b_fbasis2, fbasis,
                                                         NGg * NGg, BDd, Hh, 1);

    // node embedding
    k_embed<<<NROWS, Hh>>>(pos, vel, charges, batch, W_embed);

    for (int l = 0; l < Ll; l++) {
        // kern = basis @ W_conv[l]  (600k x 128 x 128) -> bufA
        launch_gemm(basis, W_conv + (size_t)l * BDd * Hh, nullptr, bufA, EROWS, Hh, BDd,
                    false, false);
        // fk = fiber_basis @ W_fiber[l]
        k_small_gemm<<<(NGg * NGg * Hh + 255) / 256, 256>>>(
            fbasis, W_fiber + (size_t)l * BDd * Hh, nullptr, fk, NGg * NGg, Hh, BDd, 0);
        // fused: x1 = gather-sum(kern * x[src] -> dst); x2 = LN(fiber(x1))
        k_gather_fiber_ln<<<Nn, Hh>>>(eidx, b_conv + l * Hh, ln_gamma + l * Hh,
                                      ln_beta + l * Hh);
        // FF: x += W_ff2 @ gelu(W_ff1 @ h)
        launch_gemm(x2, W_ff1 + (size_t)l * Hh * 4 * Hh, b_ff1 + l * 4 * Hh, ffh,
                    NROWS, 4 * Hh, Hh, true, false);
        launch_gemm(ffh, W_ff2 + (size_t)l * 4 * Hh * Hh, b_ff2 + l * Hh, x,
                    NROWS, Hh, 4 * Hh, false, true);
    }

    // readout
    launch_gemm(x, W_ro1, b_ro1, ffh, NROWS, Hh, Hh, true, false);
    k_output<<<Nn, Hh>>>(W_ro2, b_ro2, out);
}

// round 13
// speedup vs baseline: 1.2011x; 1.0854x over previous
#include <cuda_runtime.h>
#include <cuda_bf16.h>
#include <math.h>
#include <stdint.h>

// Problem dims (fixed by the dataset)
constexpr int Nn  = 4000;
constexpr int Ee  = 50000;
constexpr int NGg = 12;
constexpr int Hh  = 128;
constexpr int BDd = 128;
constexpr int Ll  = 2;
constexpr int Bb  = 100;

constexpr int EROWS = Ee * NGg;     // 600000
constexpr int NROWS = Nn * NGg;     // 48000

// ---------------- scratch (device globals; no cudaMalloc allowed) -------------
__device__ __align__(16) float g_grid_node[Nn * NGg * 3];
__device__ __align__(16) float g_eipoly[EROWS * 12];
__device__ __align__(16) float g_kern0[(size_t)EROWS * Hh];
__device__ __align__(16) float g_kern1[(size_t)EROWS * Hh];
__device__ __align__(16) float g_x  [NROWS * Hh];
__device__ __align__(16) float g_x2 [NROWS * Hh];
__device__ __align__(16) float g_ffh[NROWS * 4 * Hh];
__device__ __align__(16) float g_fipoly[NGg * NGg * 2];
__device__ __align__(16) float g_fh1   [NGg * NGg * Hh];
__device__ __align__(16) float g_fbasis[NGg * NGg * BDd];
__device__ __align__(16) float g_fk    [NGg * NGg * Hh];
__device__ float g_gsum[Bb * 4];   // per-graph: sum_x, sum_y, sum_z, count
// CSR by destination
__device__ int g_deg[Nn];
__device__ int g_off[Nn + 1];
__device__ int g_cur[Nn];
__device__ int g_csr[Ee];

__device__ __forceinline__ float gelu_f(float x) {
    return 0.5f * x * (1.0f + erff(x * 0.70710678118654752f));
}

// ---------------- tiny kernels -------------------------------------------------
__global__ void k_zero(float* p, int n) {
    int i = blockIdx.x * blockDim.x + threadIdx.x;
    if (i < n) p[i] = 0.f;
}

__global__ void k_zero_int(int* p, int n) {
    int i = blockIdx.x * blockDim.x + threadIdx.x;
    if (i < n) p[i] = 0;
}

__global__ void k_gsum(const float* __restrict__ pos, const int* __restrict__ batch) {
    int n = blockIdx.x * blockDim.x + threadIdx.x;
    if (n >= Nn) return;
    int b = batch[n];
    atomicAdd(&g_gsum[b * 4 + 0], pos[n * 3 + 0]);
    atomicAdd(&g_gsum[b * 4 + 1], pos[n * 3 + 1]);
    atomicAdd(&g_gsum[b * 4 + 2], pos[n * 3 + 2]);
    atomicAdd(&g_gsum[b * 4 + 3], 1.f);
}

__global__ void k_grid_node(const int* __restrict__ batch,
                            const float* __restrict__ grid0,
                            const float* __restrict__ R) {
    int idx = blockIdx.x * blockDim.x + threadIdx.x;  // n*NG + k
    if (idx >= Nn * NGg) return;
    int n = idx / NGg, k = idx % NGg;
    const float* Rb = R + batch[n] * 9;
    float gx = grid0[k * 3 + 0], gy = grid0[k * 3 + 1], gz = grid0[k * 3 + 2];
    float* o = g_grid_node + idx * 3;
    o[0] = Rb[0] * gx + Rb[1] * gy + Rb[2] * gz;
    o[1] = Rb[3] * gx + Rb[4] * gy + Rb[5] * gz;
    o[2] = Rb[6] * gx + Rb[7] * gy + Rb[8] * gz;
}

__global__ void k_eipoly(const float* __restrict__ pos,
                         const float* __restrict__ charges,
                         const int* __restrict__ eidx) {
    int idx = blockIdx.x * blockDim.x + threadIdx.x;  // e*NG + k
    if (idx >= EROWS) return;
    int e = idx / NGg, k = idx % NGg;
    int s = eidx[e], d = eidx[Ee + e];
    float rx = pos[s * 3 + 0] - pos[d * 3 + 0];
    float ry = pos[s * 3 + 1] - pos[d * 3 + 1];
    float rz = pos[s * 3 + 2] - pos[d * 3 + 2];
    const float* g = g_grid_node + (s * NGg + k) * 3;
    float inv1 = rx * g[0] + ry * g[1] + rz * g[2];
    float vx = rx - inv1 * g[0], vy = ry - inv1 * g[1], vz = rz - inv1 * g[2];
    float inv2 = sqrtf(vx * vx + vy * vy + vz * vz);
    float cp = charges[s] * charges[d];
    float e0 = inv1, e1 = inv2, e2 = cp;
    float* o = g_eipoly + (size_t)idx * 12;
    o[0] = e0;  o[1] = e1;  o[2] = e2;
    o[3] = e0 * e0; o[4]  = e0 * e1; o[5]  = e0 * e2;
    o[6] = e1 * e0; o[7]  = e1 * e1; o[8]  = e1 * e2;
    o[9] = e2 * e0; o[10] = e2 * e1; o[11] = e2 * e2;
}

__global__ void k_fipoly(const float* __restrict__ grid0) {
    int idx = threadIdx.x;
    if (idx >= NGg * NGg) return;
    int p = idx / NGg, o = idx % NGg;
    float fi = grid0[p * 3 + 0] * grid0[o * 3 + 0] +
               grid0[p * 3 + 1] * grid0[o * 3 + 1] +
               grid0[p * 3 + 2] * grid0[o * 3 + 2];
    g_fipoly[idx * 2 + 0] = fi;
    g_fipoly[idx * 2 + 1] = fi * fi;
}

// naive GEMM for tiny fiber matrices (M=144) — fp32, negligible time
__global__ void k_small_gemm(const float* __restrict__ A, const float* __restrict__ W,
                             const float* __restrict__ bias, float* __restrict__ C,
                             int M, int N, int K, int act) {
    int idx = blockIdx.x * blockDim.x + threadIdx.x;
    if (idx >= M * N) return;
    int r = idx / N, c = idx % N;
    float acc = bias ? bias[c] : 0.f;
    for (int k = 0; k < K; k++) acc = fmaf(A[r * K + k], W[k * N + c], acc);
    C[idx] = act ? gelu_f(acc) : acc;
}

__global__ void k_embed(const float* __restrict__ pos, const float* __restrict__ vel,
                        const float* __restrict__ charges, const int* __restrict__ batch,
                        const float* __restrict__ We) {
    int nk = blockIdx.x;           // n*NG + k
    int h = threadIdx.x;           // 0..127
    int n = nk / NGg;
    const float* g = g_grid_node + nk * 3;
    float vx = vel[n * 3 + 0], vy = vel[n * 3 + 1], vz = vel[n * 3 + 2];
    int b = batch[n];
    float cnt = fmaxf(g_gsum[b * 4 + 3], 1.f);
    float rpx = pos[n * 3 + 0] - g_gsum[b * 4 + 0] / cnt;
    float rpy = pos[n * 3 + 1] - g_gsum[b * 4 + 1] / cnt;
    float rpz = pos[n * 3 + 2] - g_gsum[b * 4 + 2] / cnt;
    float f0 = vx * g[0] + vy * g[1] + vz * g[2];
    float f1 = rpx * g[0] + rpy * g[1] + rpz * g[2];
    float f2 = charges[n];
    float f3 = sqrtf(vx * vx + vy * vy + vz * vz);
    g_x[(size_t)nk * Hh + h] =
        f0 * We[h] + f1 * We[Hh + h] + f2 * We[2 * Hh + h] + f3 * We[3 * Hh + h];
}

// ---------------- CSR build (by destination) ------------------------------------
__global__ void k_count(const int* __restrict__ eidx) {
    int e = blockIdx.x * blockDim.x + threadIdx.x;
    if (e >= Ee) return;
    atomicAdd(&g_deg[eidx[Ee + e]], 1);
}

__global__ void k_scan() {
    __shared__ int sh[1024];
    int tid = threadIdx.x;
    int base = tid * 4;
    int v[4];
    int s0 = 0;
#pragma unroll
    for (int i = 0; i < 4; i++) {
        int idx = base + i;
        v[i] = (idx < Nn) ? g_deg[idx] : 0;
        s0 += v[i];
    }
    sh[tid] = s0;
    __syncthreads();
    for (int off = 1; off < 1024; off <<= 1) {
        int t = (tid >= off) ? sh[tid - off] : 0;
        __syncthreads();
        sh[tid] += t;
        __syncthreads();
    }
    int ex = sh[tid] - s0;
#pragma unroll
    for (int i = 0; i < 4; i++) {
        int idx = base + i;
        if (idx < Nn) { g_off[idx] = ex; ex += v[i]; }
    }
    if (tid == 1023) g_off[Nn] = sh[1023];
}

__global__ void k_fill(const int* __restrict__ eidx) {
    int e = blockIdx.x * blockDim.x + threadIdx.x;
    if (e >= Ee) return;
    int d = eidx[Ee + e];
    int pos = g_off[d] + atomicAdd(&g_cur[d], 1);
    g_csr[pos] = e;
}

// ---------------- fused gather + fiber contraction + LayerNorm ------------------
__global__ void __launch_bounds__(128) k_gather_fiber_ln(
    const int* __restrict__ eidx, const float* __restrict__ kern,
    const float* __restrict__ bconv, const float* __restrict__ gamma,
    const float* __restrict__ beta) {
    int n = blockIdx.x;
    int c = threadIdx.x;
    float acc[NGg];
#pragma unroll
    for (int o = 0; o < NGg; o++) acc[o] = 0.f;

    const int beg = g_off[n], end = g_off[n + 1];
    for (int j = beg; j < end; j++) {
        int e = g_csr[j];
        int s = eidx[e];
        const float* kr = &kern[(size_t)e * NGg * Hh + c];
        const float* xr = &g_x[(size_t)s * NGg * Hh + c];
#pragma unroll
        for (int o = 0; o < NGg; o++)
            acc[o] = fmaf(kr[o * Hh], xr[o * Hh], acc[o]);
    }

    __shared__ float red[4];
    for (int p = 0; p < NGg; p++) {
        float v = 0.f;
        const float* fkp = &g_fk[(size_t)p * NGg * Hh + c];
#pragma unroll
        for (int o = 0; o < NGg; o++)
            v = fmaf(acc[o], fkp[o * Hh], v);
        v = v * (1.0f / NGg) + bconv[c];

        float s = v;
#pragma unroll
        for (int off = 16; off > 0; off >>= 1) s += __shfl_down_sync(0xffffffffu, s, off);
        if ((c & 31) == 0) red[c >> 5] = s;
        __syncthreads();
        float mean = (red[0] + red[1] + red[2] + red[3]) * (1.f / Hh);
        __syncthreads();
        float dd = v - mean;
        s = dd * dd;
#pragma unroll
        for (int off = 16; off > 0; off >>= 1) s += __shfl_down_sync(0xffffffffu, s, off);
        if ((c & 31) == 0) red[c >> 5] = s;
        __syncthreads();
        float var = (red[0] + red[1] + red[2] + red[3]) * (1.f / Hh);
        g_x2[((size_t)n * NGg + p) * Hh + c] = dd * rsqrtf(var + 1e-5f) * gamma[c] + beta[c];
        __syncthreads();
    }
}

// out[n,d] = (1/NG) sum_k grid_node[n,k,d] * (t[n,k,:]·W_ro2 + b_ro2)
__global__ void k_output(const float* __restrict__ Wro2, const float* __restrict__ bro2,
                         float* __restrict__ out) {
    int n = blockIdx.x;
    int h = threadIdx.x;
    __shared__ float red[4];
    __shared__ float ybc;
    float a0 = 0.f, a1 = 0.f, a2 = 0.f;
    for (int k = 0; k < NGg; k++) {
        float s = g_ffh[((size_t)(n * NGg + k)) * Hh + h] * Wro2[h];
#pragma unroll
        for (int off = 16; off > 0; off >>= 1) s += __shfl_down_sync(0xffffffffu, s, off);
        if ((h & 31) == 0) red[h >> 5] = s;
        __syncthreads();
        if (h == 0) ybc = red[0] + red[1] + red[2] + red[3] + bro2[0];
        __syncthreads();
        float y = ybc;
        a0 += g_grid_node[(n * NGg + k) * 3 + 0] * y;
        a1 += g_grid_node[(n * NGg + k) * 3 + 1] * y;
        a2 += g_grid_node[(n * NGg + k) * 3 + 2] * y;
        __syncthreads();
    }
    if (h == 0) {
        out[n * 3 + 0] = a0 * (1.f / NGg);
        out[n * 3 + 1] = a1 * (1.f / NGg);
        out[n * 3 + 2] = a2 * (1.f / NGg);
    }
}

// ---------------- bf16x3 tensor-core GEMM (≈fp32 accuracy) ---------------------
constexpr int BM = 128, BN = 128, BK = 32;
constexpr int ASTRIDE = BK + 8;      // 40 bf16/row -> conflict-free ldmatrix
constexpr int BSTRIDE = BN + 8;      // 136 bf16/row -> conflict-free ldmatrix(.trans)

__device__ __forceinline__ void mma_bf16(float* d, const uint32_t* a, const uint32_t* b) {
    asm volatile(
        "mma.sync.aligned.m16n8k16.row.col.f32.bf16.bf16.f32 "
        "{%0,%1,%2,%3}, {%4,%5,%6,%7}, {%8,%9}, {%0,%1,%2,%3};\n"
        : "+f"(d[0]), "+f"(d[1]), "+f"(d[2]), "+f"(d[3])
        : "r"(a[0]), "r"(a[1]), "r"(a[2]), "r"(a[3]), "r"(b[0]), "r"(b[1]));
}

__device__ __forceinline__ void ldm_x4(uint32_t* r, const __nv_bfloat16* p) {
    uint32_t addr = (uint32_t)__cvta_generic_to_shared(p);
    asm volatile("ldmatrix.sync.aligned.m8n8.x4.shared.b16 {%0,%1,%2,%3}, [%4];"
                 : "=r"(r[0]), "=r"(r[1]), "=r"(r[2]), "=r"(r[3]) : "r"(addr));
}

__device__ __forceinline__ void ldm_x2t(uint32_t* r, const __nv_bfloat16* p) {
    uint32_t addr = (uint32_t)__cvta_generic_to_shared(p);
    asm volatile("ldmatrix.sync.aligned.m8n8.x2.trans.shared.b16 {%0,%1}, [%2];"
                 : "=r"(r[0]), "=r"(r[1]) : "r"(addr));
}

__device__ __forceinline__ void split_bf16(float v, __nv_bfloat16& hi, __nv_bfloat16& lo) {
    hi = __float2bfloat16_rn(v);
    lo = __float2bfloat16_rn(v - __bfloat162float(hi));
}

template <bool GELU, bool ACCUM>
__global__ void __launch_bounds__(256, 2) gemm_bf16x3(
    const float* __restrict__ A, const float* __restrict__ Bw,
    const float* __restrict__ bias, float* __restrict__ C,
    int M, int N, int K) {
    __shared__ __nv_bfloat16 As1[BM][ASTRIDE];
    __shared__ __nv_bfloat16 As2[BM][ASTRIDE];
    __shared__ __nv_bfloat16 Bs1[BK][BSTRIDE];
    __shared__ __nv_bfloat16 Bs2[BK][BSTRIDE];

    const int tid  = threadIdx.x;
    const int lane = tid & 31;
    const int warp = tid >> 5;
    const int wm = warp & 1;
    const int wn = warp >> 1;
    const int br = blockIdx.x * BM;
    const int bc = blockIdx.y * BN;
    const int gid = lane >> 2;
    const int qid = lane & 3;

    float acc[4][4][4];
#pragma unroll
    for (int mt = 0; mt < 4; mt++)
#pragma unroll
        for (int nt = 0; nt < 4; nt++)
#pragma unroll
            for (int j = 0; j < 4; j++) acc[mt][nt][j] = 0.f;

    const int aRow = ((lane >> 3) & 1) * 8 + (lane & 7);
    const int aKof = (lane >> 4) * 8;
    const int bK   = lane & 15;

    const int ktiles = (K + BK - 1) / BK;
    for (int kt = 0; kt < ktiles; kt++) {
        const int k0 = kt * BK;
#pragma unroll
        for (int it = 0; it < 4; it++) {
            int f = it * 256 + tid;
            int row = f >> 3, kq = (f & 7) * 4;
            float4 v = make_float4(0.f, 0.f, 0.f, 0.f);
            int gr = br + row;
            if (gr < M && (k0 + kq) < K)
                v = *reinterpret_cast<const float4*>(&A[(size_t)gr * K + k0 + kq]);
            __nv_bfloat16 h0, h1, h2, h3, l0, l1, l2, l3;
            split_bf16(v.x, h0, l0); split_bf16(v.y, h1, l1);
            split_bf16(v.z, h2, l2); split_bf16(v.w, h3, l3);
            *reinterpret_cast<__nv_bfloat162*>(&As1[row][kq])     = __nv_bfloat162(h0, h1);
            *reinterpret_cast<__nv_bfloat162*>(&As1[row][kq + 2]) = __nv_bfloat162(h2, h3);
            *reinterpret_cast<__nv_bfloat162*>(&As2[row][kq])     = __nv_bfloat162(l0, l1);
            *reinterpret_cast<__nv_bfloat162*>(&As2[row][kq + 2]) = __nv_bfloat162(l2, l3);
        }
#pragma unroll
        for (int it = 0; it < 4; it++) {
            int f = it * 256 + tid;
            int krow = f >> 5, n4 = (f & 31) * 4;
            float4 v = make_float4(0.f, 0.f, 0.f, 0.f);
            if ((k0 + krow) < K)
                v = *reinterpret_cast<const float4*>(&Bw[(size_t)(k0 + krow) * N + bc + n4]);
            __nv_bfloat16 h0, h1, h2, h3, l0, l1, l2, l3;
            split_bf16(v.x, h0, l0); split_bf16(v.y, h1, l1);
            split_bf16(v.z, h2, l2); split_bf16(v.w, h3, l3);
            *reinterpret_cast<__nv_bfloat162*>(&Bs1[krow][n4])     = __nv_bfloat162(h0, h1);
            *reinterpret_cast<__nv_bfloat162*>(&Bs1[krow][n4 + 2]) = __nv_bfloat162(h2, h3);
            *reinterpret_cast<__nv_bfloat162*>(&Bs2[krow][n4])     = __nv_bfloat162(l0, l1);
            *reinterpret_cast<__nv_bfloat162*>(&Bs2[krow][n4 + 2]) = __nv_bfloat162(l2, l3);
        }
        __syncthreads();

#pragma unroll
        for (int ks = 0; ks < 2; ks++) {
            const int kk = ks * 16;
            uint32_t bb[4][2], bs[4][2];
#pragma unroll
            for (int nt = 0; nt < 4; nt++) {
                const int n0 = wn * 32 + nt * 8;
                ldm_x2t(bb[nt], &Bs1[kk + bK][n0]);
                ldm_x2t(bs[nt], &Bs2[kk + bK][n0]);
            }
#pragma unroll
            for (int mt = 0; mt < 4; mt++) {
                const int r0 = wm * 64 + mt * 16 + aRow;
                uint32_t ah[4], al[4];
                ldm_x4(ah, &As1[r0][kk + aKof]);
                ldm_x4(al, &As2[r0][kk + aKof]);
#pragma unroll
                for (int nt = 0; nt < 4; nt++) {
                    mma_bf16(acc[mt][nt], al, bb[nt]);
                    mma_bf16(acc[mt][nt], ah, bs[nt]);
                    mma_bf16(acc[mt][nt], ah, bb[nt]);
                }
            }
        }
        __syncthreads();
    }

#pragma unroll
    for (int nt = 0; nt < 4; nt++) {
        const int c = bc + wn * 32 + nt * 8 + qid * 2;
        float b0 = 0.f, b1 = 0.f;
        if (bias) { b0 = bias[c]; b1 = bias[c + 1]; }
#pragma unroll
        for (int mt = 0; mt < 4; mt++) {
            int r0 = br + wm * 64 + mt * 16 + gid;
#pragma unroll
            for (int half = 0; half < 2; half++) {
                int r = r0 + half * 8;
                if (r >= M) continue;
                float v0 = acc[mt][nt][half * 2 + 0] + b0;
                float v1 = acc[mt][nt][half * 2 + 1] + b1;
                if (GELU) { v0 = gelu_f(v0); v1 = gelu_f(v1); }
                float2* p = reinterpret_cast<float2*>(&C[(size_t)r * N + c]);
                if (ACCUM) {
                    float2 o = *p;
                    o.x += v0; o.y += v1;
                    *p = o;
                } else {
                    *p = make_float2(v0, v1);
                }
            }
        }
    }
}

// ---------------- fully fused edge chain: eipoly -> basis -> kern0,kern1 --------
// h1 AND basis never leave smem. A tile stride 136 bf16: conflict-free ldmatrix.
constexpr int A2S = 136;
constexpr size_t FK_OFF_A1 = 0;
constexpr size_t FK_OFF_A2 = FK_OFF_A1 + (size_t)BM * A2S * 2;     // 34816
constexpr size_t FK_OFF_B1 = FK_OFF_A2 + (size_t)BM * A2S * 2;     // 69632
constexpr size_t FK_OFF_B2 = FK_OFF_B1 + (size_t)BK * BSTRIDE * 2; // 78336
constexpr size_t FK_SMEM   = FK_OFF_B2 + (size_t)BK * BSTRIDE * 2; // 87040
// phase-1 staging (eip tile, W1, b1) lives in the B region (union; 12.8KB <= 17.4KB)

struct KBCtx {
    const __nv_bfloat16 *As1, *As2;
    __nv_bfloat16 *Bs1, *Bs2;
    int tid, wm, wn, aRow, aKof, bK;
};

// one full K=128 mainloop against row-major weights Bw [128][128]
__device__ __forceinline__ void kb_mainloop(const KBCtx& cx,
                                            const float* __restrict__ Bw,
                                            float acc[4][4][4]) {
#pragma unroll
    for (int mt = 0; mt < 4; mt++)
#pragma unroll
        for (int nt = 0; nt < 4; nt++)
#pragma unroll
            for (int j = 0; j < 4; j++) acc[mt][nt][j] = 0.f;
#pragma unroll
    for (int kt = 0; kt < 4; kt++) {
        const int k0 = kt * BK;
#pragma unroll
        for (int it = 0; it < 4; it++) {
            int f = it * 256 + cx.tid;
            int krow = f >> 5, n4 = (f & 31) * 4;
            float4 v = *reinterpret_cast<const float4*>(&Bw[(size_t)(k0 + krow) * Hh + n4]);
            __nv_bfloat16 h0, h1, h2, h3, l0, l1, l2, l3;
            split_bf16(v.x, h0, l0); split_bf16(v.y, h1, l1);
            split_bf16(v.z, h2, l2); split_bf16(v.w, h3, l3);
            *reinterpret_cast<__nv_bfloat162*>(&cx.Bs1[krow * BSTRIDE + n4])     = __nv_bfloat162(h0, h1);
            *reinterpret_cast<__nv_bfloat162*>(&cx.Bs1[krow * BSTRIDE + n4 + 2]) = __nv_bfloat162(h2, h3);
            *reinterpret_cast<__nv_bfloat162*>(&cx.Bs2[krow * BSTRIDE + n4])     = __nv_bfloat162(l0, l1);
            *reinterpret_cast<__nv_bfloat162*>(&cx.Bs2[krow * BSTRIDE + n4 + 2]) = __nv_bfloat162(l2, l3);
        }
        __syncthreads();
#pragma unroll
        for (int ks = 0; ks < 2; ks++) {
            const int kk = ks * 16;
            uint32_t bb[4][2], bs[4][2];
#pragma unroll
            for (int nt = 0; nt < 4; nt++) {
                const int n0 = cx.wn * 32 + nt * 8;
                ldm_x2t(bb[nt], &cx.Bs1[(kk + cx.bK) * BSTRIDE + n0]);
                ldm_x2t(bs[nt], &cx.Bs2[(kk + cx.bK) * BSTRIDE + n0]);
            }
#pragma unroll
            for (int mt = 0; mt < 4; mt++) {
                const int r0 = cx.wm * 64 + mt * 16 + cx.aRow;
                uint32_t ah[4], al[4];
                ldm_x4(ah, &cx.As1[r0 * A2S + k0 + kk + cx.aKof]);
                ldm_x4(al, &cx.As2[r0 * A2S + k0 + kk + cx.aKof]);
#pragma unroll
                for (int nt = 0; nt < 4; nt++) {
                    mma_bf16(acc[mt][nt], al, bb[nt]);
                    mma_bf16(acc[mt][nt], ah, bs[nt]);
                    mma_bf16(acc[mt][nt], ah, bb[nt]);
                }
            }
        }
        __syncthreads();
    }
}

__global__ void __launch_bounds__(256, 2) k_basis_kern(
    const float* __restrict__ eip,
    const float* __restrict__ W1, const float* __restrict__ b1,
    const float* __restrict__ W2, const float* __restrict__ b2,
    const float* __restrict__ Wc,     // [2][128][128]
    float* __restrict__ kern0, float* __restrict__ kern1, int M) {
    extern __shared__ char smraw[];
    __nv_bfloat16* As1 = reinterpret_cast<__nv_bfloat16*>(smraw + FK_OFF_A1); // [128][136]
    __nv_bfloat16* As2 = reinterpret_cast<__nv_bfloat16*>(smraw + FK_OFF_A2);
    __nv_bfloat16* Bs1 = reinterpret_cast<__nv_bfloat16*>(smraw + FK_OFF_B1); // [32][136]
    __nv_bfloat16* Bs2 = reinterpret_cast<__nv_bfloat16*>(smraw + FK_OFF_B2);
    // phase-1 staging union (inside B region): EIP[1536], W1s[1536], b1s[128]
    float* EIP = reinterpret_cast<float*>(smraw + FK_OFF_B1);
    float* W1s = EIP + BM * 12;
    float* b1s = W1s + 12 * Hh;

    const int tid  = threadIdx.x;
    const int lane = tid & 31;
    const int warp = tid >> 5;
    const int wm = warp & 1;
    const int wn = warp >> 1;
    const int br = blockIdx.x * BM;
    const int gid = lane >> 2;
    const int qid = lane & 3;

    KBCtx cx;
    cx.As1 = As1; cx.As2 = As2; cx.Bs1 = Bs1; cx.Bs2 = Bs2;
    cx.tid = tid; cx.wm = wm; cx.wn = wn;
    cx.aRow = ((lane >> 3) & 1) * 8 + (lane & 7);
    cx.aKof = (lane >> 4) * 8;
    cx.bK   = lane & 15;

    // ---- phase 1: stage eip tile + W1 + b1; compute h1 -> As (split bf16) ----
    for (int f = tid; f < 12 * Hh; f += 256) W1s[f] = W1[f];
    if (tid < Hh) b1s[tid] = b1[tid];
    {
        const int total4 = (EROWS * 12) / 4;
        const int base4 = br * 3;
#pragma unroll
        for (int it = 0; it < 2; it++) {
            int f = it * 256 + tid;
            if (f < 384) {
                float4 v = make_float4(0.f, 0.f, 0.f, 0.f);
                if (base4 + f < total4)
                    v = *reinterpret_cast<const float4*>(&eip[(size_t)(base4 + f) * 4]);
                *reinterpret_cast<float4*>(&EIP[f * 4]) = v;
            }
        }
    }
    __syncthreads();
    {
        const int r  = tid >> 1;
        const int cb = (tid & 1) * 64;
        float e[12];
#pragma unroll
        for (int k = 0; k < 12; k++) e[k] = EIP[r * 12 + k];
        __syncthreads();   // done reading EIP before B region reused as Bs
#pragma unroll
        for (int c2 = 0; c2 < 64; c2 += 2) {
            int c = cb + c2;
            float a0 = 0.f, a1 = 0.f;
#pragma unroll
            for (int k = 0; k < 12; k++) {
                a0 = fmaf(e[k], W1s[k * Hh + c], a0);
                a1 = fmaf(e[k], W1s[k * Hh + c + 1], a1);
            }
            // NOTE: W1s/b1s also live in B region — read them before Bs writes.
            a0 = gelu_f(a0 + b1s[c]); a1 = gelu_f(a1 + b1s[c + 1]);
            __nv_bfloat16 h0, l0, h1, l1;
            split_bf16(a0, h0, l0);
            split_bf16(a1, h1, l1);
            *reinterpret_cast<__nv_bfloat162*>(&As1[r * A2S + c]) = __nv_bfloat162(h0, h1);
            *reinterpret_cast<__nv_bfloat162*>(&As2[r * A2S + c]) = __nv_bfloat162(l0, l1);
        }
    }
    __syncthreads();

    float acc[4][4][4];

    // ---- phase 2: basis = gelu(h1 @ W2 + b2), kept in registers then smem ----
    kb_mainloop(cx, W2, acc);
    {
#pragma unroll
        for (int nt = 0; nt < 4; nt++) {
            const int c = wn * 32 + nt * 8 + qid * 2;
            float bb0 = b2[c], bb1 = b2[c + 1];
#pragma unroll
            for (int mt = 0; mt < 4; mt++) {
                int rl = wm * 64 + mt * 16 + gid;
#pragma unroll
                for (int half = 0; half < 2; half++) {
                    int r = rl + half * 8;
                    float v0 = gelu_f(acc[mt][nt][half * 2 + 0] + bb0);
                    float v1 = gelu_f(acc[mt][nt][half * 2 + 1] + bb1);
                    __nv_bfloat16 h0, l0, h1, l1;
                    split_bf16(v0, h0, l0);
                    split_bf16(v1, h1, l1);
                    *reinterpret_cast<__nv_bfloat162*>(&As1[r * A2S + c]) = __nv_bfloat162(h0, h1);
                    *reinterpret_cast<__nv_bfloat162*>(&As2[r * A2S + c]) = __nv_bfloat162(l0, l1);
                }
            }
        }
    }
    __syncthreads();

    // ---- phase 3: kern_l = basis @ W_conv[l], l = 0,1 ----
#pragma unroll
    for (int l = 0; l < 2; l++) {
        kb_mainloop(cx, Wc + (size_t)l * BDd * Hh, acc);
        float* kern = l == 0 ? kern0 : kern1;
#pragma unroll
        for (int nt = 0; nt < 4; nt++) {
            const int c = wn * 32 + nt * 8 + qid * 2;
#pragma unroll
            for (int mt = 0; mt < 4; mt++) {
                int r0 = br + wm * 64 + mt * 16 + gid;
#pragma unroll
                for (int half = 0; half < 2; half++) {
                    int r = r0 + half * 8;
                    if (r >= M) continue;
                    *reinterpret_cast<float2*>(&kern[(size_t)r * Hh + c]) =
                        make_float2(acc[mt][nt][half * 2 + 0], acc[mt][nt][half * 2 + 1]);
                }
            }
        }
        // no sync needed between l=0 epilogue and l=1 B-loads beyond the
        // __syncthreads already inside kb_mainloop's first k-tile
    }
}

// ---------------- host launch ----------------------------------------------------
static void launch_gemm(const float* A, const float* W, const float* bias, float* C,
                        int M, int N, int K, bool gelu_act, bool accum) {
    dim3 grid((M + BM - 1) / BM, N / BN);
    if (gelu_act)   gemm_bf16x3<true, false><<<grid, 256>>>(A, W, bias, C, M, N, K);
    else if (accum) gemm_bf16x3<false, true><<<grid, 256>>>(A, W, bias, C, M, N, K);
    else            gemm_bf16x3<false, false><<<grid, 256>>>(A, W, bias, C, M, N, K);
}

extern "C" void kernel_launch(void* const* d_in, const int* in_sizes, int n_in,
                              void* d_out, int out_size) {
    const float* pos      = (const float*)d_in[0];
    const float* vel      = (const float*)d_in[1];
    const float* charges  = (const float*)d_in[2];
    const int*   batch    = (const int*)d_in[3];
    const int*   eidx     = (const int*)d_in[4];
    const float* grid0    = (const float*)d_in[5];
    const float* R        = (const float*)d_in[6];
    const float* W_basis1 = (const float*)d_in[7];
    const float* b_basis1 = (const float*)d_in[8];
    const float* W_basis2 = (const float*)d_in[9];
    const float* b_basis2 = (const float*)d_in[10];
    const float* W_fbasis1 = (const float*)d_in[11];
    const float* b_fbasis1 = (const float*)d_in[12];
    const float* W_fbasis2 = (const float*)d_in[13];
    const float* b_fbasis2 = (const float*)d_in[14];
    const float* W_embed  = (const float*)d_in[15];
    const float* W_conv   = (const float*)d_in[16];
    const float* W_fiber  = (const float*)d_in[17];
    const float* b_conv   = (const float*)d_in[18];
    const float* ln_gamma = (const float*)d_in[19];
    const float* ln_beta  = (const float*)d_in[20];
    const float* W_ff1    = (const float*)d_in[21];
    const float* b_ff1    = (const float*)d_in[22];
    const float* W_ff2    = (const float*)d_in[23];
    const float* b_ff2    = (const float*)d_in[24];
    const float* W_ro1    = (const float*)d_in[25];
    const float* b_ro1    = (const float*)d_in[26];
    const float* W_ro2    = (const float*)d_in[27];
    const float* b_ro2    = (const float*)d_in[28];
    float* out = (float*)d_out;

    float *kern0, *kern1, *x, *x2, *ffh, *eip, *fip, *fh1, *fbasis, *fk, *gsum;
    int *deg, *cur;
    cudaGetSymbolAddress((void**)&kern0, g_kern0);
    cudaGetSymbolAddress((void**)&kern1, g_kern1);
    cudaGetSymbolAddress((void**)&x,     g_x);
    cudaGetSymbolAddress((void**)&x2,    g_x2);
    cudaGetSymbolAddress((void**)&ffh,   g_ffh);
    cudaGetSymbolAddress((void**)&eip,   g_eipoly);
    cudaGetSymbolAddress((void**)&fip,   g_fipoly);
    cudaGetSymbolAddress((void**)&fh1,   g_fh1);
    cudaGetSymbolAddress((void**)&fbasis,g_fbasis);
    cudaGetSymbolAddress((void**)&fk,    g_fk);
    cudaGetSymbolAddress((void**)&gsum,  g_gsum);
    cudaGetSymbolAddress((void**)&deg,   g_deg);
    cudaGetSymbolAddress((void**)&cur,   g_cur);

    static bool attr_done = false;
    if (!attr_done) {
        cudaFuncSetAttribute(k_basis_kern, cudaFuncAttributeMaxDynamicSharedMemorySize,
                             (int)FK_SMEM);
        attr_done = true;
    }

    // graph statistics + rotated grids
    k_zero<<<(Bb * 4 + 255) / 256, 256>>>(gsum, Bb * 4);
    k_gsum<<<(Nn + 255) / 256, 256>>>(pos, batch);
    k_grid_node<<<(Nn * NGg + 255) / 256, 256>>>(batch, grid0, R);

    // CSR by destination (built once, reused by both layers)
    k_zero_int<<<(Nn + 255) / 256, 256>>>(deg, Nn);
    k_zero_int<<<(Nn + 255) / 256, 256>>>(cur, Nn);
    k_count<<<(Ee + 255) / 256, 256>>>(eidx);
    k_scan<<<1, 1024>>>();
    k_fill<<<(Ee + 255) / 256, 256>>>(eidx);

    // edge chain fully fused: eipoly -> basis (smem only) -> kern0, kern1
    k_eipoly<<<(EROWS + 255) / 256, 256>>>(pos, charges, eidx);
    k_basis_kern<<<(EROWS + BM - 1) / BM, 256, FK_SMEM>>>(
        eip, W_basis1, b_basis1, W_basis2, b_basis2, W_conv, kern0, kern1, EROWS);

    // fiber basis MLP: 144 rows
    k_fipoly<<<1, 256>>>(grid0);
    k_small_gemm<<<(NGg * NGg * Hh + 255) / 256, 256>>>(fip, W_fbasis1, b_fbasis1, fh1,
                                                        NGg * NGg, Hh, 2, 1);
    k_small_gemm<<<(NGg * NGg * BDd + 255) / 256, 256>>>(fh1, W_fbasis2, b_fbasis2, fbasis,
                                                         NGg * NGg, BDd, Hh, 1);

    // node embedding
    k_embed<<<NROWS, Hh>>>(pos, vel, charges, batch, W_embed);

    for (int l = 0; l < Ll; l++) {
        // fk = fiber_basis @ W_fiber[l]
        k_small_gemm<<<(NGg * NGg * Hh + 255) / 256, 256>>>(
            fbasis, W_fiber + (size_t)l * BDd * Hh, nullptr, fk, NGg * NGg, Hh, BDd, 0);
        // fused: x1 = gather-sum(kern_l * x[src] -> dst); x2 = LN(fiber(x1))
        k_gather_fiber_ln<<<Nn, Hh>>>(eidx, l == 0 ? kern0 : kern1, b_conv + l * Hh,
                                      ln_gamma + l * Hh, ln_beta + l * Hh);
        // FF: x += W_ff2 @ gelu(W_ff1 @ h)
        launch_gemm(x2, W_ff1 + (size_t)l * Hh * 4 * Hh, b_ff1 + l * 4 * Hh, ffh,
                    NROWS, 4 * Hh, Hh, true, false);
        launch_gemm(ffh, W_ff2 + (size_t)l * 4 * Hh * Hh, b_ff2 + l * Hh, x,
                    NROWS, Hh, 4 * Hh, false, true);
    }

    // readout
    launch_gemm(x, W_ro1, b_ro1, ffh, NROWS, Hh, Hh, true, false);
    k_output<<<Nn, Hh>>>(W_ro2, b_ro2, out);
}

// round 14
// speedup vs baseline: 1.2170x; 1.0132x over previous
#include <cuda_runtime.h>
#include <cuda_bf16.h>
#include <math.h>
#include <stdint.h>

// Problem dims (fixed by the dataset)
constexpr int Nn  = 4000;
constexpr int Ee  = 50000;
constexpr int NGg = 12;
constexpr int Hh  = 128;
constexpr int BDd = 128;
constexpr int Ll  = 2;
constexpr int Bb  = 100;

constexpr int EROWS = Ee * NGg;     // 600000
constexpr int NROWS = Nn * NGg;     // 48000

// ---------------- scratch (device globals; no cudaMalloc allowed) -------------
__device__ __align__(16) float g_grid_node[Nn * NGg * 3];
__device__ __align__(16) float g_kern0[(size_t)EROWS * Hh];
__device__ __align__(16) float g_kern1[(size_t)EROWS * Hh];
__device__ __align__(16) float g_x  [NROWS * Hh];
__device__ __align__(16) float g_x2 [NROWS * Hh];
__device__ __align__(16) float g_ffh[NROWS * 4 * Hh];
__device__ __align__(16) float g_fipoly[NGg * NGg * 2];
__device__ __align__(16) float g_fh1   [NGg * NGg * Hh];
__device__ __align__(16) float g_fbasis[NGg * NGg * BDd];
__device__ __align__(16) float g_fk    [NGg * NGg * Hh];
__device__ float g_gsum[Bb * 4];   // per-graph: sum_x, sum_y, sum_z, count
// CSR by destination
__device__ int g_deg[Nn];
__device__ int g_off[Nn + 1];
__device__ int g_cur[Nn];
__device__ int g_csr[Ee];

__device__ __forceinline__ float gelu_f(float x) {
    return 0.5f * x * (1.0f + erff(x * 0.70710678118654752f));
}

// ---------------- tiny kernels -------------------------------------------------
// zero deg, cur (ints) and gsum (floats) in one launch
__global__ void k_init() {
    int i = blockIdx.x * blockDim.x + threadIdx.x;
    if (i < Nn) { g_deg[i] = 0; g_cur[i] = 0; }
    if (i < Bb * 4) g_gsum[i] = 0.f;
}

__global__ void k_gsum(const float* __restrict__ pos, const int* __restrict__ batch) {
    int n = blockIdx.x * blockDim.x + threadIdx.x;
    if (n >= Nn) return;
    int b = batch[n];
    atomicAdd(&g_gsum[b * 4 + 0], pos[n * 3 + 0]);
    atomicAdd(&g_gsum[b * 4 + 1], pos[n * 3 + 1]);
    atomicAdd(&g_gsum[b * 4 + 2], pos[n * 3 + 2]);
    atomicAdd(&g_gsum[b * 4 + 3], 1.f);
}

__global__ void k_grid_node(const int* __restrict__ batch,
                            const float* __restrict__ grid0,
                            const float* __restrict__ R) {
    int idx = blockIdx.x * blockDim.x + threadIdx.x;  // n*NG + k
    if (idx >= Nn * NGg) return;
    int n = idx / NGg, k = idx % NGg;
    const float* Rb = R + batch[n] * 9;
    float gx = grid0[k * 3 + 0], gy = grid0[k * 3 + 1], gz = grid0[k * 3 + 2];
    float* o = g_grid_node + idx * 3;
    o[0] = Rb[0] * gx + Rb[1] * gy + Rb[2] * gz;
    o[1] = Rb[3] * gx + Rb[4] * gy + Rb[5] * gz;
    o[2] = Rb[6] * gx + Rb[7] * gy + Rb[8] * gz;
}

__global__ void k_fipoly(const float* __restrict__ grid0) {
    int idx = threadIdx.x;
    if (idx >= NGg * NGg) return;
    int p = idx / NGg, o = idx % NGg;
    float fi = grid0[p * 3 + 0] * grid0[o * 3 + 0] +
               grid0[p * 3 + 1] * grid0[o * 3 + 1] +
               grid0[p * 3 + 2] * grid0[o * 3 + 2];
    g_fipoly[idx * 2 + 0] = fi;
    g_fipoly[idx * 2 + 1] = fi * fi;
}

// naive GEMM for tiny fiber matrices (M=144) — fp32, negligible time
__global__ void k_small_gemm(const float* __restrict__ A, const float* __restrict__ W,
                             const float* __restrict__ bias, float* __restrict__ C,
                             int M, int N, int K, int act) {
    int idx = blockIdx.x * blockDim.x + threadIdx.x;
    if (idx >= M * N) return;
    int r = idx / N, c = idx % N;
    float acc = bias ? bias[c] : 0.f;
    for (int k = 0; k < K; k++) acc = fmaf(A[r * K + k], W[k * N + c], acc);
    C[idx] = act ? gelu_f(acc) : acc;
}

__global__ void k_embed(const float* __restrict__ pos, const float* __restrict__ vel,
                        const float* __restrict__ charges, const int* __restrict__ batch,
                        const float* __restrict__ We) {
    int nk = blockIdx.x;           // n*NG + k
    int h = threadIdx.x;           // 0..127
    int n = nk / NGg;
    const float* g = g_grid_node + nk * 3;
    float vx = vel[n * 3 + 0], vy = vel[n * 3 + 1], vz = vel[n * 3 + 2];
    int b = batch[n];
    float cnt = fmaxf(g_gsum[b * 4 + 3], 1.f);
    float rpx = pos[n * 3 + 0] - g_gsum[b * 4 + 0] / cnt;
    float rpy = pos[n * 3 + 1] - g_gsum[b * 4 + 1] / cnt;
    float rpz = pos[n * 3 + 2] - g_gsum[b * 4 + 2] / cnt;
    float f0 = vx * g[0] + vy * g[1] + vz * g[2];
    float f1 = rpx * g[0] + rpy * g[1] + rpz * g[2];
    float f2 = charges[n];
    float f3 = sqrtf(vx * vx + vy * vy + vz * vz);
    g_x[(size_t)nk * Hh + h] =
        f0 * We[h] + f1 * We[Hh + h] + f2 * We[2 * Hh + h] + f3 * We[3 * Hh + h];
}

// ---------------- CSR build (by destination) ------------------------------------
__global__ void k_count(const int* __restrict__ eidx) {
    int e = blockIdx.x * blockDim.x + threadIdx.x;
    if (e >= Ee) return;
    atomicAdd(&g_deg[eidx[Ee + e]], 1);
}

__global__ void k_scan() {
    __shared__ int sh[1024];
    int tid = threadIdx.x;
    int base = tid * 4;
    int v[4];
    int s0 = 0;
#pragma unroll
    for (int i = 0; i < 4; i++) {
        int idx = base + i;
        v[i] = (idx < Nn) ? g_deg[idx] : 0;
        s0 += v[i];
    }
    sh[tid] = s0;
    __syncthreads();
    for (int off = 1; off < 1024; off <<= 1) {
        int t = (tid >= off) ? sh[tid - off] : 0;
        __syncthreads();
        sh[tid] += t;
        __syncthreads();
    }
    int ex = sh[tid] - s0;
#pragma unroll
    for (int i = 0; i < 4; i++) {
        int idx = base + i;
        if (idx < Nn) { g_off[idx] = ex; ex += v[i]; }
    }
    if (tid == 1023) g_off[Nn] = sh[1023];
}

__global__ void k_fill(const int* __restrict__ eidx) {
    int e = blockIdx.x * blockDim.x + threadIdx.x;
    if (e >= Ee) return;
    int d = eidx[Ee + e];
    int pos = g_off[d] + atomicAdd(&g_cur[d], 1);
    g_csr[pos] = e;
}

// ---------------- fused gather + fiber contraction + LayerNorm ------------------
__global__ void __launch_bounds__(128) k_gather_fiber_ln(
    const int* __restrict__ eidx, const float* __restrict__ kern,
    const float* __restrict__ bconv, const float* __restrict__ gamma,
    const float* __restrict__ beta) {
    int n = blockIdx.x;
    int c = threadIdx.x;
    float acc[NGg];
#pragma unroll
    for (int o = 0; o < NGg; o++) acc[o] = 0.f;

    const int beg = g_off[n], end = g_off[n + 1];
    for (int j = beg; j < end; j++) {
        int e = g_csr[j];
        int s = eidx[e];
        const float* kr = &kern[(size_t)e * NGg * Hh + c];
        const float* xr = &g_x[(size_t)s * NGg * Hh + c];
#pragma unroll
        for (int o = 0; o < NGg; o++)
            acc[o] = fmaf(kr[o * Hh], xr[o * Hh], acc[o]);
    }

    __shared__ float red[4];
    for (int p = 0; p < NGg; p++) {
        float v = 0.f;
        const float* fkp = &g_fk[(size_t)p * NGg * Hh + c];
#pragma unroll
        for (int o = 0; o < NGg; o++)
            v = fmaf(acc[o], fkp[o * Hh], v);
        v = v * (1.0f / NGg) + bconv[c];

        float s = v;
#pragma unroll
        for (int off = 16; off > 0; off >>= 1) s += __shfl_down_sync(0xffffffffu, s, off);
        if ((c & 31) == 0) red[c >> 5] = s;
        __syncthreads();
        float mean = (red[0] + red[1] + red[2] + red[3]) * (1.f / Hh);
        __syncthreads();
        float dd = v - mean;
        s = dd * dd;
#pragma unroll
        for (int off = 16; off > 0; off >>= 1) s += __shfl_down_sync(0xffffffffu, s, off);
        if ((c & 31) == 0) red[c >> 5] = s;
        __syncthreads();
        float var = (red[0] + red[1] + red[2] + red[3]) * (1.f / Hh);
        g_x2[((size_t)n * NGg + p) * Hh + c] = dd * rsqrtf(var + 1e-5f) * gamma[c] + beta[c];
        __syncthreads();
    }
}

// out[n,d] = (1/NG) sum_k grid_node[n,k,d] * (t[n,k,:]·W_ro2 + b_ro2)
__global__ void k_output(const float* __restrict__ Wro2, const float* __restrict__ bro2,
                         float* __restrict__ out) {
    int n = blockIdx.x;
    int h = threadIdx.x;
    __shared__ float red[4];
    __shared__ float ybc;
    float a0 = 0.f, a1 = 0.f, a2 = 0.f;
    for (int k = 0; k < NGg; k++) {
        float s = g_ffh[((size_t)(n * NGg + k)) * Hh + h] * Wro2[h];
#pragma unroll
        for (int off = 16; off > 0; off >>= 1) s += __shfl_down_sync(0xffffffffu, s, off);
        if ((h & 31) == 0) red[h >> 5] = s;
        __syncthreads();
        if (h == 0) ybc = red[0] + red[1] + red[2] + red[3] + bro2[0];
        __syncthreads();
        float y = ybc;
        a0 += g_grid_node[(n * NGg + k) * 3 + 0] * y;
        a1 += g_grid_node[(n * NGg + k) * 3 + 1] * y;
        a2 += g_grid_node[(n * NGg + k) * 3 + 2] * y;
        __syncthreads();
    }
    if (h == 0) {
        out[n * 3 + 0] = a0 * (1.f / NGg);
        out[n * 3 + 1] = a1 * (1.f / NGg);
        out[n * 3 + 2] = a2 * (1.f / NGg);
    }
}

// ---------------- bf16x3 tensor-core GEMM (≈fp32 accuracy) ---------------------
constexpr int BM = 128, BN = 128, BK = 32;
constexpr int ASTRIDE = BK + 8;      // 40 bf16/row -> conflict-free ldmatrix
constexpr int BSTRIDE = BN + 8;      // 136 bf16/row -> conflict-free ldmatrix(.trans)

__device__ __forceinline__ void mma_bf16(float* d, const uint32_t* a, const uint32_t* b) {
    asm volatile(
        "mma.sync.aligned.m16n8k16.row.col.f32.bf16.bf16.f32 "
        "{%0,%1,%2,%3}, {%4,%5,%6,%7}, {%8,%9}, {%0,%1,%2,%3};\n"
        : "+f"(d[0]), "+f"(d[1]), "+f"(d[2]), "+f"(d[3])
        : "r"(a[0]), "r"(a[1]), "r"(a[2]), "r"(a[3]), "r"(b[0]), "r"(b[1]));
}

__device__ __forceinline__ void ldm_x4(uint32_t* r, const __nv_bfloat16* p) {
    uint32_t addr = (uint32_t)__cvta_generic_to_shared(p);
    asm volatile("ldmatrix.sync.aligned.m8n8.x4.shared.b16 {%0,%1,%2,%3}, [%4];"
                 : "=r"(r[0]), "=r"(r[1]), "=r"(r[2]), "=r"(r[3]) : "r"(addr));
}

__device__ __forceinline__ void ldm_x2t(uint32_t* r, const __nv_bfloat16* p) {
    uint32_t addr = (uint32_t)__cvta_generic_to_shared(p);
    asm volatile("ldmatrix.sync.aligned.m8n8.x2.trans.shared.b16 {%0,%1}, [%2];"
                 : "=r"(r[0]), "=r"(r[1]) : "r"(addr));
}

__device__ __forceinline__ void split_bf16(float v, __nv_bfloat16& hi, __nv_bfloat16& lo) {
    hi = __float2bfloat16_rn(v);
    lo = __float2bfloat16_rn(v - __bfloat162float(hi));
}

template <bool GELU, bool ACCUM>
__global__ void __launch_bounds__(256, 2) gemm_bf16x3(
    const float* __restrict__ A, const float* __restrict__ Bw,
    const float* __restrict__ bias, float* __restrict__ C,
    int M, int N, int K) {
    __shared__ __nv_bfloat16 As1[BM][ASTRIDE];
    __shared__ __nv_bfloat16 As2[BM][ASTRIDE];
    __shared__ __nv_bfloat16 Bs1[BK][BSTRIDE];
    __shared__ __nv_bfloat16 Bs2[BK][BSTRIDE];

    const int tid  = threadIdx.x;
    const int lane = tid & 31;
    const int warp = tid >> 5;
    const int wm = warp & 1;
    const int wn = warp >> 1;
    const int br = blockIdx.x * BM;
    const int bc = blockIdx.y * BN;
    const int gid = lane >> 2;
    const int qid = lane & 3;

    float acc[4][4][4];
#pragma unroll
    for (int mt = 0; mt < 4; mt++)
#pragma unroll
        for (int nt = 0; nt < 4; nt++)
#pragma unroll
            for (int j = 0; j < 4; j++) acc[mt][nt][j] = 0.f;

    const int aRow = ((lane >> 3) & 1) * 8 + (lane & 7);
    const int aKof = (lane >> 4) * 8;
    const int bK   = lane & 15;

    const int ktiles = (K + BK - 1) / BK;
    for (int kt = 0; kt < ktiles; kt++) {
        const int k0 = kt * BK;
#pragma unroll
        for (int it = 0; it < 4; it++) {
            int f = it * 256 + tid;
            int row = f >> 3, kq = (f & 7) * 4;
            float4 v = make_float4(0.f, 0.f, 0.f, 0.f);
            int gr = br + row;
            if (gr < M && (k0 + kq) < K)
                v = *reinterpret_cast<const float4*>(&A[(size_t)gr * K + k0 + kq]);
            __nv_bfloat16 h0, h1, h2, h3, l0, l1, l2, l3;
            split_bf16(v.x, h0, l0); split_bf16(v.y, h1, l1);
            split_bf16(v.z, h2, l2); split_bf16(v.w, h3, l3);
            *reinterpret_cast<__nv_bfloat162*>(&As1[row][kq])     = __nv_bfloat162(h0, h1);
            *reinterpret_cast<__nv_bfloat162*>(&As1[row][kq + 2]) = __nv_bfloat162(h2, h3);
            *reinterpret_cast<__nv_bfloat162*>(&As2[row][kq])     = __nv_bfloat162(l0, l1);
            *reinterpret_cast<__nv_bfloat162*>(&As2[row][kq + 2]) = __nv_bfloat162(l2, l3);
        }
#pragma unroll
        for (int it = 0; it < 4; it++) {
            int f = it * 256 + tid;
            int krow = f >> 5, n4 = (f & 31) * 4;
            float4 v = make_float4(0.f, 0.f, 0.f, 0.f);
            if ((k0 + krow) < K)
                v = *reinterpret_cast<const float4*>(&Bw[(size_t)(k0 + krow) * N + bc + n4]);
            __nv_bfloat16 h0, h1, h2, h3, l0, l1, l2, l3;
            split_bf16(v.x, h0, l0); split_bf16(v.y, h1, l1);
            split_bf16(v.z, h2, l2); split_bf16(v.w, h3, l3);
            *reinterpret_cast<__nv_bfloat162*>(&Bs1[krow][n4])     = __nv_bfloat162(h0, h1);
            *reinterpret_cast<__nv_bfloat162*>(&Bs1[krow][n4 + 2]) = __nv_bfloat162(h2, h3);
            *reinterpret_cast<__nv_bfloat162*>(&Bs2[krow][n4])     = __nv_bfloat162(l0, l1);
            *reinterpret_cast<__nv_bfloat162*>(&Bs2[krow][n4 + 2]) = __nv_bfloat162(l2, l3);
        }
        __syncthreads();

#pragma unroll
        for (int ks = 0; ks < 2; ks++) {
            const int kk = ks * 16;
            uint32_t bb[4][2], bs[4][2];
#pragma unroll
            for (int nt = 0; nt < 4; nt++) {
                const int n0 = wn * 32 + nt * 8;
                ldm_x2t(bb[nt], &Bs1[kk + bK][n0]);
                ldm_x2t(bs[nt], &Bs2[kk + bK][n0]);
            }
#pragma unroll
            for (int mt = 0; mt < 4; mt++) {
                const int r0 = wm * 64 + mt * 16 + aRow;
                uint32_t ah[4], al[4];
                ldm_x4(ah, &As1[r0][kk + aKof]);
                ldm_x4(al, &As2[r0][kk + aKof]);
#pragma unroll
                for (int nt = 0; nt < 4; nt++) {
                    mma_bf16(acc[mt][nt], al, bb[nt]);
                    mma_bf16(acc[mt][nt], ah, bs[nt]);
                    mma_bf16(acc[mt][nt], ah, bb[nt]);
                }
            }
        }
        __syncthreads();
    }

#pragma unroll
    for (int nt = 0; nt < 4; nt++) {
        const int c = bc + wn * 32 + nt * 8 + qid * 2;
        float b0 = 0.f, b1 = 0.f;
        if (bias) { b0 = bias[c]; b1 = bias[c + 1]; }
#pragma unroll
        for (int mt = 0; mt < 4; mt++) {
            int r0 = br + wm * 64 + mt * 16 + gid;
#pragma unroll
            for (int half = 0; half < 2; half++) {
                int r = r0 + half * 8;
                if (r >= M) continue;
                float v0 = acc[mt][nt][half * 2 + 0] + b0;
                float v1 = acc[mt][nt][half * 2 + 1] + b1;
                if (GELU) { v0 = gelu_f(v0); v1 = gelu_f(v1); }
                float2* p = reinterpret_cast<float2*>(&C[(size_t)r * N + c]);
                if (ACCUM) {
                    float2 o = *p;
                    o.x += v0; o.y += v1;
                    *p = o;
                } else {
                    *p = make_float2(v0, v1);
                }
            }
        }
    }
}

// ---------------- fully fused edge chain: features -> basis -> kern0,kern1 ------
// ei_poly, h1 AND basis never leave smem. A tile stride 136 bf16: conflict-free.
// B tiles double-buffered: next weight tile prefetched to regs during compute.
constexpr int A2S = 136;
constexpr int BTILE = BK * BSTRIDE;                                 // bf16 elems/buffer
constexpr size_t FK_OFF_A1 = 0;
constexpr size_t FK_OFF_A2 = FK_OFF_A1 + (size_t)BM * A2S * 2;      // 34816
constexpr size_t FK_OFF_B1 = FK_OFF_A2 + (size_t)BM * A2S * 2;      // 69632 (2 buffers)
constexpr size_t FK_OFF_B2 = FK_OFF_B1 + (size_t)2 * BTILE * 2;     // 87040 (2 buffers)
constexpr size_t FK_SMEM   = FK_OFF_B2 + (size_t)2 * BTILE * 2;     // 104448
// phase-1 staging (EIP, W1, b1 = 12.8KB) unions into the B1 region (17.4KB)

struct KBCtx {
    const __nv_bfloat16 *As1, *As2;
    __nv_bfloat16 *Bs1, *Bs2;        // base of 2-buffer arrays
    int tid, wm, wn, aRow, aKof, bK;
};

__device__ __forceinline__ void kb_store_B(const KBCtx& cx, int buf, const float4* v) {
    __nv_bfloat16* B1 = cx.Bs1 + buf * BTILE;
    __nv_bfloat16* B2 = cx.Bs2 + buf * BTILE;
#pragma unroll
    for (int it = 0; it < 4; it++) {
        int f = it * 256 + cx.tid;
        int krow = f >> 5, n4 = (f & 31) * 4;
        __nv_bfloat16 h0, h1, h2, h3, l0, l1, l2, l3;
        split_bf16(v[it].x, h0, l0); split_bf16(v[it].y, h1, l1);
        split_bf16(v[it].z, h2, l2); split_bf16(v[it].w, h3, l3);
        *reinterpret_cast<__nv_bfloat162*>(&B1[krow * BSTRIDE + n4])     = __nv_bfloat162(h0, h1);
        *reinterpret_cast<__nv_bfloat162*>(&B1[krow * BSTRIDE + n4 + 2]) = __nv_bfloat162(h2, h3);
        *reinterpret_cast<__nv_bfloat162*>(&B2[krow * BSTRIDE + n4])     = __nv_bfloat162(l0, l1);
        *reinterpret_cast<__nv_bfloat162*>(&B2[krow * BSTRIDE + n4 + 2]) = __nv_bfloat162(l2, l3);
    }
}

__device__ __forceinline__ void kb_load_B(const KBCtx& cx, const float* __restrict__ Bw,
                                          int k0, float4* v) {
#pragma unroll
    for (int it = 0; it < 4; it++) {
        int f = it * 256 + cx.tid;
        int krow = f >> 5, n4 = (f & 31) * 4;
        v[it] = *reinterpret_cast<const float4*>(&Bw[(size_t)(k0 + krow) * Hh + n4]);
    }
}

// one full K=128 mainloop against row-major weights Bw [128][128], B double-buffered
__device__ __forceinline__ void kb_mainloop(const KBCtx& cx,
                                            const float* __restrict__ Bw,
                                            float acc[4][4][4]) {
#pragma unroll
    for (int mt = 0; mt < 4; mt++)
#pragma unroll
        for (int nt = 0; nt < 4; nt++)
#pragma unroll
            for (int j = 0; j < 4; j++) acc[mt][nt][j] = 0.f;

    float4 v[4];
    kb_load_B(cx, Bw, 0, v);
    kb_store_B(cx, 0, v);
    __syncthreads();

#pragma unroll
    for (int kt = 0; kt < 4; kt++) {
        const int k0 = kt * BK;
        if (kt < 3) kb_load_B(cx, Bw, k0 + BK, v);   // prefetch: overlaps compute
        const __nv_bfloat16* B1 = cx.Bs1 + (kt & 1) * BTILE;
        const __nv_bfloat16* B2 = cx.Bs2 + (kt & 1) * BTILE;
#pragma unroll
        for (int ks = 0; ks < 2; ks++) {
            const int kk = ks * 16;
            uint32_t bb[4][2], bs[4][2];
#pragma unroll
            for (int nt = 0; nt < 4; nt++) {
                const int n0 = cx.wn * 32 + nt * 8;
                ldm_x2t(bb[nt], &B1[(kk + cx.bK) * BSTRIDE + n0]);
                ldm_x2t(bs[nt], &B2[(kk + cx.bK) * BSTRIDE + n0]);
            }
#pragma unroll
            for (int mt = 0; mt < 4; mt++) {
                const int r0 = cx.wm * 64 + mt * 16 + cx.aRow;
                uint32_t ah[4], al[4];
                ldm_x4(ah, &cx.As1[r0 * A2S + k0 + kk + cx.aKof]);
                ldm_x4(al, &cx.As2[r0 * A2S + k0 + kk + cx.aKof]);
#pragma unroll
                for (int nt = 0; nt < 4; nt++) {
                    mma_bf16(acc[mt][nt], al, bb[nt]);
                    mma_bf16(acc[mt][nt], ah, bs[nt]);
                    mma_bf16(acc[mt][nt], ah, bb[nt]);
                }
            }
        }
        if (kt < 3) kb_store_B(cx, (kt + 1) & 1, v);  // other buffer: no WAR hazard
        __syncthreads();
    }
}

__global__ void __launch_bounds__(256, 2) k_basis_kern(
    const float* __restrict__ pos, const float* __restrict__ charges,
    const int* __restrict__ eidx,
    const float* __restrict__ W1, const float* __restrict__ b1,
    const float* __restrict__ W2, const float* __restrict__ b2,
    const float* __restrict__ Wc,     // [2][128][128]
    float* __restrict__ kern0, float* __restrict__ kern1, int M) {
    extern __shared__ char smraw[];
    __nv_bfloat16* As1 = reinterpret_cast<__nv_bfloat16*>(smraw + FK_OFF_A1); // [128][136]
    __nv_bfloat16* As2 = reinterpret_cast<__nv_bfloat16*>(smraw + FK_OFF_A2);
    __nv_bfloat16* Bs1 = reinterpret_cast<__nv_bfloat16*>(smraw + FK_OFF_B1); // 2x[32][136]
    __nv_bfloat16* Bs2 = reinterpret_cast<__nv_bfloat16*>(smraw + FK_OFF_B2);
    // phase-1 staging union (inside B1 region): EIP[1536], W1s[1536], b1s[128]
    float* EIP = reinterpret_cast<float*>(smraw + FK_OFF_B1);
    float* W1s = EIP + BM * 12;
    float* b1s = W1s + 12 * Hh;

    const int tid  = threadIdx.x;
    const int lane = tid & 31;
    const int warp = tid >> 5;
    const int wm = warp & 1;
    const int wn = warp >> 1;
    const int br = blockIdx.x * BM;
    const int gid = lane >> 2;
    const int qid = lane & 3;

    KBCtx cx;
    cx.As1 = As1; cx.As2 = As2; cx.Bs1 = Bs1; cx.Bs2 = Bs2;
    cx.tid = tid; cx.wm = wm; cx.wn = wn;
    cx.aRow = ((lane >> 3) & 1) * 8 + (lane & 7);
    cx.aKof = (lane >> 4) * 8;
    cx.bK   = lane & 15;

    // ---- phase 0: compute edge-invariant features in-kernel (one row/thread) ----
    for (int f = tid; f < 12 * Hh; f += 256) W1s[f] = W1[f];
    if (tid < Hh) b1s[tid] = b1[tid];
    if (tid < BM) {
        int row = br + tid;
        float f0 = 0.f, f1 = 0.f, f2 = 0.f;
        if (row < M) {
            int e = row / NGg;
            int k = row - e * NGg;
            int s = eidx[e], d = eidx[Ee + e];
            float rx = pos[s * 3 + 0] - pos[d * 3 + 0];
            float ry = pos[s * 3 + 1] - pos[d * 3 + 1];
            float rz = pos[s * 3 + 2] - pos[d * 3 + 2];
            const float* g = g_grid_node + (s * NGg + k) * 3;
            float inv1 = rx * g[0] + ry * g[1] + rz * g[2];
            float vx = rx - inv1 * g[0], vy = ry - inv1 * g[1], vz = rz - inv1 * g[2];
            float inv2 = sqrtf(vx * vx + vy * vy + vz * vz);
            f0 = inv1; f1 = inv2; f2 = charges[s] * charges[d];
        }
        float* o = &EIP[tid * 12];
        o[0] = f0;  o[1] = f1;  o[2] = f2;
        o[3] = f0 * f0; o[4]  = f0 * f1; o[5]  = f0 * f2;
        o[6] = f1 * f0; o[7]  = f1 * f1; o[8]  = f1 * f2;
        o[9] = f2 * f0; o[10] = f2 * f1; o[11] = f2 * f2;
    }
    __syncthreads();

    // ---- phase 1: h1 = gelu(eip@W1 + b1) -> As (split bf16, persistent) ----
    {
        const int r  = tid >> 1;
        const int cb = (tid & 1) * 64;
        float e[12];
#pragma unroll
        for (int k = 0; k < 12; k++) e[k] = EIP[r * 12 + k];
        float bloc[2];
        // (b1s read below, before B region reused as Bs buffers)
#pragma unroll
        for (int c2 = 0; c2 < 64; c2 += 2) {
            int c = cb + c2;
            float a0 = 0.f, a1 = 0.f;
#pragma unroll
            for (int k = 0; k < 12; k++) {
                a0 = fmaf(e[k], W1s[k * Hh + c], a0);
                a1 = fmaf(e[k], W1s[k * Hh + c + 1], a1);
            }
            bloc[0] = b1s[c]; bloc[1] = b1s[c + 1];
            a0 = gelu_f(a0 + bloc[0]); a1 = gelu_f(a1 + bloc[1]);
            __nv_bfloat16 h0, l0, h1, l1;
            split_bf16(a0, h0, l0);
            split_bf16(a1, h1, l1);
            *reinterpret_cast<__nv_bfloat162*>(&As1[r * A2S + c]) = __nv_bfloat162(h0, h1);
            *reinterpret_cast<__nv_bfloat162*>(&As2[r * A2S + c]) = __nv_bfloat162(l0, l1);
        }
    }
    __syncthreads();   // staging reads done; B region free for Bs buffers

    float acc[4][4][4];

    // ---- phase 2: basis = gelu(h1 @ W2 + b2) -> back into As (smem only) ----
    kb_mainloop(cx, W2, acc);
    {
#pragma unroll
        for (int nt = 0; nt < 4; nt++) {
            const int c = wn * 32 + nt * 8 + qid * 2;
            float bb0 = b2[c], bb1 = b2[c + 1];
#pragma unroll
            for (int mt = 0; mt < 4; mt++) {
                int rl = wm * 64 + mt * 16 + gid;
#pragma unroll
                for (int half = 0; half < 2; half++) {
                    int r = rl + half * 8;
                    float v0 = gelu_f(acc[mt][nt][half * 2 + 0] + bb0);
                    float v1 = gelu_f(acc[mt][nt][half * 2 + 1] + bb1);
                    __nv_bfloat16 h0, l0, h1, l1;
                    split_bf16(v0, h0, l0);
                    split_bf16(v1, h1, l1);
                    *reinterpret_cast<__nv_bfloat162*>(&As1[r * A2S + c]) = __nv_bfloat162(h0, h1);
                    *reinterpret_cast<__nv_bfloat162*>(&As2[r * A2S + c]) = __nv_bfloat162(l0, l1);
                }
            }
        }
    }
    __syncthreads();

    // ---- phase 3: kern_l = basis @ W_conv[l], l = 0,1 ----
#pragma unroll
    for (int l = 0; l < 2; l++) {
        kb_mainloop(cx, Wc + (size_t)l * BDd * Hh, acc);
        float* kern = l == 0 ? kern0 : kern1;
#pragma unroll
        for (int nt = 0; nt < 4; nt++) {
            const int c = wn * 32 + nt * 8 + qid * 2;
#pragma unroll
            for (int mt = 0; mt < 4; mt++) {
                int r0 = br + wm * 64 + mt * 16 + gid;
#pragma unroll
                for (int half = 0; half < 2; half++) {
                    int r = r0 + half * 8;
                    if (r >= M) continue;
                    *reinterpret_cast<float2*>(&kern[(size_t)r * Hh + c]) =
                        make_float2(acc[mt][nt][half * 2 + 0], acc[mt][nt][half * 2 + 1]);
                }
            }
        }
    }
}

// ---------------- host launch ----------------------------------------------------
static void launch_gemm(const float* A, const float* W, const float* bias, float* C,
                        int M, int N, int K, bool gelu_act, bool accum) {
    dim3 grid((M + BM - 1) / BM, N / BN);
    if (gelu_act)   gemm_bf16x3<true, false><<<grid, 256>>>(A, W, bias, C, M, N, K);
    else if (accum) gemm_bf16x3<false, true><<<grid, 256>>>(A, W, bias, C, M, N, K);
    else            gemm_bf16x3<false, false><<<grid, 256>>>(A, W, bias, C, M, N, K);
}

extern "C" void kernel_launch(void* const* d_in, const int* in_sizes, int n_in,
                              void* d_out, int out_size) {
    const float* pos      = (const float*)d_in[0];
    const float* vel      = (const float*)d_in[1];
    const float* charges  = (const float*)d_in[2];
    const int*   batch    = (const int*)d_in[3];
    const int*   eidx     = (const int*)d_in[4];
    const float* grid0    = (const float*)d_in[5];
    const float* R        = (const float*)d_in[6];
    const float* W_basis1 = (const float*)d_in[7];
    const float* b_basis1 = (const float*)d_in[8];
    const float* W_basis2 = (const float*)d_in[9];
    const float* b_basis2 = (const float*)d_in[10];
    const float* W_fbasis1 = (const float*)d_in[11];
    const float* b_fbasis1 = (const float*)d_in[12];
    const float* W_fbasis2 = (const float*)d_in[13];
    const float* b_fbasis2 = (const float*)d_in[14];
    const float* W_embed  = (const float*)d_in[15];
    const float* W_conv   = (const float*)d_in[16];
    const float* W_fiber  = (const float*)d_in[17];
    const float* b_conv   = (const float*)d_in[18];
    const float* ln_gamma = (const float*)d_in[19];
    const float* ln_beta  = (const float*)d_in[20];
    const float* W_ff1    = (const float*)d_in[21];
    const float* b_ff1    = (const float*)d_in[22];
    const float* W_ff2    = (const float*)d_in[23];
    const float* b_ff2    = (const float*)d_in[24];
    const float* W_ro1    = (const float*)d_in[25];
    const float* b_ro1    = (const float*)d_in[26];
    const float* W_ro2    = (const float*)d_in[27];
    const float* b_ro2    = (const float*)d_in[28];
    float* out = (float*)d_out;

    float *kern0, *kern1, *x, *x2, *ffh, *fip, *fh1, *fbasis, *fk;
    cudaGetSymbolAddress((void**)&kern0, g_kern0);
    cudaGetSymbolAddress((void**)&kern1, g_kern1);
    cudaGetSymbolAddress((void**)&x,     g_x);
    cudaGetSymbolAddress((void**)&x2,    g_x2);
    cudaGetSymbolAddress((void**)&ffh,   g_ffh);
    cudaGetSymbolAddress((void**)&fip,   g_fipoly);
    cudaGetSymbolAddress((void**)&fh1,   g_fh1);
    cudaGetSymbolAddress((void**)&fbasis,g_fbasis);
    cudaGetSymbolAddress((void**)&fk,    g_fk);

    static bool attr_done = false;
    if (!attr_done) {
        cudaFuncSetAttribute(k_basis_kern, cudaFuncAttributeMaxDynamicSharedMemorySize,
                             (int)FK_SMEM);
        attr_done = true;
    }

    // init + graph statistics + rotated grids
    k_init<<<(Nn + 255) / 256, 256>>>();
    k_gsum<<<(Nn + 255) / 256, 256>>>(pos, batch);
    k_grid_node<<<(Nn * NGg + 255) / 256, 256>>>(batch, grid0, R);

    // CSR by destination (built once, reused by both layers)
    k_count<<<(Ee + 255) / 256, 256>>>(eidx);
    k_scan<<<1, 1024>>>();
    k_fill<<<(Ee + 255) / 256, 256>>>(eidx);

    // edge chain fully fused: features -> h1 -> basis (all smem) -> kern0, kern1
    k_basis_kern<<<(EROWS + BM - 1) / BM, 256, FK_SMEM>>>(
        pos, charges, eidx, W_basis1, b_basis1, W_basis2, b_basis2, W_conv,
        kern0, kern1, EROWS);

    // fiber basis MLP: 144 rows
    k_fipoly<<<1, 256>>>(grid0);
    k_small_gemm<<<(NGg * NGg * Hh + 255) / 256, 256>>>(fip, W_fbasis1, b_fbasis1, fh1,
                                                        NGg * NGg, Hh, 2, 1);
    k_small_gemm<<<(NGg * NGg * BDd + 255) / 256, 256>>>(fh1, W_fbasis2, b_fbasis2, fbasis,
                                                         NGg * NGg, BDd, Hh, 1);

    // node embedding
    k_embed<<<NROWS, Hh>>>(pos, vel, charges, batch, W_embed);

    for (int l = 0; l < Ll; l++) {
        // fk = fiber_basis @ W_fiber[l]
        k_small_gemm<<<(NGg * NGg * Hh + 255) / 256, 256>>>(
            fbasis, W_fiber + (size_t)l * BDd * Hh, nullptr, fk, NGg * NGg, Hh, BDd, 0);
        // fused: x1 = gather-sum(kern_l * x[src] -> dst); x2 = LN(fiber(x1))
        k_gather_fiber_ln<<<Nn, Hh>>>(eidx, l == 0 ? kern0 : kern1, b_conv + l * Hh,
                                      ln_gamma + l * Hh, ln_beta + l * Hh);
        // FF: x += W_ff2 @ gelu(W_ff1 @ h)
        launch_gemm(x2, W_ff1 + (size_t)l * Hh * 4 * Hh, b_ff1 + l * 4 * Hh, ffh,
                    NROWS, 4 * Hh, Hh, true, false);
        launch_gemm(ffh, W_ff2 + (size_t)l * 4 * Hh * Hh, b_ff2 + l * Hh, x,
                    NROWS, Hh, 4 * Hh, false, true);
    }

    // readout
    launch_gemm(x, W_ro1, b_ro1, ffh, NROWS, Hh, Hh, true, false);
    k_output<<<Nn, Hh>>>(W_ro2, b_ro2, out);
}

// round 15
// speedup vs baseline: 1.3174x; 1.0825x over previous
#include <cuda_runtime.h>
#include <cuda_bf16.h>
#include <math.h>
#include <stdint.h>

// Problem dims (fixed by the dataset)
constexpr int Nn  = 4000;
constexpr int Ee  = 50000;
constexpr int NGg = 12;
constexpr int Hh  = 128;
constexpr int BDd = 128;
constexpr int Ll  = 2;
constexpr int Bb  = 100;

constexpr int EROWS = Ee * NGg;     // 600000
constexpr int NROWS = Nn * NGg;     // 48000

// ---------------- scratch (device globals; no cudaMalloc allowed) -------------
__device__ __align__(16) float g_grid_node[Nn * NGg * 3];
__device__ __align__(16) float g_kern0[(size_t)EROWS * Hh];
__device__ __align__(16) float g_kern1[(size_t)EROWS * Hh];
__device__ __align__(16) float g_x  [NROWS * Hh];
__device__ __align__(16) float g_x2 [NROWS * Hh];
__device__ __align__(16) float g_ro [NROWS * Hh];
__device__ __align__(16) float g_fipoly[NGg * NGg * 2];
__device__ __align__(16) float g_fh1   [NGg * NGg * Hh];
__device__ __align__(16) float g_fbasis[NGg * NGg * BDd];
__device__ __align__(16) float g_fk    [NGg * NGg * Hh];
__device__ float g_gsum[Bb * 4];   // per-graph: sum_x, sum_y, sum_z, count
// CSR by destination
__device__ int g_deg[Nn];
__device__ int g_off[Nn + 1];
__device__ int g_cur[Nn];
__device__ int g_csr[Ee];

__device__ __forceinline__ float gelu_f(float x) {
    return 0.5f * x * (1.0f + erff(x * 0.70710678118654752f));
}

// ---------------- tiny kernels -------------------------------------------------
__global__ void k_init() {
    int i = blockIdx.x * blockDim.x + threadIdx.x;
    if (i < Nn) { g_deg[i] = 0; g_cur[i] = 0; }
    if (i < Bb * 4) g_gsum[i] = 0.f;
}

__global__ void k_gsum(const float* __restrict__ pos, const int* __restrict__ batch) {
    int n = blockIdx.x * blockDim.x + threadIdx.x;
    if (n >= Nn) return;
    int b = batch[n];
    atomicAdd(&g_gsum[b * 4 + 0], pos[n * 3 + 0]);
    atomicAdd(&g_gsum[b * 4 + 1], pos[n * 3 + 1]);
    atomicAdd(&g_gsum[b * 4 + 2], pos[n * 3 + 2]);
    atomicAdd(&g_gsum[b * 4 + 3], 1.f);
}

__global__ void k_grid_node(const int* __restrict__ batch,
                            const float* __restrict__ grid0,
                            const float* __restrict__ R) {
    int idx = blockIdx.x * blockDim.x + threadIdx.x;  // n*NG + k
    if (idx >= Nn * NGg) return;
    int n = idx / NGg, k = idx % NGg;
    const float* Rb = R + batch[n] * 9;
    float gx = grid0[k * 3 + 0], gy = grid0[k * 3 + 1], gz = grid0[k * 3 + 2];
    float* o = g_grid_node + idx * 3;
    o[0] = Rb[0] * gx + Rb[1] * gy + Rb[2] * gz;
    o[1] = Rb[3] * gx + Rb[4] * gy + Rb[5] * gz;
    o[2] = Rb[6] * gx + Rb[7] * gy + Rb[8] * gz;
}

__global__ void k_fipoly(const float* __restrict__ grid0) {
    int idx = threadIdx.x;
    if (idx >= NGg * NGg) return;
    int p = idx / NGg, o = idx % NGg;
    float fi = grid0[p * 3 + 0] * grid0[o * 3 + 0] +
               grid0[p * 3 + 1] * grid0[o * 3 + 1] +
               grid0[p * 3 + 2] * grid0[o * 3 + 2];
    g_fipoly[idx * 2 + 0] = fi;
    g_fipoly[idx * 2 + 1] = fi * fi;
}

// naive GEMM for tiny fiber matrices (M=144) — fp32, negligible time
__global__ void k_small_gemm(const float* __restrict__ A, const float* __restrict__ W,
                             const float* __restrict__ bias, float* __restrict__ C,
                             int M, int N, int K, int act) {
    int idx = blockIdx.x * blockDim.x + threadIdx.x;
    if (idx >= M * N) return;
    int r = idx / N, c = idx % N;
    float acc = bias ? bias[c] : 0.f;
    for (int k = 0; k < K; k++) acc = fmaf(A[r * K + k], W[k * N + c], acc);
    C[idx] = act ? gelu_f(acc) : acc;
}

__global__ void k_embed(const float* __restrict__ pos, const float* __restrict__ vel,
                        const float* __restrict__ charges, const int* __restrict__ batch,
                        const float* __restrict__ We) {
    int nk = blockIdx.x;           // n*NG + k
    int h = threadIdx.x;           // 0..127
    int n = nk / NGg;
    const float* g = g_grid_node + nk * 3;
    float vx = vel[n * 3 + 0], vy = vel[n * 3 + 1], vz = vel[n * 3 + 2];
    int b = batch[n];
    float cnt = fmaxf(g_gsum[b * 4 + 3], 1.f);
    float rpx = pos[n * 3 + 0] - g_gsum[b * 4 + 0] / cnt;
    float rpy = pos[n * 3 + 1] - g_gsum[b * 4 + 1] / cnt;
    float rpz = pos[n * 3 + 2] - g_gsum[b * 4 + 2] / cnt;
    float f0 = vx * g[0] + vy * g[1] + vz * g[2];
    float f1 = rpx * g[0] + rpy * g[1] + rpz * g[2];
    float f2 = charges[n];
    float f3 = sqrtf(vx * vx + vy * vy + vz * vz);
    g_x[(size_t)nk * Hh + h] =
        f0 * We[h] + f1 * We[Hh + h] + f2 * We[2 * Hh + h] + f3 * We[3 * Hh + h];
}

// ---------------- CSR build (by destination) ------------------------------------
__global__ void k_count(const int* __restrict__ eidx) {
    int e = blockIdx.x * blockDim.x + threadIdx.x;
    if (e >= Ee) return;
    atomicAdd(&g_deg[eidx[Ee + e]], 1);
}

__global__ void k_scan() {
    __shared__ int sh[1024];
    int tid = threadIdx.x;
    int base = tid * 4;
    int v[4];
    int s0 = 0;
#pragma unroll
    for (int i = 0; i < 4; i++) {
        int idx = base + i;
        v[i] = (idx < Nn) ? g_deg[idx] : 0;
        s0 += v[i];
    }
    sh[tid] = s0;
    __syncthreads();
    for (int off = 1; off < 1024; off <<= 1) {
        int t = (tid >= off) ? sh[tid - off] : 0;
        __syncthreads();
        sh[tid] += t;
        __syncthreads();
    }
    int ex = sh[tid] - s0;
#pragma unroll
    for (int i = 0; i < 4; i++) {
        int idx = base + i;
        if (idx < Nn) { g_off[idx] = ex; ex += v[i]; }
    }
    if (tid == 1023) g_off[Nn] = sh[1023];
}

__global__ void k_fill(const int* __restrict__ eidx) {
    int e = blockIdx.x * blockDim.x + threadIdx.x;
    if (e >= Ee) return;
    int d = eidx[Ee + e];
    int pos = g_off[d] + atomicAdd(&g_cur[d], 1);
    g_csr[pos] = e;
}

// ---------------- fused gather + fiber contraction + LayerNorm ------------------
__global__ void __launch_bounds__(128) k_gather_fiber_ln(
    const int* __restrict__ eidx, const float* __restrict__ kern,
    const float* __restrict__ bconv, const float* __restrict__ gamma,
    const float* __restrict__ beta) {
    int n = blockIdx.x;
    int c = threadIdx.x;
    float acc[NGg];
#pragma unroll
    for (int o = 0; o < NGg; o++) acc[o] = 0.f;

    const int beg = g_off[n], end = g_off[n + 1];
    for (int j = beg; j < end; j++) {
        int e = g_csr[j];
        int s = eidx[e];
        const float* kr = &kern[(size_t)e * NGg * Hh + c];
        const float* xr = &g_x[(size_t)s * NGg * Hh + c];
#pragma unroll
        for (int o = 0; o < NGg; o++)
            acc[o] = fmaf(__ldcs(&kr[o * Hh]), xr[o * Hh], acc[o]);
    }

    __shared__ float red[4];
    for (int p = 0; p < NGg; p++) {
        float v = 0.f;
        const float* fkp = &g_fk[(size_t)p * NGg * Hh + c];
#pragma unroll
        for (int o = 0; o < NGg; o++)
            v = fmaf(acc[o], fkp[o * Hh], v);
        v = v * (1.0f / NGg) + bconv[c];

        float s = v;
#pragma unroll
        for (int off = 16; off > 0; off >>= 1) s += __shfl_down_sync(0xffffffffu, s, off);
        if ((c & 31) == 0) red[c >> 5] = s;
        __syncthreads();
        float mean = (red[0] + red[1] + red[2] + red[3]) * (1.f / Hh);
        __syncthreads();
        float dd = v - mean;
        s = dd * dd;
#pragma unroll
        for (int off = 16; off > 0; off >>= 1) s += __shfl_down_sync(0xffffffffu, s, off);
        if ((c & 31) == 0) red[c >> 5] = s;
        __syncthreads();
        float var = (red[0] + red[1] + red[2] + red[3]) * (1.f / Hh);
        g_x2[((size_t)n * NGg + p) * Hh + c] = dd * rsqrtf(var + 1e-5f) * gamma[c] + beta[c];
        __syncthreads();
    }
}

// out[n,d] = (1/NG) sum_k grid_node[n,k,d] * (t[n,k,:]·W_ro2 + b_ro2)
__global__ void k_output(const float* __restrict__ Wro2, const float* __restrict__ bro2,
                         float* __restrict__ out) {
    int n = blockIdx.x;
    int h = threadIdx.x;
    __shared__ float red[4];
    __shared__ float ybc;
    float a0 = 0.f, a1 = 0.f, a2 = 0.f;
    for (int k = 0; k < NGg; k++) {
        float s = g_ro[((size_t)(n * NGg + k)) * Hh + h] * Wro2[h];
#pragma unroll
        for (int off = 16; off > 0; off >>= 1) s += __shfl_down_sync(0xffffffffu, s, off);
        if ((h & 31) == 0) red[h >> 5] = s;
        __syncthreads();
        if (h == 0) ybc = red[0] + red[1] + red[2] + red[3] + bro2[0];
        __syncthreads();
        float y = ybc;
        a0 += g_grid_node[(n * NGg + k) * 3 + 0] * y;
        a1 += g_grid_node[(n * NGg + k) * 3 + 1] * y;
        a2 += g_grid_node[(n * NGg + k) * 3 + 2] * y;
        __syncthreads();
    }
    if (h == 0) {
        out[n * 3 + 0] = a0 * (1.f / NGg);
        out[n * 3 + 1] = a1 * (1.f / NGg);
        out[n * 3 + 2] = a2 * (1.f / NGg);
    }
}

// ---------------- bf16x3 tensor-core GEMM (≈fp32 accuracy) ---------------------
constexpr int BM = 128, BN = 128, BK = 32;
constexpr int ASTRIDE = BK + 8;      // 40 bf16/row -> conflict-free ldmatrix
constexpr int BSTRIDE = BN + 8;      // 136 bf16/row -> conflict-free ldmatrix(.trans)

__device__ __forceinline__ void mma_bf16(float* d, const uint32_t* a, const uint32_t* b) {
    asm volatile(
        "mma.sync.aligned.m16n8k16.row.col.f32.bf16.bf16.f32 "
        "{%0,%1,%2,%3}, {%4,%5,%6,%7}, {%8,%9}, {%0,%1,%2,%3};\n"
        : "+f"(d[0]), "+f"(d[1]), "+f"(d[2]), "+f"(d[3])
        : "r"(a[0]), "r"(a[1]), "r"(a[2]), "r"(a[3]), "r"(b[0]), "r"(b[1]));
}

__device__ __forceinline__ void ldm_x4(uint32_t* r, const __nv_bfloat16* p) {
    uint32_t addr = (uint32_t)__cvta_generic_to_shared(p);
    asm volatile("ldmatrix.sync.aligned.m8n8.x4.shared.b16 {%0,%1,%2,%3}, [%4];"
                 : "=r"(r[0]), "=r"(r[1]), "=r"(r[2]), "=r"(r[3]) : "r"(addr));
}

__device__ __forceinline__ void ldm_x2t(uint32_t* r, const __nv_bfloat16* p) {
    uint32_t addr = (uint32_t)__cvta_generic_to_shared(p);
    asm volatile("ldmatrix.sync.aligned.m8n8.x2.trans.shared.b16 {%0,%1}, [%2];"
                 : "=r"(r[0]), "=r"(r[1]) : "r"(addr));
}

__device__ __forceinline__ void split_bf16(float v, __nv_bfloat16& hi, __nv_bfloat16& lo) {
    hi = __float2bfloat16_rn(v);
    lo = __float2bfloat16_rn(v - __bfloat162float(hi));
}

template <bool GELU, bool ACCUM>
__global__ void __launch_bounds__(256, 2) gemm_bf16x3(
    const float* __restrict__ A, const float* __restrict__ Bw,
    const float* __restrict__ bias, float* __restrict__ C,
    int M, int N, int K) {
    __shared__ __nv_bfloat16 As1[BM][ASTRIDE];
    __shared__ __nv_bfloat16 As2[BM][ASTRIDE];
    __shared__ __nv_bfloat16 Bs1[BK][BSTRIDE];
    __shared__ __nv_bfloat16 Bs2[BK][BSTRIDE];

    const int tid  = threadIdx.x;
    const int lane = tid & 31;
    const int warp = tid >> 5;
    const int wm = warp & 1;
    const int wn = warp >> 1;
    const int br = blockIdx.x * BM;
    const int bc = blockIdx.y * BN;
    const int gid = lane >> 2;
    const int qid = lane & 3;

    float acc[4][4][4];
#pragma unroll
    for (int mt = 0; mt < 4; mt++)
#pragma unroll
        for (int nt = 0; nt < 4; nt++)
#pragma unroll
            for (int j = 0; j < 4; j++) acc[mt][nt][j] = 0.f;

    const int aRow = ((lane >> 3) & 1) * 8 + (lane & 7);
    const int aKof = (lane >> 4) * 8;
    const int bK   = lane & 15;

    const int ktiles = (K + BK - 1) / BK;
    for (int kt = 0; kt < ktiles; kt++) {
        const int k0 = kt * BK;
#pragma unroll
        for (int it = 0; it < 4; it++) {
            int f = it * 256 + tid;
            int row = f >> 3, kq = (f & 7) * 4;
            float4 v = make_float4(0.f, 0.f, 0.f, 0.f);
            int gr = br + row;
            if (gr < M && (k0 + kq) < K)
                v = *reinterpret_cast<const float4*>(&A[(size_t)gr * K + k0 + kq]);
            __nv_bfloat16 h0, h1, h2, h3, l0, l1, l2, l3;
            split_bf16(v.x, h0, l0); split_bf16(v.y, h1, l1);
            split_bf16(v.z, h2, l2); split_bf16(v.w, h3, l3);
            *reinterpret_cast<__nv_bfloat162*>(&As1[row][kq])     = __nv_bfloat162(h0, h1);
            *reinterpret_cast<__nv_bfloat162*>(&As1[row][kq + 2]) = __nv_bfloat162(h2, h3);
            *reinterpret_cast<__nv_bfloat162*>(&As2[row][kq])     = __nv_bfloat162(l0, l1);
            *reinterpret_cast<__nv_bfloat162*>(&As2[row][kq + 2]) = __nv_bfloat162(l2, l3);
        }
#pragma unroll
        for (int it = 0; it < 4; it++) {
            int f = it * 256 + tid;
            int krow = f >> 5, n4 = (f & 31) * 4;
            float4 v = make_float4(0.f, 0.f, 0.f, 0.f);
            if ((k0 + krow) < K)
                v = *reinterpret_cast<const float4*>(&Bw[(size_t)(k0 + krow) * N + bc + n4]);
            __nv_bfloat16 h0, h1, h2, h3, l0, l1, l2, l3;
            split_bf16(v.x, h0, l0); split_bf16(v.y, h1, l1);
            split_bf16(v.z, h2, l2); split_bf16(v.w, h3, l3);
            *reinterpret_cast<__nv_bfloat162*>(&Bs1[krow][n4])     = __nv_bfloat162(h0, h1);
            *reinterpret_cast<__nv_bfloat162*>(&Bs1[krow][n4 + 2]) = __nv_bfloat162(h2, h3);
            *reinterpret_cast<__nv_bfloat162*>(&Bs2[krow][n4])     = __nv_bfloat162(l0, l1);
            *reinterpret_cast<__nv_bfloat162*>(&Bs2[krow][n4 + 2]) = __nv_bfloat162(l2, l3);
        }
        __syncthreads();

#pragma unroll
        for (int ks = 0; ks < 2; ks++) {
            const int kk = ks * 16;
            uint32_t bb[4][2], bs[4][2];
#pragma unroll
            for (int nt = 0; nt < 4; nt++) {
                const int n0 = wn * 32 + nt * 8;
                ldm_x2t(bb[nt], &Bs1[kk + bK][n0]);
                ldm_x2t(bs[nt], &Bs2[kk + bK][n0]);
            }
#pragma unroll
            for (int mt = 0; mt < 4; mt++) {
                const int r0 = wm * 64 + mt * 16 + aRow;
                uint32_t ah[4], al[4];
                ldm_x4(ah, &As1[r0][kk + aKof]);
                ldm_x4(al, &As2[r0][kk + aKof]);
#pragma unroll
                for (int nt = 0; nt < 4; nt++) {
                    mma_bf16(acc[mt][nt], al, bb[nt]);
                    mma_bf16(acc[mt][nt], ah, bs[nt]);
                    mma_bf16(acc[mt][nt], ah, bb[nt]);
                }
            }
        }
        __syncthreads();
    }

#pragma unroll
    for (int nt = 0; nt < 4; nt++) {
        const int c = bc + wn * 32 + nt * 8 + qid * 2;
        float b0 = 0.f, b1 = 0.f;
        if (bias) { b0 = bias[c]; b1 = bias[c + 1]; }
#pragma unroll
        for (int mt = 0; mt < 4; mt++) {
            int r0 = br + wm * 64 + mt * 16 + gid;
#pragma unroll
            for (int half = 0; half < 2; half++) {
                int r = r0 + half * 8;
                if (r >= M) continue;
                float v0 = acc[mt][nt][half * 2 + 0] + b0;
                float v1 = acc[mt][nt][half * 2 + 1] + b1;
                if (GELU) { v0 = gelu_f(v0); v1 = gelu_f(v1); }
                float2* p = reinterpret_cast<float2*>(&C[(size_t)r * N + c]);
                if (ACCUM) {
                    float2 o = *p;
                    o.x += v0; o.y += v1;
                    *p = o;
                } else {
                    *p = make_float2(v0, v1);
                }
            }
        }
    }
}

// ---------------- shared helpers for smem-A fused kernels -----------------------
constexpr int A2S = 136;
constexpr int BTILE = BK * BSTRIDE;

__device__ __forceinline__ void split_store_B(__nv_bfloat16* B1, __nv_bfloat16* B2,
                                              int tid, const float4* v) {
#pragma unroll
    for (int it = 0; it < 4; it++) {
        int f = it * 256 + tid;
        int krow = f >> 5, n4 = (f & 31) * 4;
        __nv_bfloat16 h0, h1, h2, h3, l0, l1, l2, l3;
        split_bf16(v[it].x, h0, l0); split_bf16(v[it].y, h1, l1);
        split_bf16(v[it].z, h2, l2); split_bf16(v[it].w, h3, l3);
        *reinterpret_cast<__nv_bfloat162*>(&B1[krow * BSTRIDE + n4])     = __nv_bfloat162(h0, h1);
        *reinterpret_cast<__nv_bfloat162*>(&B1[krow * BSTRIDE + n4 + 2]) = __nv_bfloat162(h2, h3);
        *reinterpret_cast<__nv_bfloat162*>(&B2[krow * BSTRIDE + n4])     = __nv_bfloat162(l0, l1);
        *reinterpret_cast<__nv_bfloat162*>(&B2[krow * BSTRIDE + n4 + 2]) = __nv_bfloat162(l2, l3);
    }
}

__device__ __forceinline__ void load_B_tile(const float* __restrict__ Bw, int ldb,
                                            int tid, int k0, float4* v) {
#pragma unroll
    for (int it = 0; it < 4; it++) {
        int f = it * 256 + tid;
        int krow = f >> 5, n4 = (f & 31) * 4;
        v[it] = *reinterpret_cast<const float4*>(&Bw[(size_t)(k0 + krow) * ldb + n4]);
    }
}

// ---------------- fully fused edge chain: features -> basis -> kern0,kern1 ------
constexpr size_t FK_OFF_A1 = 0;
constexpr size_t FK_OFF_A2 = FK_OFF_A1 + (size_t)BM * A2S * 2;      // 34816
constexpr size_t FK_OFF_B1 = FK_OFF_A2 + (size_t)BM * A2S * 2;      // 69632 (2 buffers)
constexpr size_t FK_OFF_B2 = FK_OFF_B1 + (size_t)2 * BTILE * 2;     // 87040 (2 buffers)
constexpr size_t FK_SMEM   = FK_OFF_B2 + (size_t)2 * BTILE * 2;     // 104448

struct KBCtx {
    const __nv_bfloat16 *As1, *As2;
    __nv_bfloat16 *Bs1, *Bs2;        // base of 2-buffer arrays
    int tid, wm, wn, aRow, aKof, bK;
};

// one full K=128 mainloop against row-major weights Bw [128][128], B double-buffered
__device__ __forceinline__ void kb_mainloop(const KBCtx& cx,
                                            const float* __restrict__ Bw,
                                            float acc[4][4][4]) {
#pragma unroll
    for (int mt = 0; mt < 4; mt++)
#pragma unroll
        for (int nt = 0; nt < 4; nt++)
#pragma unroll
            for (int j = 0; j < 4; j++) acc[mt][nt][j] = 0.f;

    float4 v[4];
    load_B_tile(Bw, Hh, cx.tid, 0, v);
    split_store_B(cx.Bs1, cx.Bs2, cx.tid, v);
    __syncthreads();

#pragma unroll
    for (int kt = 0; kt < 4; kt++) {
        const int k0 = kt * BK;
        if (kt < 3) load_B_tile(Bw, Hh, cx.tid, k0 + BK, v);
        const __nv_bfloat16* B1 = cx.Bs1 + (kt & 1) * BTILE;
        const __nv_bfloat16* B2 = cx.Bs2 + (kt & 1) * BTILE;
#pragma unroll
        for (int ks = 0; ks < 2; ks++) {
            const int kk = ks * 16;
            uint32_t bb[4][2], bs[4][2];
#pragma unroll
            for (int nt = 0; nt < 4; nt++) {
                const int n0 = cx.wn * 32 + nt * 8;
                ldm_x2t(bb[nt], &B1[(kk + cx.bK) * BSTRIDE + n0]);
                ldm_x2t(bs[nt], &B2[(kk + cx.bK) * BSTRIDE + n0]);
            }
#pragma unroll
            for (int mt = 0; mt < 4; mt++) {
                const int r0 = cx.wm * 64 + mt * 16 + cx.aRow;
                uint32_t ah[4], al[4];
                ldm_x4(ah, &cx.As1[r0 * A2S + k0 + kk + cx.aKof]);
                ldm_x4(al, &cx.As2[r0 * A2S + k0 + kk + cx.aKof]);
#pragma unroll
                for (int nt = 0; nt < 4; nt++) {
                    mma_bf16(acc[mt][nt], al, bb[nt]);
                    mma_bf16(acc[mt][nt], ah, bs[nt]);
                    mma_bf16(acc[mt][nt], ah, bb[nt]);
                }
            }
        }
        if (kt < 3) split_store_B(cx.Bs1 + ((kt + 1) & 1) * BTILE,
                                  cx.Bs2 + ((kt + 1) & 1) * BTILE, cx.tid, v);
        __syncthreads();
    }
}

__global__ void __launch_bounds__(256, 2) k_basis_kern(
    const float* __restrict__ pos, const float* __restrict__ charges,
    const int* __restrict__ eidx,
    const float* __restrict__ W1, const float* __restrict__ b1,
    const float* __restrict__ W2, const float* __restrict__ b2,
    const float* __restrict__ Wc,     // [2][128][128]
    float* __restrict__ kern0, float* __restrict__ kern1, int M) {
    extern __shared__ char smraw[];
    __nv_bfloat16* As1 = reinterpret_cast<__nv_bfloat16*>(smraw + FK_OFF_A1); // [128][136]
    __nv_bfloat16* As2 = reinterpret_cast<__nv_bfloat16*>(smraw + FK_OFF_A2);
    __nv_bfloat16* Bs1 = reinterpret_cast<__nv_bfloat16*>(smraw + FK_OFF_B1); // 2x[32][136]
    __nv_bfloat16* Bs2 = reinterpret_cast<__nv_bfloat16*>(smraw + FK_OFF_B2);
    float* EIP = reinterpret_cast<float*>(smraw + FK_OFF_B1);
    float* W1s = EIP + BM * 12;
    float* b1s = W1s + 12 * Hh;

    const int tid  = threadIdx.x;
    const int lane = tid & 31;
    const int warp = tid >> 5;
    const int wm = warp & 1;
    const int wn = warp >> 1;
    const int br = blockIdx.x * BM;
    const int gid = lane >> 2;
    const int qid = lane & 3;

    KBCtx cx;
    cx.As1 = As1; cx.As2 = As2; cx.Bs1 = Bs1; cx.Bs2 = Bs2;
    cx.tid = tid; cx.wm = wm; cx.wn = wn;
    cx.aRow = ((lane >> 3) & 1) * 8 + (lane & 7);
    cx.aKof = (lane >> 4) * 8;
    cx.bK   = lane & 15;

    // ---- phase 0: compute edge-invariant features in-kernel (one row/thread) ----
    for (int f = tid; f < 12 * Hh; f += 256) W1s[f] = W1[f];
    if (tid < Hh) b1s[tid] = b1[tid];
    if (tid < BM) {
        int row = br + tid;
        float f0 = 0.f, f1 = 0.f, f2 = 0.f;
        if (row < M) {
            int e = row / NGg;
            int k = row - e * NGg;
            int s = eidx[e], d = eidx[Ee + e];
            float rx = pos[s * 3 + 0] - pos[d * 3 + 0];
            float ry = pos[s * 3 + 1] - pos[d * 3 + 1];
            float rz = pos[s * 3 + 2] - pos[d * 3 + 2];
            const float* g = g_grid_node + (s * NGg + k) * 3;
            float inv1 = rx * g[0] + ry * g[1] + rz * g[2];
            float vx = rx - inv1 * g[0], vy = ry - inv1 * g[1], vz = rz - inv1 * g[2];
            float inv2 = sqrtf(vx * vx + vy * vy + vz * vz);
            f0 = inv1; f1 = inv2; f2 = charges[s] * charges[d];
        }
        float* o = &EIP[tid * 12];
        o[0] = f0;  o[1] = f1;  o[2] = f2;
        o[3] = f0 * f0; o[4]  = f0 * f1; o[5]  = f0 * f2;
        o[6] = f1 * f0; o[7]  = f1 * f1; o[8]  = f1 * f2;
        o[9] = f2 * f0; o[10] = f2 * f1; o[11] = f2 * f2;
    }
    __syncthreads();

    // ---- phase 1: h1 = gelu(eip@W1 + b1) -> As (split bf16, persistent) ----
    {
        const int r  = tid >> 1;
        const int cb = (tid & 1) * 64;
        float e[12];
#pragma unroll
        for (int k = 0; k < 12; k++) e[k] = EIP[r * 12 + k];
#pragma unroll
        for (int c2 = 0; c2 < 64; c2 += 2) {
            int c = cb + c2;
            float a0 = 0.f, a1 = 0.f;
#pragma unroll
            for (int k = 0; k < 12; k++) {
                a0 = fmaf(e[k], W1s[k * Hh + c], a0);
                a1 = fmaf(e[k], W1s[k * Hh + c + 1], a1);
            }
            a0 = gelu_f(a0 + b1s[c]); a1 = gelu_f(a1 + b1s[c + 1]);
            __nv_bfloat16 h0, l0, h1, l1;
            split_bf16(a0, h0, l0);
            split_bf16(a1, h1, l1);
            *reinterpret_cast<__nv_bfloat162*>(&As1[r * A2S + c]) = __nv_bfloat162(h0, h1);
            *reinterpret_cast<__nv_bfloat162*>(&As2[r * A2S + c]) = __nv_bfloat162(l0, l1);
        }
    }
    __syncthreads();

    float acc[4][4][4];

    // ---- phase 2: basis = gelu(h1 @ W2 + b2) -> back into As (smem only) ----
    kb_mainloop(cx, W2, acc);
    {
#pragma unroll
        for (int nt = 0; nt < 4; nt++) {
            const int c = wn * 32 + nt * 8 + qid * 2;
            float bb0 = b2[c], bb1 = b2[c + 1];
#pragma unroll
            for (int mt = 0; mt < 4; mt++) {
                int rl = wm * 64 + mt * 16 + gid;
#pragma unroll
                for (int half = 0; half < 2; half++) {
                    int r = rl + half * 8;
                    float v0 = gelu_f(acc[mt][nt][half * 2 + 0] + bb0);
                    float v1 = gelu_f(acc[mt][nt][half * 2 + 1] + bb1);
                    __nv_bfloat16 h0, l0, h1, l1;
                    split_bf16(v0, h0, l0);
                    split_bf16(v1, h1, l1);
                    *reinterpret_cast<__nv_bfloat162*>(&As1[r * A2S + c]) = __nv_bfloat162(h0, h1);
                    *reinterpret_cast<__nv_bfloat162*>(&As2[r * A2S + c]) = __nv_bfloat162(l0, l1);
                }
            }
        }
    }
    __syncthreads();

    // ---- phase 3: kern_l = basis @ W_conv[l], l = 0,1 (streaming stores) ----
#pragma unroll
    for (int l = 0; l < 2; l++) {
        kb_mainloop(cx, Wc + (size_t)l * BDd * Hh, acc);
        float* kern = l == 0 ? kern0 : kern1;
#pragma unroll
        for (int nt = 0; nt < 4; nt++) {
            const int c = wn * 32 + nt * 8 + qid * 2;
#pragma unroll
            for (int mt = 0; mt < 4; mt++) {
                int r0 = br + wm * 64 + mt * 16 + gid;
#pragma unroll
                for (int half = 0; half < 2; half++) {
                    int r = r0 + half * 8;
                    if (r >= M) continue;
                    __stcs(reinterpret_cast<float2*>(&kern[(size_t)r * Hh + c]),
                           make_float2(acc[mt][nt][half * 2 + 0], acc[mt][nt][half * 2 + 1]));
                }
            }
        }
    }
}

// ---------------- fused FF block: x += W_ff2 @ gelu(W_ff1 @ x2)  -----------------
// BM=64 rows/block; hidden (512) processed in 4 chunks of 128; h never leaves smem.
constexpr int FBM = 64;
constexpr size_t FF_OFF_AX1 = 0;
constexpr size_t FF_OFF_AX2 = FF_OFF_AX1 + (size_t)FBM * A2S * 2;   // 17408
constexpr size_t FF_OFF_AH1 = FF_OFF_AX2 + (size_t)FBM * A2S * 2;   // 34816
constexpr size_t FF_OFF_AH2 = FF_OFF_AH1 + (size_t)FBM * A2S * 2;   // 52224
constexpr size_t FF_OFF_B1  = FF_OFF_AH2 + (size_t)FBM * A2S * 2;   // 69632 (2 bufs)
constexpr size_t FF_OFF_B2  = FF_OFF_B1 + (size_t)2 * BTILE * 2;    // 87040 (2 bufs)
constexpr size_t FF_SMEM    = FF_OFF_B2 + (size_t)2 * BTILE * 2;    // 104448

// K=128 mainloop, 64-row A in smem, warp tile 32x32. CLEAR selects init vs accum.
template <bool CLEAR>
__device__ __forceinline__ void ff_mainloop(
    const __nv_bfloat16* __restrict__ A1, const __nv_bfloat16* __restrict__ A2,
    __nv_bfloat16* Bs1, __nv_bfloat16* Bs2,
    const float* __restrict__ Bw, int ldb,
    int tid, int wm, int wn, int aRow, int aKof, int bKl,
    float acc[2][4][4]) {
    if (CLEAR) {
#pragma unroll
        for (int mt = 0; mt < 2; mt++)
#pragma unroll
            for (int nt = 0; nt < 4; nt++)
#pragma unroll
                for (int j = 0; j < 4; j++) acc[mt][nt][j] = 0.f;
    }
    float4 v[4];
    load_B_tile(Bw, ldb, tid, 0, v);
    split_store_B(Bs1, Bs2, tid, v);
    __syncthreads();

#pragma unroll
    for (int kt = 0; kt < 4; kt++) {
        const int k0 = kt * BK;
        if (kt < 3) load_B_tile(Bw, ldb, tid, k0 + BK, v);
        const __nv_bfloat16* B1 = Bs1 + (kt & 1) * BTILE;
        const __nv_bfloat16* B2 = Bs2 + (kt & 1) * BTILE;
#pragma unroll
        for (int ks = 0; ks < 2; ks++) {
            const int kk = ks * 16;
            uint32_t bb[4][2], bs[4][2];
#pragma unroll
            for (int nt = 0; nt < 4; nt++) {
                const int n0 = wn * 32 + nt * 8;
                ldm_x2t(bb[nt], &B1[(kk + bKl) * BSTRIDE + n0]);
                ldm_x2t(bs[nt], &B2[(kk + bKl) * BSTRIDE + n0]);
            }
#pragma unroll
            for (int mt = 0; mt < 2; mt++) {
                const int r0 = wm * 32 + mt * 16 + aRow;
                uint32_t ah[4], al[4];
                ldm_x4(ah, &A1[r0 * A2S + k0 + kk + aKof]);
                ldm_x4(al, &A2[r0 * A2S + k0 + kk + aKof]);
#pragma unroll
                for (int nt = 0; nt < 4; nt++) {
                    mma_bf16(acc[mt][nt], al, bb[nt]);
                    mma_bf16(acc[mt][nt], ah, bs[nt]);
                    mma_bf16(acc[mt][nt], ah, bb[nt]);
                }
            }
        }
        if (kt < 3) split_store_B(Bs1 + ((kt + 1) & 1) * BTILE,
                                  Bs2 + ((kt + 1) & 1) * BTILE, tid, v);
        __syncthreads();
    }
}

__global__ void __launch_bounds__(256, 2) k_ff_fused(
    const float* __restrict__ x2, const float* __restrict__ Wff1,
    const float* __restrict__ bff1, const float* __restrict__ Wff2,
    const float* __restrict__ bff2, float* __restrict__ x, int M) {
    extern __shared__ char smraw[];
    __nv_bfloat16* Ax1 = reinterpret_cast<__nv_bfloat16*>(smraw + FF_OFF_AX1);
    __nv_bfloat16* Ax2 = reinterpret_cast<__nv_bfloat16*>(smraw + FF_OFF_AX2);
    __nv_bfloat16* Ah1 = reinterpret_cast<__nv_bfloat16*>(smraw + FF_OFF_AH1);
    __nv_bfloat16* Ah2 = reinterpret_cast<__nv_bfloat16*>(smraw + FF_OFF_AH2);
    __nv_bfloat16* Bs1 = reinterpret_cast<__nv_bfloat16*>(smraw + FF_OFF_B1);
    __nv_bfloat16* Bs2 = reinterpret_cast<__nv_bfloat16*>(smraw + FF_OFF_B2);

    const int tid  = threadIdx.x;
    const int lane = tid & 31;
    const int warp = tid >> 5;
    const int wm = warp & 1;             // 2 warps along M (32 rows each)
    const int wn = warp >> 1;            // 4 warps along N (32 cols each)
    const int br = blockIdx.x * FBM;
    const int gid = lane >> 2;
    const int qid = lane & 3;
    const int aRow = ((lane >> 3) & 1) * 8 + (lane & 7);
    const int aKof = (lane >> 4) * 8;
    const int bKl  = lane & 15;

    // stage x2 tile (64 x 128 fp32) -> split bf16 Ax
#pragma unroll
    for (int it = 0; it < 8; it++) {
        int f = it * 256 + tid;
        int row = f >> 5, kq = (f & 31) * 4;
        float4 v = make_float4(0.f, 0.f, 0.f, 0.f);
        int gr = br + row;
        if (gr < M)
            v = *reinterpret_cast<const float4*>(&x2[(size_t)gr * Hh + kq]);
        __nv_bfloat16 h0, h1, h2, h3, l0, l1, l2, l3;
        split_bf16(v.x, h0, l0); split_bf16(v.y, h1, l1);
        split_bf16(v.z, h2, l2); split_bf16(v.w, h3, l3);
        *reinterpret_cast<__nv_bfloat162*>(&Ax1[row * A2S + kq])     = __nv_bfloat162(h0, h1);
        *reinterpret_cast<__nv_bfloat162*>(&Ax1[row * A2S + kq + 2]) = __nv_bfloat162(h2, h3);
        *reinterpret_cast<__nv_bfloat162*>(&Ax2[row * A2S + kq])     = __nv_bfloat162(l0, l1);
        *reinterpret_cast<__nv_bfloat162*>(&Ax2[row * A2S + kq + 2]) = __nv_bfloat162(l2, l3);
    }
    __syncthreads();

    float acc1[2][4][4];
    float acc2[2][4][4];
#pragma unroll
    for (int mt = 0; mt < 2; mt++)
#pragma unroll
        for (int nt = 0; nt < 4; nt++)
#pragma unroll
            for (int j = 0; j < 4; j++) acc2[mt][nt][j] = 0.f;

#pragma unroll
    for (int chunk = 0; chunk < 4; chunk++) {
        // h_chunk = gelu(x2 @ W_ff1[:, chunk*128 : +128] + b_ff1[chunk])
        ff_mainloop<true>(Ax1, Ax2, Bs1, Bs2, Wff1 + chunk * Hh, 4 * Hh,
                          tid, wm, wn, aRow, aKof, bKl, acc1);
#pragma unroll
        for (int nt = 0; nt < 4; nt++) {
            const int c = wn * 32 + nt * 8 + qid * 2;
            float bb0 = bff1[chunk * Hh + c], bb1 = bff1[chunk * Hh + c + 1];
#pragma unroll
            for (int mt = 0; mt < 2; mt++) {
                int rl = wm * 32 + mt * 16 + gid;
#pragma unroll
                for (int half = 0; half < 2; half++) {
                    int r = rl + half * 8;
                    float v0 = gelu_f(acc1[mt][nt][half * 2 + 0] + bb0);
                    float v1 = gelu_f(acc1[mt][nt][half * 2 + 1] + bb1);
                    __nv_bfloat16 h0, l0, h1, l1;
                    split_bf16(v0, h0, l0);
                    split_bf16(v1, h1, l1);
                    *reinterpret_cast<__nv_bfloat162*>(&Ah1[r * A2S + c]) = __nv_bfloat162(h0, h1);
                    *reinterpret_cast<__nv_bfloat162*>(&Ah2[r * A2S + c]) = __nv_bfloat162(l0, l1);
                }
            }
        }
        // acc2 += h_chunk @ W_ff2[chunk*128 : +128, :]
        // (Ah writes above are ordered before ldmatrix by the sync inside ff_mainloop)
        ff_mainloop<false>(Ah1, Ah2, Bs1, Bs2, Wff2 + (size_t)chunk * Hh * Hh, Hh,
                           tid, wm, wn, aRow, aKof, bKl, acc2);
    }

    // epilogue: x += acc2 + b_ff2
#pragma unroll
    for (int nt = 0; nt < 4; nt++) {
        const int c = wn * 32 + nt * 8 + qid * 2;
        float bb0 = bff2[c], bb1 = bff2[c + 1];
#pragma unroll
        for (int mt = 0; mt < 2; mt++) {
            int r0 = br + wm * 32 + mt * 16 + gid;
#pragma unroll
            for (int half = 0; half < 2; half++) {
                int r = r0 + half * 8;
                if (r >= M) continue;
                float2* p = reinterpret_cast<float2*>(&x[(size_t)r * Hh + c]);
                float2 o = *p;
                o.x += acc2[mt][nt][half * 2 + 0] + bb0;
                o.y += acc2[mt][nt][half * 2 + 1] + bb1;
                *p = o;
            }
        }
    }
}

// ---------------- host launch ----------------------------------------------------
static void launch_gemm(const float* A, const float* W, const float* bias, float* C,
                        int M, int N, int K, bool gelu_act, bool accum) {
    dim3 grid((M + BM - 1) / BM, N / BN);
    if (gelu_act)   gemm_bf16x3<true, false><<<grid, 256>>>(A, W, bias, C, M, N, K);
    else if (accum) gemm_bf16x3<false, true><<<grid, 256>>>(A, W, bias, C, M, N, K);
    else            gemm_bf16x3<false, false><<<grid, 256>>>(A, W, bias, C, M, N, K);
}

extern "C" void kernel_launch(void* const* d_in, const int* in_sizes, int n_in,
                              void* d_out, int out_size) {
    const float* pos      = (const float*)d_in[0];
    const float* vel      = (const float*)d_in[1];
    const float* charges  = (const float*)d_in[2];
    const int*   batch    = (const int*)d_in[3];
    const int*   eidx     = (const int*)d_in[4];
    const float* grid0    = (const float*)d_in[5];
    const float* R        = (const float*)d_in[6];
    const float* W_basis1 = (const float*)d_in[7];
    const float* b_basis1 = (const float*)d_in[8];
    const float* W_basis2 = (const float*)d_in[9];
    const float* b_basis2 = (const float*)d_in[10];
    const float* W_fbasis1 = (const float*)d_in[11];
    const float* b_fbasis1 = (const float*)d_in[12];
    const float* W_fbasis2 = (const float*)d_in[13];
    const float* b_fbasis2 = (const float*)d_in[14];
    const float* W_embed  = (const float*)d_in[15];
    const float* W_conv   = (const float*)d_in[16];
    const float* W_fiber  = (const float*)d_in[17];
    const float* b_conv   = (const float*)d_in[18];
    const float* ln_gamma = (const float*)d_in[19];
    const float* ln_beta  = (const float*)d_in[20];
    const float* W_ff1    = (const float*)d_in[21];
    const float* b_ff1    = (const float*)d_in[22];
    const float* W_ff2    = (const float*)d_in[23];
    const float* b_ff2    = (const float*)d_in[24];
    const float* W_ro1    = (const float*)d_in[25];
    const float* b_ro1    = (const float*)d_in[26];
    const float* W_ro2    = (const float*)d_in[27];
    const float* b_ro2    = (const float*)d_in[28];
    float* out = (float*)d_out;

    float *kern0, *kern1, *x, *x2, *ro, *fip, *fh1, *fbasis, *fk;
    cudaGetSymbolAddress((void**)&kern0, g_kern0);
    cudaGetSymbolAddress((void**)&kern1, g_kern1);
    cudaGetSymbolAddress((void**)&x,     g_x);
    cudaGetSymbolAddress((void**)&x2,    g_x2);
    cudaGetSymbolAddress((void**)&ro,    g_ro);
    cudaGetSymbolAddress((void**)&fip,   g_fipoly);
    cudaGetSymbolAddress((void**)&fh1,   g_fh1);
    cudaGetSymbolAddress((void**)&fbasis,g_fbasis);
    cudaGetSymbolAddress((void**)&fk,    g_fk);

    static bool attr_done = false;
    if (!attr_done) {
        cudaFuncSetAttribute(k_basis_kern, cudaFuncAttributeMaxDynamicSharedMemorySize,
                             (int)FK_SMEM);
        cudaFuncSetAttribute(k_ff_fused, cudaFuncAttributeMaxDynamicSharedMemorySize,
                             (int)FF_SMEM);
        attr_done = true;
    }

    // init + graph statistics + rotated grids
    k_init<<<(Nn + 255) / 256, 256>>>();
    k_gsum<<<(Nn + 255) / 256, 256>>>(pos, batch);
    k_grid_node<<<(Nn * NGg + 255) / 256, 256>>>(batch, grid0, R);

    // CSR by destination (built once, reused by both layers)
    k_count<<<(Ee + 255) / 256, 256>>>(eidx);
    k_scan<<<1, 1024>>>();
    k_fill<<<(Ee + 255) / 256, 256>>>(eidx);

    // edge chain fully fused: features -> h1 -> basis (all smem) -> kern0, kern1
    k_basis_kern<<<(EROWS + BM - 1) / BM, 256, FK_SMEM>>>(
        pos, charges, eidx, W_basis1, b_basis1, W_basis2, b_basis2, W_conv,
        kern0, kern1, EROWS);

    // fiber basis MLP: 144 rows
    k_fipoly<<<1, 256>>>(grid0);
    k_small_gemm<<<(NGg * NGg * Hh + 255) / 256, 256>>>(fip, W_fbasis1, b_fbasis1, fh1,
                                                        NGg * NGg, Hh, 2, 1);
    k_small_gemm<<<(NGg * NGg * BDd + 255) / 256, 256>>>(fh1, W_fbasis2, b_fbasis2, fbasis,
                                                         NGg * NGg, BDd, Hh, 1);

    // node embedding
    k_embed<<<NROWS, Hh>>>(pos, vel, charges, batch, W_embed);

    for (int l = 0; l < Ll; l++) {
        // fk = fiber_basis @ W_fiber[l]
        k_small_gemm<<<(NGg * NGg * Hh + 255) / 256, 256>>>(
            fbasis, W_fiber + (size_t)l * BDd * Hh, nullptr, fk, NGg * NGg, Hh, BDd, 0);
        // fused: x1 = gather-sum(kern_l * x[src] -> dst); x2 = LN(fiber(x1))
        k_gather_fiber_ln<<<Nn, Hh>>>(eidx, l == 0 ? kern0 : kern1, b_conv + l * Hh,
                                      ln_gamma + l * Hh, ln_beta + l * Hh);
        // fused FF: x += W_ff2 @ gelu(W_ff1 @ x2)   (hidden never leaves smem)
        k_ff_fused<<<(NROWS + FBM - 1) / FBM, 256, FF_SMEM>>>(
            x2, W_ff1 + (size_t)l * Hh * 4 * Hh, b_ff1 + l * 4 * Hh,
            W_ff2 + (size_t)l * 4 * Hh * Hh, b_ff2 + l * Hh, x, NROWS);
    }

    // readout
    launch_gemm(x, W_ro1, b_ro1, ro, NROWS, Hh, Hh, true, false);
    k_output<<<Nn, Hh>>>(W_ro2, b_ro2, out);
}

// round 16
// speedup vs baseline: 1.3311x; 1.0104x over previous
#include <cuda_runtime.h>
#include <cuda_bf16.h>
#include <cuda_fp16.h>
#include <math.h>
#include <stdint.h>

// Problem dims (fixed by the dataset)
constexpr int Nn  = 4000;
constexpr int Ee  = 50000;
constexpr int NGg = 12;
constexpr int Hh  = 128;
constexpr int BDd = 128;
constexpr int Ll  = 2;
constexpr int Bb  = 100;

constexpr int EROWS = Ee * NGg;     // 600000
constexpr int NROWS = Nn * NGg;     // 48000

// ---------------- scratch (device globals; no cudaMalloc allowed) -------------
__device__ __align__(16) float g_grid_node[Nn * NGg * 3];
__device__ __align__(16) __half g_kern0[(size_t)EROWS * Hh];
__device__ __align__(16) __half g_kern1[(size_t)EROWS * Hh];
__device__ __align__(16) float g_x  [NROWS * Hh];
__device__ __align__(16) float g_x2 [NROWS * Hh];
__device__ __align__(16) float g_ro [NROWS * Hh];
__device__ __align__(16) float g_fipoly[NGg * NGg * 2];
__device__ __align__(16) float g_fh1   [NGg * NGg * Hh];
__device__ __align__(16) float g_fbasis[NGg * NGg * BDd];
__device__ __align__(16) float g_fk    [NGg * NGg * Hh];
__device__ float g_gsum[Bb * 4];   // per-graph: sum_x, sum_y, sum_z, count
// CSR by destination
__device__ int g_deg[Nn];
__device__ int g_off[Nn + 1];
__device__ int g_cur[Nn];
__device__ int g_csr[Ee];

__device__ __forceinline__ float gelu_f(float x) {
    return 0.5f * x * (1.0f + erff(x * 0.70710678118654752f));
}

// ---------------- tiny kernels -------------------------------------------------
__global__ void k_init() {
    int i = blockIdx.x * blockDim.x + threadIdx.x;
    if (i < Nn) { g_deg[i] = 0; g_cur[i] = 0; }
    if (i < Bb * 4) g_gsum[i] = 0.f;
}

__global__ void k_gsum(const float* __restrict__ pos, const int* __restrict__ batch) {
    int n = blockIdx.x * blockDim.x + threadIdx.x;
    if (n >= Nn) return;
    int b = batch[n];
    atomicAdd(&g_gsum[b * 4 + 0], pos[n * 3 + 0]);
    atomicAdd(&g_gsum[b * 4 + 1], pos[n * 3 + 1]);
    atomicAdd(&g_gsum[b * 4 + 2], pos[n * 3 + 2]);
    atomicAdd(&g_gsum[b * 4 + 3], 1.f);
}

__global__ void k_grid_node(const int* __restrict__ batch,
                            const float* __restrict__ grid0,
                            const float* __restrict__ R) {
    int idx = blockIdx.x * blockDim.x + threadIdx.x;  // n*NG + k
    if (idx >= Nn * NGg) return;
    int n = idx / NGg, k = idx % NGg;
    const float* Rb = R + batch[n] * 9;
    float gx = grid0[k * 3 + 0], gy = grid0[k * 3 + 1], gz = grid0[k * 3 + 2];
    float* o = g_grid_node + idx * 3;
    o[0] = Rb[0] * gx + Rb[1] * gy + Rb[2] * gz;
    o[1] = Rb[3] * gx + Rb[4] * gy + Rb[5] * gz;
    o[2] = Rb[6] * gx + Rb[7] * gy + Rb[8] * gz;
}

__global__ void k_fipoly(const float* __restrict__ grid0) {
    int idx = threadIdx.x;
    if (idx >= NGg * NGg) return;
    int p = idx / NGg, o = idx % NGg;
    float fi = grid0[p * 3 + 0] * grid0[o * 3 + 0] +
               grid0[p * 3 + 1] * grid0[o * 3 + 1] +
               grid0[p * 3 + 2] * grid0[o * 3 + 2];
    g_fipoly[idx * 2 + 0] = fi;
    g_fipoly[idx * 2 + 1] = fi * fi;
}

// naive GEMM for tiny fiber matrices (M=144) — fp32, negligible time
__global__ void k_small_gemm(const float* __restrict__ A, const float* __restrict__ W,
                             const float* __restrict__ bias, float* __restrict__ C,
                             int M, int N, int K, int act) {
    int idx = blockIdx.x * blockDim.x + threadIdx.x;
    if (idx >= M * N) return;
    int r = idx / N, c = idx % N;
    float acc = bias ? bias[c] : 0.f;
    for (int k = 0; k < K; k++) acc = fmaf(A[r * K + k], W[k * N + c], acc);
    C[idx] = act ? gelu_f(acc) : acc;
}

__global__ void k_embed(const float* __restrict__ pos, const float* __restrict__ vel,
                        const float* __restrict__ charges, const int* __restrict__ batch,
                        const float* __restrict__ We) {
    int nk = blockIdx.x;           // n*NG + k
    int h = threadIdx.x;           // 0..127
    int n = nk / NGg;
    const float* g = g_grid_node + nk * 3;
    float vx = vel[n * 3 + 0], vy = vel[n * 3 + 1], vz = vel[n * 3 + 2];
    int b = batch[n];
    float cnt = fmaxf(g_gsum[b * 4 + 3], 1.f);
    float rpx = pos[n * 3 + 0] - g_gsum[b * 4 + 0] / cnt;
    float rpy = pos[n * 3 + 1] - g_gsum[b * 4 + 1] / cnt;
    float rpz = pos[n * 3 + 2] - g_gsum[b * 4 + 2] / cnt;
    float f0 = vx * g[0] + vy * g[1] + vz * g[2];
    float f1 = rpx * g[0] + rpy * g[1] + rpz * g[2];
    float f2 = charges[n];
    float f3 = sqrtf(vx * vx + vy * vy + vz * vz);
    g_x[(size_t)nk * Hh + h] =
        f0 * We[h] + f1 * We[Hh + h] + f2 * We[2 * Hh + h] + f3 * We[3 * Hh + h];
}

// ---------------- CSR build (by destination) ------------------------------------
__global__ void k_count(const int* __restrict__ eidx) {
    int e = blockIdx.x * blockDim.x + threadIdx.x;
    if (e >= Ee) return;
    atomicAdd(&g_deg[eidx[Ee + e]], 1);
}

__global__ void k_scan() {
    __shared__ int sh[1024];
    int tid = threadIdx.x;
    int base = tid * 4;
    int v[4];
    int s0 = 0;
#pragma unroll
    for (int i = 0; i < 4; i++) {
        int idx = base + i;
        v[i] = (idx < Nn) ? g_deg[idx] : 0;
        s0 += v[i];
    }
    sh[tid] = s0;
    __syncthreads();
    for (int off = 1; off < 1024; off <<= 1) {
        int t = (tid >= off) ? sh[tid - off] : 0;
        __syncthreads();
        sh[tid] += t;
        __syncthreads();
    }
    int ex = sh[tid] - s0;
#pragma unroll
    for (int i = 0; i < 4; i++) {
        int idx = base + i;
        if (idx < Nn) { g_off[idx] = ex; ex += v[i]; }
    }
    if (tid == 1023) g_off[Nn] = sh[1023];
}

__global__ void k_fill(const int* __restrict__ eidx) {
    int e = blockIdx.x * blockDim.x + threadIdx.x;
    if (e >= Ee) return;
    int d = eidx[Ee + e];
    int pos = g_off[d] + atomicAdd(&g_cur[d], 1);
    g_csr[pos] = e;
}

// ---------------- fused gather + fiber contraction + LayerNorm ------------------
__global__ void __launch_bounds__(128) k_gather_fiber_ln(
    const int* __restrict__ eidx, const __half* __restrict__ kern,
    const float* __restrict__ bconv, const float* __restrict__ gamma,
    const float* __restrict__ beta) {
    int n = blockIdx.x;
    int c = threadIdx.x;
    float acc[NGg];
#pragma unroll
    for (int o = 0; o < NGg; o++) acc[o] = 0.f;

    const int beg = g_off[n], end = g_off[n + 1];
    for (int j = beg; j < end; j++) {
        int e = g_csr[j];
        int s = eidx[e];
        const __half* kr = &kern[(size_t)e * NGg * Hh + c];
        const float* xr = &g_x[(size_t)s * NGg * Hh + c];
#pragma unroll
        for (int o = 0; o < NGg; o++)
            acc[o] = fmaf(__half2float(__ldcs(kr + o * Hh)), xr[o * Hh], acc[o]);
    }

    __shared__ float red[4];
    for (int p = 0; p < NGg; p++) {
        float v = 0.f;
        const float* fkp = &g_fk[(size_t)p * NGg * Hh + c];
#pragma unroll
        for (int o = 0; o < NGg; o++)
            v = fmaf(acc[o], fkp[o * Hh], v);
        v = v * (1.0f / NGg) + bconv[c];

        float s = v;
#pragma unroll
        for (int off = 16; off > 0; off >>= 1) s += __shfl_down_sync(0xffffffffu, s, off);
        if ((c & 31) == 0) red[c >> 5] = s;
        __syncthreads();
        float mean = (red[0] + red[1] + red[2] + red[3]) * (1.f / Hh);
        __syncthreads();
        float dd = v - mean;
        s = dd * dd;
#pragma unroll
        for (int off = 16; off > 0; off >>= 1) s += __shfl_down_sync(0xffffffffu, s, off);
        if ((c & 31) == 0) red[c >> 5] = s;
        __syncthreads();
        float var = (red[0] + red[1] + red[2] + red[3]) * (1.f / Hh);
        g_x2[((size_t)n * NGg + p) * Hh + c] = dd * rsqrtf(var + 1e-5f) * gamma[c] + beta[c];
        __syncthreads();
    }
}

// out[n,d] = (1/NG) sum_k grid_node[n,k,d] * (t[n,k,:]·W_ro2 + b_ro2)
__global__ void k_output(const float* __restrict__ Wro2, const float* __restrict__ bro2,
                         float* __restrict__ out) {
    int n = blockIdx.x;
    int h = threadIdx.x;
    __shared__ float red[4];
    __shared__ float ybc;
    float a0 = 0.f, a1 = 0.f, a2 = 0.f;
    for (int k = 0; k < NGg; k++) {
        float s = g_ro[((size_t)(n * NGg + k)) * Hh + h] * Wro2[h];
#pragma unroll
        for (int off = 16; off > 0; off >>= 1) s += __shfl_down_sync(0xffffffffu, s, off);
        if ((h & 31) == 0) red[h >> 5] = s;
        __syncthreads();
        if (h == 0) ybc = red[0] + red[1] + red[2] + red[3] + bro2[0];
        __syncthreads();
        float y = ybc;
        a0 += g_grid_node[(n * NGg + k) * 3 + 0] * y;
        a1 += g_grid_node[(n * NGg + k) * 3 + 1] * y;
        a2 += g_grid_node[(n * NGg + k) * 3 + 2] * y;
        __syncthreads();
    }
    if (h == 0) {
        out[n * 3 + 0] = a0 * (1.f / NGg);
        out[n * 3 + 1] = a1 * (1.f / NGg);
        out[n * 3 + 2] = a2 * (1.f / NGg);
    }
}

// ---------------- bf16x3 tensor-core GEMM (≈fp32 accuracy) ---------------------
constexpr int BM = 128, BN = 128, BK = 32;
constexpr int ASTRIDE = BK + 8;      // 40 bf16/row -> conflict-free ldmatrix
constexpr int BSTRIDE = BN + 8;      // 136 bf16/row -> conflict-free ldmatrix(.trans)

__device__ __forceinline__ void mma_bf16(float* d, const uint32_t* a, const uint32_t* b) {
    asm volatile(
        "mma.sync.aligned.m16n8k16.row.col.f32.bf16.bf16.f32 "
        "{%0,%1,%2,%3}, {%4,%5,%6,%7}, {%8,%9}, {%0,%1,%2,%3};\n"
        : "+f"(d[0]), "+f"(d[1]), "+f"(d[2]), "+f"(d[3])
        : "r"(a[0]), "r"(a[1]), "r"(a[2]), "r"(a[3]), "r"(b[0]), "r"(b[1]));
}

__device__ __forceinline__ void ldm_x4(uint32_t* r, const __nv_bfloat16* p) {
    uint32_t addr = (uint32_t)__cvta_generic_to_shared(p);
    asm volatile("ldmatrix.sync.aligned.m8n8.x4.shared.b16 {%0,%1,%2,%3}, [%4];"
                 : "=r"(r[0]), "=r"(r[1]), "=r"(r[2]), "=r"(r[3]) : "r"(addr));
}

__device__ __forceinline__ void ldm_x2t(uint32_t* r, const __nv_bfloat16* p) {
    uint32_t addr = (uint32_t)__cvta_generic_to_shared(p);
    asm volatile("ldmatrix.sync.aligned.m8n8.x2.trans.shared.b16 {%0,%1}, [%2];"
                 : "=r"(r[0]), "=r"(r[1]) : "r"(addr));
}

__device__ __forceinline__ void split_bf16(float v, __nv_bfloat16& hi, __nv_bfloat16& lo) {
    hi = __float2bfloat16_rn(v);
    lo = __float2bfloat16_rn(v - __bfloat162float(hi));
}

template <bool GELU, bool ACCUM>
__global__ void __launch_bounds__(256, 2) gemm_bf16x3(
    const float* __restrict__ A, const float* __restrict__ Bw,
    const float* __restrict__ bias, float* __restrict__ C,
    int M, int N, int K) {
    __shared__ __nv_bfloat16 As1[BM][ASTRIDE];
    __shared__ __nv_bfloat16 As2[BM][ASTRIDE];
    __shared__ __nv_bfloat16 Bs1[BK][BSTRIDE];
    __shared__ __nv_bfloat16 Bs2[BK][BSTRIDE];

    const int tid  = threadIdx.x;
    const int lane = tid & 31;
    const int warp = tid >> 5;
    const int wm = warp & 1;
    const int wn = warp >> 1;
    const int br = blockIdx.x * BM;
    const int bc = blockIdx.y * BN;
    const int gid = lane >> 2;
    const int qid = lane & 3;

    float acc[4][4][4];
#pragma unroll
    for (int mt = 0; mt < 4; mt++)
#pragma unroll
        for (int nt = 0; nt < 4; nt++)
#pragma unroll
            for (int j = 0; j < 4; j++) acc[mt][nt][j] = 0.f;

    const int aRow = ((lane >> 3) & 1) * 8 + (lane & 7);
    const int aKof = (lane >> 4) * 8;
    const int bK   = lane & 15;

    const int ktiles = (K + BK - 1) / BK;
    for (int kt = 0; kt < ktiles; kt++) {
        const int k0 = kt * BK;
#pragma unroll
        for (int it = 0; it < 4; it++) {
            int f = it * 256 + tid;
            int row = f >> 3, kq = (f & 7) * 4;
            float4 v = make_float4(0.f, 0.f, 0.f, 0.f);
            int gr = br + row;
            if (gr < M && (k0 + kq) < K)
                v = *reinterpret_cast<const float4*>(&A[(size_t)gr * K + k0 + kq]);
            __nv_bfloat16 h0, h1, h2, h3, l0, l1, l2, l3;
            split_bf16(v.x, h0, l0); split_bf16(v.y, h1, l1);
            split_bf16(v.z, h2, l2); split_bf16(v.w, h3, l3);
            *reinterpret_cast<__nv_bfloat162*>(&As1[row][kq])     = __nv_bfloat162(h0, h1);
            *reinterpret_cast<__nv_bfloat162*>(&As1[row][kq + 2]) = __nv_bfloat162(h2, h3);
            *reinterpret_cast<__nv_bfloat162*>(&As2[row][kq])     = __nv_bfloat162(l0, l1);
            *reinterpret_cast<__nv_bfloat162*>(&As2[row][kq + 2]) = __nv_bfloat162(l2, l3);
        }
#pragma unroll
        for (int it = 0; it < 4; it++) {
            int f = it * 256 + tid;
            int krow = f >> 5, n4 = (f & 31) * 4;
            float4 v = make_float4(0.f, 0.f, 0.f, 0.f);
            if ((k0 + krow) < K)
                v = *reinterpret_cast<const float4*>(&Bw[(size_t)(k0 + krow) * N + bc + n4]);
            __nv_bfloat16 h0, h1, h2, h3, l0, l1, l2, l3;
            split_bf16(v.x, h0, l0); split_bf16(v.y, h1, l1);
            split_bf16(v.z, h2, l2); split_bf16(v.w, h3, l3);
            *reinterpret_cast<__nv_bfloat162*>(&Bs1[krow][n4])     = __nv_bfloat162(h0, h1);
            *reinterpret_cast<__nv_bfloat162*>(&Bs1[krow][n4 + 2]) = __nv_bfloat162(h2, h3);
            *reinterpret_cast<__nv_bfloat162*>(&Bs2[krow][n4])     = __nv_bfloat162(l0, l1);
            *reinterpret_cast<__nv_bfloat162*>(&Bs2[krow][n4 + 2]) = __nv_bfloat162(l2, l3);
        }
        __syncthreads();

#pragma unroll
        for (int ks = 0; ks < 2; ks++) {
            const int kk = ks * 16;
            uint32_t bb[4][2], bs[4][2];
#pragma unroll
            for (int nt = 0; nt < 4; nt++) {
                const int n0 = wn * 32 + nt * 8;
                ldm_x2t(bb[nt], &Bs1[kk + bK][n0]);
                ldm_x2t(bs[nt], &Bs2[kk + bK][n0]);
            }
#pragma unroll
            for (int mt = 0; mt < 4; mt++) {
                const int r0 = wm * 64 + mt * 16 + aRow;
                uint32_t ah[4], al[4];
                ldm_x4(ah, &As1[r0][kk + aKof]);
                ldm_x4(al, &As2[r0][kk + aKof]);
#pragma unroll
                for (int nt = 0; nt < 4; nt++) {
                    mma_bf16(acc[mt][nt], al, bb[nt]);
                    mma_bf16(acc[mt][nt], ah, bs[nt]);
                    mma_bf16(acc[mt][nt], ah, bb[nt]);
                }
            }
        }
        __syncthreads();
    }

#pragma unroll
    for (int nt = 0; nt < 4; nt++) {
        const int c = bc + wn * 32 + nt * 8 + qid * 2;
        float b0 = 0.f, b1 = 0.f;
        if (bias) { b0 = bias[c]; b1 = bias[c + 1]; }
#pragma unroll
        for (int mt = 0; mt < 4; mt++) {
            int r0 = br + wm * 64 + mt * 16 + gid;
#pragma unroll
            for (int half = 0; half < 2; half++) {
                int r = r0 + half * 8;
                if (r >= M) continue;
                float v0 = acc[mt][nt][half * 2 + 0] + b0;
                float v1 = acc[mt][nt][half * 2 + 1] + b1;
                if (GELU) { v0 = gelu_f(v0); v1 = gelu_f(v1); }
                float2* p = reinterpret_cast<float2*>(&C[(size_t)r * N + c]);
                if (ACCUM) {
                    float2 o = *p;
                    o.x += v0; o.y += v1;
                    *p = o;
                } else {
                    *p = make_float2(v0, v1);
                }
            }
        }
    }
}

// ---------------- shared helpers for smem-A fused kernels -----------------------
constexpr int A2S = 136;
constexpr int BTILE = BK * BSTRIDE;

__device__ __forceinline__ void split_store_B(__nv_bfloat16* B1, __nv_bfloat16* B2,
                                              int tid, const float4* v) {
#pragma unroll
    for (int it = 0; it < 4; it++) {
        int f = it * 256 + tid;
        int krow = f >> 5, n4 = (f & 31) * 4;
        __nv_bfloat16 h0, h1, h2, h3, l0, l1, l2, l3;
        split_bf16(v[it].x, h0, l0); split_bf16(v[it].y, h1, l1);
        split_bf16(v[it].z, h2, l2); split_bf16(v[it].w, h3, l3);
        *reinterpret_cast<__nv_bfloat162*>(&B1[krow * BSTRIDE + n4])     = __nv_bfloat162(h0, h1);
        *reinterpret_cast<__nv_bfloat162*>(&B1[krow * BSTRIDE + n4 + 2]) = __nv_bfloat162(h2, h3);
        *reinterpret_cast<__nv_bfloat162*>(&B2[krow * BSTRIDE + n4])     = __nv_bfloat162(l0, l1);
        *reinterpret_cast<__nv_bfloat162*>(&B2[krow * BSTRIDE + n4 + 2]) = __nv_bfloat162(l2, l3);
    }
}

__device__ __forceinline__ void load_B_tile(const float* __restrict__ Bw, int ldb,
                                            int tid, int k0, float4* v) {
#pragma unroll
    for (int it = 0; it < 4; it++) {
        int f = it * 256 + tid;
        int krow = f >> 5, n4 = (f & 31) * 4;
        v[it] = *reinterpret_cast<const float4*>(&Bw[(size_t)(k0 + krow) * ldb + n4]);
    }
}

// ---------------- fully fused edge chain: features -> basis -> kern0,kern1 ------
constexpr size_t FK_OFF_A1 = 0;
constexpr size_t FK_OFF_A2 = FK_OFF_A1 + (size_t)BM * A2S * 2;      // 34816
constexpr size_t FK_OFF_B1 = FK_OFF_A2 + (size_t)BM * A2S * 2;      // 69632 (2 buffers)
constexpr size_t FK_OFF_B2 = FK_OFF_B1 + (size_t)2 * BTILE * 2;     // 87040 (2 buffers)
constexpr size_t FK_SMEM   = FK_OFF_B2 + (size_t)2 * BTILE * 2;     // 104448

struct KBCtx {
    const __nv_bfloat16 *As1, *As2;
    __nv_bfloat16 *Bs1, *Bs2;        // base of 2-buffer arrays
    int tid, wm, wn, aRow, aKof, bK;
};

// one full K=128 mainloop against row-major weights Bw [128][128], B double-buffered
__device__ __forceinline__ void kb_mainloop(const KBCtx& cx,
                                            const float* __restrict__ Bw,
                                            float acc[4][4][4]) {
#pragma unroll
    for (int mt = 0; mt < 4; mt++)
#pragma unroll
        for (int nt = 0; nt < 4; nt++)
#pragma unroll
            for (int j = 0; j < 4; j++) acc[mt][nt][j] = 0.f;

    float4 v[4];
    load_B_tile(Bw, Hh, cx.tid, 0, v);
    split_store_B(cx.Bs1, cx.Bs2, cx.tid, v);
    __syncthreads();

#pragma unroll
    for (int kt = 0; kt < 4; kt++) {
        const int k0 = kt * BK;
        if (kt < 3) load_B_tile(Bw, Hh, cx.tid, k0 + BK, v);
        const __nv_bfloat16* B1 = cx.Bs1 + (kt & 1) * BTILE;
        const __nv_bfloat16* B2 = cx.Bs2 + (kt & 1) * BTILE;
#pragma unroll
        for (int ks = 0; ks < 2; ks++) {
            const int kk = ks * 16;
            uint32_t bb[4][2], bs[4][2];
#pragma unroll
            for (int nt = 0; nt < 4; nt++) {
                const int n0 = cx.wn * 32 + nt * 8;
                ldm_x2t(bb[nt], &B1[(kk + cx.bK) * BSTRIDE + n0]);
                ldm_x2t(bs[nt], &B2[(kk + cx.bK) * BSTRIDE + n0]);
            }
#pragma unroll
            for (int mt = 0; mt < 4; mt++) {
                const int r0 = cx.wm * 64 + mt * 16 + cx.aRow;
                uint32_t ah[4], al[4];
                ldm_x4(ah, &cx.As1[r0 * A2S + k0 + kk + cx.aKof]);
                ldm_x4(al, &cx.As2[r0 * A2S + k0 + kk + cx.aKof]);
#pragma unroll
                for (int nt = 0; nt < 4; nt++) {
                    mma_bf16(acc[mt][nt], al, bb[nt]);
                    mma_bf16(acc[mt][nt], ah, bs[nt]);
                    mma_bf16(acc[mt][nt], ah, bb[nt]);
                }
            }
        }
        if (kt < 3) split_store_B(cx.Bs1 + ((kt + 1) & 1) * BTILE,
                                  cx.Bs2 + ((kt + 1) & 1) * BTILE, cx.tid, v);
        __syncthreads();
    }
}

__global__ void __launch_bounds__(256, 2) k_basis_kern(
    const float* __restrict__ pos, const float* __restrict__ charges,
    const int* __restrict__ eidx,
    const float* __restrict__ W1, const float* __restrict__ b1,
    const float* __restrict__ W2, const float* __restrict__ b2,
    const float* __restrict__ Wc,     // [2][128][128]
    __half* __restrict__ kern0, __half* __restrict__ kern1, int M) {
    extern __shared__ char smraw[];
    __nv_bfloat16* As1 = reinterpret_cast<__nv_bfloat16*>(smraw + FK_OFF_A1); // [128][136]
    __nv_bfloat16* As2 = reinterpret_cast<__nv_bfloat16*>(smraw + FK_OFF_A2);
    __nv_bfloat16* Bs1 = reinterpret_cast<__nv_bfloat16*>(smraw + FK_OFF_B1); // 2x[32][136]
    __nv_bfloat16* Bs2 = reinterpret_cast<__nv_bfloat16*>(smraw + FK_OFF_B2);
    float* EIP = reinterpret_cast<float*>(smraw + FK_OFF_B1);
    float* W1s = EIP + BM * 12;
    float* b1s = W1s + 12 * Hh;

    const int tid  = threadIdx.x;
    const int lane = tid & 31;
    const int warp = tid >> 5;
    const int wm = warp & 1;
    const int wn = warp >> 1;
    const int br = blockIdx.x * BM;
    const int gid = lane >> 2;
    const int qid = lane & 3;

    KBCtx cx;
    cx.As1 = As1; cx.As2 = As2; cx.Bs1 = Bs1; cx.Bs2 = Bs2;
    cx.tid = tid; cx.wm = wm; cx.wn = wn;
    cx.aRow = ((lane >> 3) & 1) * 8 + (lane & 7);
    cx.aKof = (lane >> 4) * 8;
    cx.bK   = lane & 15;

    // ---- phase 0: compute edge-invariant features in-kernel (one row/thread) ----
    for (int f = tid; f < 12 * Hh; f += 256) W1s[f] = W1[f];
    if (tid < Hh) b1s[tid] = b1[tid];
    if (tid < BM) {
        int row = br + tid;
        float f0 = 0.f, f1 = 0.f, f2 = 0.f;
        if (row < M) {
            int e = row / NGg;
            int k = row - e * NGg;
            int s = eidx[e], d = eidx[Ee + e];
            float rx = pos[s * 3 + 0] - pos[d * 3 + 0];
            float ry = pos[s * 3 + 1] - pos[d * 3 + 1];
            float rz = pos[s * 3 + 2] - pos[d * 3 + 2];
            const float* g = g_grid_node + (s * NGg + k) * 3;
            float inv1 = rx * g[0] + ry * g[1] + rz * g[2];
            float vx = rx - inv1 * g[0], vy = ry - inv1 * g[1], vz = rz - inv1 * g[2];
            float inv2 = sqrtf(vx * vx + vy * vy + vz * vz);
            f0 = inv1; f1 = inv2; f2 = charges[s] * charges[d];
        }
        float* o = &EIP[tid * 12];
        o[0] = f0;  o[1] = f1;  o[2] = f2;
        o[3] = f0 * f0; o[4]  = f0 * f1; o[5]  = f0 * f2;
        o[6] = f1 * f0; o[7]  = f1 * f1; o[8]  = f1 * f2;
        o[9] = f2 * f0; o[10] = f2 * f1; o[11] = f2 * f2;
    }
    __syncthreads();

    // ---- phase 1: h1 = gelu(eip@W1 + b1) -> As (split bf16, persistent) ----
    {
        const int r  = tid >> 1;
        const int cb = (tid & 1) * 64;
        float e[12];
#pragma unroll
        for (int k = 0; k < 12; k++) e[k] = EIP[r * 12 + k];
#pragma unroll
        for (int c2 = 0; c2 < 64; c2 += 2) {
            int c = cb + c2;
            float a0 = 0.f, a1 = 0.f;
#pragma unroll
            for (int k = 0; k < 12; k++) {
                a0 = fmaf(e[k], W1s[k * Hh + c], a0);
                a1 = fmaf(e[k], W1s[k * Hh + c + 1], a1);
            }
            a0 = gelu_f(a0 + b1s[c]); a1 = gelu_f(a1 + b1s[c + 1]);
            __nv_bfloat16 h0, l0, h1, l1;
            split_bf16(a0, h0, l0);
            split_bf16(a1, h1, l1);
            *reinterpret_cast<__nv_bfloat162*>(&As1[r * A2S + c]) = __nv_bfloat162(h0, h1);
            *reinterpret_cast<__nv_bfloat162*>(&As2[r * A2S + c]) = __nv_bfloat162(l0, l1);
        }
    }
    __syncthreads();

    float acc[4][4][4];

    // ---- phase 2: basis = gelu(h1 @ W2 + b2) -> back into As (smem only) ----
    kb_mainloop(cx, W2, acc);
    {
#pragma unroll
        for (int nt = 0; nt < 4; nt++) {
            const int c = wn * 32 + nt * 8 + qid * 2;
            float bb0 = b2[c], bb1 = b2[c + 1];
#pragma unroll
            for (int mt = 0; mt < 4; mt++) {
                int rl = wm * 64 + mt * 16 + gid;
#pragma unroll
                for (int half = 0; half < 2; half++) {
                    int r = rl + half * 8;
                    float v0 = gelu_f(acc[mt][nt][half * 2 + 0] + bb0);
                    float v1 = gelu_f(acc[mt][nt][half * 2 + 1] + bb1);
                    __nv_bfloat16 h0, l0, h1, l1;
                    split_bf16(v0, h0, l0);
                    split_bf16(v1, h1, l1);
                    *reinterpret_cast<__nv_bfloat162*>(&As1[r * A2S + c]) = __nv_bfloat162(h0, h1);
                    *reinterpret_cast<__nv_bfloat162*>(&As2[r * A2S + c]) = __nv_bfloat162(l0, l1);
                }
            }
        }
    }
    __syncthreads();

    // ---- phase 3: kern_l = basis @ W_conv[l], l = 0,1 (fp16 streaming stores) ----
#pragma unroll
    for (int l = 0; l < 2; l++) {
        kb_mainloop(cx, Wc + (size_t)l * BDd * Hh, acc);
        __half* kern = l == 0 ? kern0 : kern1;
#pragma unroll
        for (int nt = 0; nt < 4; nt++) {
            const int c = wn * 32 + nt * 8 + qid * 2;
#pragma unroll
            for (int mt = 0; mt < 4; mt++) {
                int r0 = br + wm * 64 + mt * 16 + gid;
#pragma unroll
                for (int half = 0; half < 2; half++) {
                    int r = r0 + half * 8;
                    if (r >= M) continue;
                    __half2 hv = __floats2half2_rn(acc[mt][nt][half * 2 + 0],
                                                   acc[mt][nt][half * 2 + 1]);
                    __stcs(reinterpret_cast<unsigned int*>(&kern[(size_t)r * Hh + c]),
                           *reinterpret_cast<unsigned int*>(&hv));
                }
            }
        }
    }
}

// ---------------- fused FF block: x += W_ff2 @ gelu(W_ff1 @ x2)  -----------------
// BM=64 rows/block; hidden (512) processed in 4 chunks of 128; h never leaves smem.
constexpr int FBM = 64;
constexpr size_t FF_OFF_AX1 = 0;
constexpr size_t FF_OFF_AX2 = FF_OFF_AX1 + (size_t)FBM * A2S * 2;   // 17408
constexpr size_t FF_OFF_AH1 = FF_OFF_AX2 + (size_t)FBM * A2S * 2;   // 34816
constexpr size_t FF_OFF_AH2 = FF_OFF_AH1 + (size_t)FBM * A2S * 2;   // 52224
constexpr size_t FF_OFF_B1  = FF_OFF_AH2 + (size_t)FBM * A2S * 2;   // 69632 (2 bufs)
constexpr size_t FF_OFF_B2  = FF_OFF_B1 + (size_t)2 * BTILE * 2;    // 87040 (2 bufs)
constexpr size_t FF_SMEM    = FF_OFF_B2 + (size_t)2 * BTILE * 2;    // 104448

// K=128 mainloop, 64-row A in smem, warp tile 32x32. CLEAR selects init vs accum.
template <bool CLEAR>
__device__ __forceinline__ void ff_mainloop(
    const __nv_bfloat16* __restrict__ A1, const __nv_bfloat16* __restrict__ A2,
    __nv_bfloat16* Bs1, __nv_bfloat16* Bs2,
    const float* __restrict__ Bw, int ldb,
    int tid, int wm, int wn, int aRow, int aKof, int bKl,
    float acc[2][4][4]) {
    if (CLEAR) {
#pragma unroll
        for (int mt = 0; mt < 2; mt++)
#pragma unroll
            for (int nt = 0; nt < 4; nt++)
#pragma unroll
                for (int j = 0; j < 4; j++) acc[mt][nt][j] = 0.f;
    }
    float4 v[4];
    load_B_tile(Bw, ldb, tid, 0, v);
    split_store_B(Bs1, Bs2, tid, v);
    __syncthreads();

#pragma unroll
    for (int kt = 0; kt < 4; kt++) {
        const int k0 = kt * BK;
        if (kt < 3) load_B_tile(Bw, ldb, tid, k0 + BK, v);
        const __nv_bfloat16* B1 = Bs1 + (kt & 1) * BTILE;
        const __nv_bfloat16* B2 = Bs2 + (kt & 1) * BTILE;
#pragma unroll
        for (int ks = 0; ks < 2; ks++) {
            const int kk = ks * 16;
            uint32_t bb[4][2], bs[4][2];
#pragma unroll
            for (int nt = 0; nt < 4; nt++) {
                const int n0 = wn * 32 + nt * 8;
                ldm_x2t(bb[nt], &B1[(kk + bKl) * BSTRIDE + n0]);
                ldm_x2t(bs[nt], &B2[(kk + bKl) * BSTRIDE + n0]);
            }
#pragma unroll
            for (int mt = 0; mt < 2; mt++) {
                const int r0 = wm * 32 + mt * 16 + aRow;
                uint32_t ah[4], al[4];
                ldm_x4(ah, &A1[r0 * A2S + k0 + kk + aKof]);
                ldm_x4(al, &A2[r0 * A2S + k0 + kk + aKof]);
#pragma unroll
                for (int nt = 0; nt < 4; nt++) {
                    mma_bf16(acc[mt][nt], al, bb[nt]);
                    mma_bf16(acc[mt][nt], ah, bs[nt]);
                    mma_bf16(acc[mt][nt], ah, bb[nt]);
                }
            }
        }
        if (kt < 3) split_store_B(Bs1 + ((kt + 1) & 1) * BTILE,
                                  Bs2 + ((kt + 1) & 1) * BTILE, tid, v);
        __syncthreads();
    }
}

__global__ void __launch_bounds__(256, 2) k_ff_fused(
    const float* __restrict__ x2, const float* __restrict__ Wff1,
    const float* __restrict__ bff1, const float* __restrict__ Wff2,
    const float* __restrict__ bff2, float* __restrict__ x, int M) {
    extern __shared__ char smraw[];
    __nv_bfloat16* Ax1 = reinterpret_cast<__nv_bfloat16*>(smraw + FF_OFF_AX1);
    __nv_bfloat16* Ax2 = reinterpret_cast<__nv_bfloat16*>(smraw + FF_OFF_AX2);
    __nv_bfloat16* Ah1 = reinterpret_cast<__nv_bfloat16*>(smraw + FF_OFF_AH1);
    __nv_bfloat16* Ah2 = reinterpret_cast<__nv_bfloat16*>(smraw + FF_OFF_AH2);
    __nv_bfloat16* Bs1 = reinterpret_cast<__nv_bfloat16*>(smraw + FF_OFF_B1);
    __nv_bfloat16* Bs2 = reinterpret_cast<__nv_bfloat16*>(smraw + FF_OFF_B2);

    const int tid  = threadIdx.x;
    const int lane = tid & 31;
    const int warp = tid >> 5;
    const int wm = warp & 1;             // 2 warps along M (32 rows each)
    const int wn = warp >> 1;            // 4 warps along N (32 cols each)
    const int br = blockIdx.x * FBM;
    const int gid = lane >> 2;
    const int qid = lane & 3;
    const int aRow = ((lane >> 3) & 1) * 8 + (lane & 7);
    const int aKof = (lane >> 4) * 8;
    const int bKl  = lane & 15;

    // stage x2 tile (64 x 128 fp32) -> split bf16 Ax
#pragma unroll
    for (int it = 0; it < 8; it++) {
        int f = it * 256 + tid;
        int row = f >> 5, kq = (f & 31) * 4;
        float4 v = make_float4(0.f, 0.f, 0.f, 0.f);
        int gr = br + row;
        if (gr < M)
            v = *reinterpret_cast<const float4*>(&x2[(size_t)gr * Hh + kq]);
        __nv_bfloat16 h0, h1, h2, h3, l0, l1, l2, l3;
        split_bf16(v.x, h0, l0); split_bf16(v.y, h1, l1);
        split_bf16(v.z, h2, l2); split_bf16(v.w, h3, l3);
        *reinterpret_cast<__nv_bfloat162*>(&Ax1[row * A2S + kq])     = __nv_bfloat162(h0, h1);
        *reinterpret_cast<__nv_bfloat162*>(&Ax1[row * A2S + kq + 2]) = __nv_bfloat162(h2, h3);
        *reinterpret_cast<__nv_bfloat162*>(&Ax2[row * A2S + kq])     = __nv_bfloat162(l0, l1);
        *reinterpret_cast<__nv_bfloat162*>(&Ax2[row * A2S + kq + 2]) = __nv_bfloat162(l2, l3);
    }
    __syncthreads();

    float acc1[2][4][4];
    float acc2[2][4][4];
#pragma unroll
    for (int mt = 0; mt < 2; mt++)
#pragma unroll
        for (int nt = 0; nt < 4; nt++)
#pragma unroll
            for (int j = 0; j < 4; j++) acc2[mt][nt][j] = 0.f;

#pragma unroll
    for (int chunk = 0; chunk < 4; chunk++) {
        // h_chunk = gelu(x2 @ W_ff1[:, chunk*128 : +128] + b_ff1[chunk])
        ff_mainloop<true>(Ax1, Ax2, Bs1, Bs2, Wff1 + chunk * Hh, 4 * Hh,
                          tid, wm, wn, aRow, aKof, bKl, acc1);
#pragma unroll
        for (int nt = 0; nt < 4; nt++) {
            const int c = wn * 32 + nt * 8 + qid * 2;
            float bb0 = bff1[chunk * Hh + c], bb1 = bff1[chunk * Hh + c + 1];
#pragma unroll
            for (int mt = 0; mt < 2; mt++) {
                int rl = wm * 32 + mt * 16 + gid;
#pragma unroll
                for (int half = 0; half < 2; half++) {
                    int r = rl + half * 8;
                    float v0 = gelu_f(acc1[mt][nt][half * 2 + 0] + bb0);
                    float v1 = gelu_f(acc1[mt][nt][half * 2 + 1] + bb1);
                    __nv_bfloat16 h0, l0, h1, l1;
                    split_bf16(v0, h0, l0);
                    split_bf16(v1, h1, l1);
                    *reinterpret_cast<__nv_bfloat162*>(&Ah1[r * A2S + c]) = __nv_bfloat162(h0, h1);
                    *reinterpret_cast<__nv_bfloat162*>(&Ah2[r * A2S + c]) = __nv_bfloat162(l0, l1);
                }
            }
        }
        // acc2 += h_chunk @ W_ff2[chunk*128 : +128, :]
        ff_mainloop<false>(Ah1, Ah2, Bs1, Bs2, Wff2 + (size_t)chunk * Hh * Hh, Hh,
                           tid, wm, wn, aRow, aKof, bKl, acc2);
    }

    // epilogue: x += acc2 + b_ff2
#pragma unroll
    for (int nt = 0; nt < 4; nt++) {
        const int c = wn * 32 + nt * 8 + qid * 2;
        float bb0 = bff2[c], bb1 = bff2[c + 1];
#pragma unroll
        for (int mt = 0; mt < 2; mt++) {
            int r0 = br + wm * 32 + mt * 16 + gid;
#pragma unroll
            for (int half = 0; half < 2; half++) {
                int r = r0 + half * 8;
                if (r >= M) continue;
                float2* p = reinterpret_cast<float2*>(&x[(size_t)r * Hh + c]);
                float2 o = *p;
                o.x += acc2[mt][nt][half * 2 + 0] + bb0;
                o.y += acc2[mt][nt][half * 2 + 1] + bb1;
                *p = o;
            }
        }
    }
}

// ---------------- host launch ----------------------------------------------------
static void launch_gemm(const float* A, const float* W, const float* bias, float* C,
                        int M, int N, int K, bool gelu_act, bool accum) {
    dim3 grid((M + BM - 1) / BM, N / BN);
    if (gelu_act)   gemm_bf16x3<true, false><<<grid, 256>>>(A, W, bias, C, M, N, K);
    else if (accum) gemm_bf16x3<false, true><<<grid, 256>>>(A, W, bias, C, M, N, K);
    else            gemm_bf16x3<false, false><<<grid, 256>>>(A, W, bias, C, M, N, K);
}

extern "C" void kernel_launch(void* const* d_in, const int* in_sizes, int n_in,
                              void* d_out, int out_size) {
    const float* pos      = (const float*)d_in[0];
    const float* vel      = (const float*)d_in[1];
    const float* charges  = (const float*)d_in[2];
    const int*   batch    = (const int*)d_in[3];
    const int*   eidx     = (const int*)d_in[4];
    const float* grid0    = (const float*)d_in[5];
    const float* R        = (const float*)d_in[6];
    const float* W_basis1 = (const float*)d_in[7];
    const float* b_basis1 = (const float*)d_in[8];
    const float* W_basis2 = (const float*)d_in[9];
    const float* b_basis2 = (const float*)d_in[10];
    const float* W_fbasis1 = (const float*)d_in[11];
    const float* b_fbasis1 = (const float*)d_in[12];
    const float* W_fbasis2 = (const float*)d_in[13];
    const float* b_fbasis2 = (const float*)d_in[14];
    const float* W_embed  = (const float*)d_in[15];
    const float* W_conv   = (const float*)d_in[16];
    const float* W_fiber  = (const float*)d_in[17];
    const float* b_conv   = (const float*)d_in[18];
    const float* ln_gamma = (const float*)d_in[19];
    const float* ln_beta  = (const float*)d_in[20];
    const float* W_ff1    = (const float*)d_in[21];
    const float* b_ff1    = (const float*)d_in[22];
    const float* W_ff2    = (const float*)d_in[23];
    const float* b_ff2    = (const float*)d_in[24];
    const float* W_ro1    = (const float*)d_in[25];
    const float* b_ro1    = (const float*)d_in[26];
    const float* W_ro2    = (const float*)d_in[27];
    const float* b_ro2    = (const float*)d_in[28];
    float* out = (float*)d_out;

    float *x, *x2, *ro, *fip, *fh1, *fbasis, *fk;
    __half *kern0, *kern1;
    cudaGetSymbolAddress((void**)&kern0, g_kern0);
    cudaGetSymbolAddress((void**)&kern1, g_kern1);
    cudaGetSymbolAddress((void**)&x,     g_x);
    cudaGetSymbolAddress((void**)&x2,    g_x2);
    cudaGetSymbolAddress((void**)&ro,    g_ro);
    cudaGetSymbolAddress((void**)&fip,   g_fipoly);
    cudaGetSymbolAddress((void**)&fh1,   g_fh1);
    cudaGetSymbolAddress((void**)&fbasis,g_fbasis);
    cudaGetSymbolAddress((void**)&fk,    g_fk);

    static bool attr_done = false;
    if (!attr_done) {
        cudaFuncSetAttribute(k_basis_kern, cudaFuncAttributeMaxDynamicSharedMemorySize,
                             (int)FK_SMEM);
        cudaFuncSetAttribute(k_ff_fused, cudaFuncAttributeMaxDynamicSharedMemorySize,
                             (int)FF_SMEM);
        attr_done = true;
    }

    // init + graph statistics + rotated grids
    k_init<<<(Nn + 255) / 256, 256>>>();
    k_gsum<<<(Nn + 255) / 256, 256>>>(pos, batch);
    k_grid_node<<<(Nn * NGg + 255) / 256, 256>>>(batch, grid0, R);

    // CSR by destination (built once, reused by both layers)
    k_count<<<(Ee + 255) / 256, 256>>>(eidx);
    k_scan<<<1, 1024>>>();
    k_fill<<<(Ee + 255) / 256, 256>>>(eidx);

    // edge chain fully fused: features -> h1 -> basis (all smem) -> kern0, kern1
    k_basis_kern<<<(EROWS + BM - 1) / BM, 256, FK_SMEM>>>(
        pos, charges, eidx, W_basis1, b_basis1, W_basis2, b_basis2, W_conv,
        kern0, kern1, EROWS);

    // fiber basis MLP: 144 rows
    k_fipoly<<<1, 256>>>(grid0);
    k_small_gemm<<<(NGg * NGg * Hh + 255) / 256, 256>>>(fip, W_fbasis1, b_fbasis1, fh1,
                                                        NGg * NGg, Hh, 2, 1);
    k_small_gemm<<<(NGg * NGg * BDd + 255) / 256, 256>>>(fh1, W_fbasis2, b_fbasis2, fbasis,
                                                         NGg * NGg, BDd, Hh, 1);

    // node embedding
    k_embed<<<NROWS, Hh>>>(pos, vel, charges, batch, W_embed);

    for (int l = 0; l < Ll; l++) {
        // fk = fiber_basis @ W_fiber[l]
        k_small_gemm<<<(NGg * NGg * Hh + 255) / 256, 256>>>(
            fbasis, W_fiber + (size_t)l * BDd * Hh, nullptr, fk, NGg * NGg, Hh, BDd, 0);
        // fused: x1 = gather-sum(kern_l * x[src] -> dst); x2 = LN(fiber(x1))
        k_gather_fiber_ln<<<Nn, Hh>>>(eidx, l == 0 ? kern0 : kern1, b_conv + l * Hh,
                                      ln_gamma + l * Hh, ln_beta + l * Hh);
        // fused FF: x += W_ff2 @ gelu(W_ff1 @ x2)   (hidden never leaves smem)
        k_ff_fused<<<(NROWS + FBM - 1) / FBM, 256, FF_SMEM>>>(
            x2, W_ff1 + (size_t)l * Hh * 4 * Hh, b_ff1 + l * 4 * Hh,
            W_ff2 + (size_t)l * 4 * Hh * Hh, b_ff2 + l * Hh, x, NROWS);
    }

    // readout
    launch_gemm(x, W_ro1, b_ro1, ro, NROWS, Hh, Hh, true, false);
    k_output<<<Nn, Hh>>>(W_ro2, b_ro2, out);
}

// round 17
// speedup vs baseline: 1.3619x; 1.0232x over previous
#include <cuda_runtime.h>
#include <cuda_bf16.h>
#include <cuda_fp16.h>
#include <math.h>
#include <stdint.h>

// Problem dims (fixed by the dataset)
constexpr int Nn  = 4000;
constexpr int Ee  = 50000;
constexpr int NGg = 12;
constexpr int Hh  = 128;
constexpr int BDd = 128;
constexpr int Ll  = 2;
constexpr int Bb  = 100;

constexpr int EROWS = Ee * NGg;     // 600000
constexpr int NROWS = Nn * NGg;     // 48000

// ---------------- scratch (device globals; no cudaMalloc allowed) -------------
__device__ __align__(16) float g_grid_node[Nn * NGg * 3];
__device__ __align__(16) __half g_kern0[(size_t)EROWS * Hh];
__device__ __align__(16) __half g_kern1[(size_t)EROWS * Hh];
__device__ __align__(16) float g_x  [NROWS * Hh];
__device__ __align__(16) float g_x2 [NROWS * Hh];
__device__ __align__(16) float g_ro [NROWS * Hh];
__device__ __align__(16) float g_fipoly[NGg * NGg * 2];
__device__ __align__(16) float g_fh1   [NGg * NGg * Hh];
__device__ __align__(16) float g_fbasis[NGg * NGg * BDd];
__device__ __align__(16) float g_fk    [NGg * NGg * Hh];
__device__ float g_gsum[Bb * 4];   // per-graph: sum_x, sum_y, sum_z, count
// CSR by destination
__device__ int g_deg[Nn];
__device__ int g_off[Nn + 1];
__device__ int g_cur[Nn];
__device__ int g_csr[Ee];

__device__ __forceinline__ float gelu_f(float x) {
    return 0.5f * x * (1.0f + erff(x * 0.70710678118654752f));
}

__device__ __forceinline__ float to_tf32(float x) {
    uint32_t y;
    asm("cvt.rna.tf32.f32 %0, %1;" : "=r"(y) : "f"(x));
    return __uint_as_float(y);
}

// ---------------- tiny kernels -------------------------------------------------
__global__ void k_init() {
    int i = blockIdx.x * blockDim.x + threadIdx.x;
    if (i < Nn) { g_deg[i] = 0; g_cur[i] = 0; }
    if (i < Bb * 4) g_gsum[i] = 0.f;
}

__global__ void k_gsum(const float* __restrict__ pos, const int* __restrict__ batch) {
    int n = blockIdx.x * blockDim.x + threadIdx.x;
    if (n >= Nn) return;
    int b = batch[n];
    atomicAdd(&g_gsum[b * 4 + 0], pos[n * 3 + 0]);
    atomicAdd(&g_gsum[b * 4 + 1], pos[n * 3 + 1]);
    atomicAdd(&g_gsum[b * 4 + 2], pos[n * 3 + 2]);
    atomicAdd(&g_gsum[b * 4 + 3], 1.f);
}

__global__ void k_grid_node(const int* __restrict__ batch,
                            const float* __restrict__ grid0,
                            const float* __restrict__ R) {
    int idx = blockIdx.x * blockDim.x + threadIdx.x;  // n*NG + k
    if (idx >= Nn * NGg) return;
    int n = idx / NGg, k = idx % NGg;
    const float* Rb = R + batch[n] * 9;
    float gx = grid0[k * 3 + 0], gy = grid0[k * 3 + 1], gz = grid0[k * 3 + 2];
    float* o = g_grid_node + idx * 3;
    o[0] = Rb[0] * gx + Rb[1] * gy + Rb[2] * gz;
    o[1] = Rb[3] * gx + Rb[4] * gy + Rb[5] * gz;
    o[2] = Rb[6] * gx + Rb[7] * gy + Rb[8] * gz;
}

__global__ void k_fipoly(const float* __restrict__ grid0) {
    int idx = threadIdx.x;
    if (idx >= NGg * NGg) return;
    int p = idx / NGg, o = idx % NGg;
    float fi = grid0[p * 3 + 0] * grid0[o * 3 + 0] +
               grid0[p * 3 + 1] * grid0[o * 3 + 1] +
               grid0[p * 3 + 2] * grid0[o * 3 + 2];
    g_fipoly[idx * 2 + 0] = fi;
    g_fipoly[idx * 2 + 1] = fi * fi;
}

// naive GEMM for tiny fiber matrices (M=144) — fp32, negligible time
__global__ void k_small_gemm(const float* __restrict__ A, const float* __restrict__ W,
                             const float* __restrict__ bias, float* __restrict__ C,
                             int M, int N, int K, int act) {
    int idx = blockIdx.x * blockDim.x + threadIdx.x;
    if (idx >= M * N) return;
    int r = idx / N, c = idx % N;
    float acc = bias ? bias[c] : 0.f;
    for (int k = 0; k < K; k++) acc = fmaf(A[r * K + k], W[k * N + c], acc);
    C[idx] = act ? gelu_f(acc) : acc;
}

__global__ void k_embed(const float* __restrict__ pos, const float* __restrict__ vel,
                        const float* __restrict__ charges, const int* __restrict__ batch,
                        const float* __restrict__ We) {
    int nk = blockIdx.x;           // n*NG + k
    int h = threadIdx.x;           // 0..127
    int n = nk / NGg;
    const float* g = g_grid_node + nk * 3;
    float vx = vel[n * 3 + 0], vy = vel[n * 3 + 1], vz = vel[n * 3 + 2];
    int b = batch[n];
    float cnt = fmaxf(g_gsum[b * 4 + 3], 1.f);
    float rpx = pos[n * 3 + 0] - g_gsum[b * 4 + 0] / cnt;
    float rpy = pos[n * 3 + 1] - g_gsum[b * 4 + 1] / cnt;
    float rpz = pos[n * 3 + 2] - g_gsum[b * 4 + 2] / cnt;
    float f0 = vx * g[0] + vy * g[1] + vz * g[2];
    float f1 = rpx * g[0] + rpy * g[1] + rpz * g[2];
    float f2 = charges[n];
    float f3 = sqrtf(vx * vx + vy * vy + vz * vz);
    g_x[(size_t)nk * Hh + h] =
        f0 * We[h] + f1 * We[Hh + h] + f2 * We[2 * Hh + h] + f3 * We[3 * Hh + h];
}

// ---------------- CSR build (by destination) ------------------------------------
__global__ void k_count(const int* __restrict__ eidx) {
    int e = blockIdx.x * blockDim.x + threadIdx.x;
    if (e >= Ee) return;
    atomicAdd(&g_deg[eidx[Ee + e]], 1);
}

__global__ void k_scan() {
    __shared__ int sh[1024];
    int tid = threadIdx.x;
    int base = tid * 4;
    int v[4];
    int s0 = 0;
#pragma unroll
    for (int i = 0; i < 4; i++) {
        int idx = base + i;
        v[i] = (idx < Nn) ? g_deg[idx] : 0;
        s0 += v[i];
    }
    sh[tid] = s0;
    __syncthreads();
    for (int off = 1; off < 1024; off <<= 1) {
        int t = (tid >= off) ? sh[tid - off] : 0;
        __syncthreads();
        sh[tid] += t;
        __syncthreads();
    }
    int ex = sh[tid] - s0;
#pragma unroll
    for (int i = 0; i < 4; i++) {
        int idx = base + i;
        if (idx < Nn) { g_off[idx] = ex; ex += v[i]; }
    }
    if (tid == 1023) g_off[Nn] = sh[1023];
}

__global__ void k_fill(const int* __restrict__ eidx) {
    int e = blockIdx.x * blockDim.x + threadIdx.x;
    if (e >= Ee) return;
    int d = eidx[Ee + e];
    int pos = g_off[d] + atomicAdd(&g_cur[d], 1);
    g_csr[pos] = e;
}

// ---------------- fused gather + fiber contraction + LayerNorm ------------------
__global__ void __launch_bounds__(128) k_gather_fiber_ln(
    const int* __restrict__ eidx, const __half* __restrict__ kern,
    const float* __restrict__ bconv, const float* __restrict__ gamma,
    const float* __restrict__ beta) {
    int n = blockIdx.x;
    int c = threadIdx.x;
    float acc[NGg];
#pragma unroll
    for (int o = 0; o < NGg; o++) acc[o] = 0.f;

    const int beg = g_off[n], end = g_off[n + 1];
    for (int j = beg; j < end; j++) {
        int e = g_csr[j];
        int s = eidx[e];
        const __half* kr = &kern[(size_t)e * NGg * Hh + c];
        const float* xr = &g_x[(size_t)s * NGg * Hh + c];
#pragma unroll
        for (int o = 0; o < NGg; o++)
            acc[o] = fmaf(__half2float(__ldcs(kr + o * Hh)), xr[o * Hh], acc[o]);
    }

    __shared__ float red[4];
    for (int p = 0; p < NGg; p++) {
        float v = 0.f;
        const float* fkp = &g_fk[(size_t)p * NGg * Hh + c];
#pragma unroll
        for (int o = 0; o < NGg; o++)
            v = fmaf(acc[o], fkp[o * Hh], v);
        v = v * (1.0f / NGg) + bconv[c];

        float s = v;
#pragma unroll
        for (int off = 16; off > 0; off >>= 1) s += __shfl_down_sync(0xffffffffu, s, off);
        if ((c & 31) == 0) red[c >> 5] = s;
        __syncthreads();
        float mean = (red[0] + red[1] + red[2] + red[3]) * (1.f / Hh);
        __syncthreads();
        float dd = v - mean;
        s = dd * dd;
#pragma unroll
        for (int off = 16; off > 0; off >>= 1) s += __shfl_down_sync(0xffffffffu, s, off);
        if ((c & 31) == 0) red[c >> 5] = s;
        __syncthreads();
        float var = (red[0] + red[1] + red[2] + red[3]) * (1.f / Hh);
        g_x2[((size_t)n * NGg + p) * Hh + c] = dd * rsqrtf(var + 1e-5f) * gamma[c] + beta[c];
        __syncthreads();
    }
}

// out[n,d] = (1/NG) sum_k grid_node[n,k,d] * (t[n,k,:]·W_ro2 + b_ro2)
__global__ void k_output(const float* __restrict__ Wro2, const float* __restrict__ bro2,
                         float* __restrict__ out) {
    int n = blockIdx.x;
    int h = threadIdx.x;
    __shared__ float red[4];
    __shared__ float ybc;
    float a0 = 0.f, a1 = 0.f, a2 = 0.f;
    for (int k = 0; k < NGg; k++) {
        float s = g_ro[((size_t)(n * NGg + k)) * Hh + h] * Wro2[h];
#pragma unroll
        for (int off = 16; off > 0; off >>= 1) s += __shfl_down_sync(0xffffffffu, s, off);
        if ((h & 31) == 0) red[h >> 5] = s;
        __syncthreads();
        if (h == 0) ybc = red[0] + red[1] + red[2] + red[3] + bro2[0];
        __syncthreads();
        float y = ybc;
        a0 += g_grid_node[(n * NGg + k) * 3 + 0] * y;
        a1 += g_grid_node[(n * NGg + k) * 3 + 1] * y;
        a2 += g_grid_node[(n * NGg + k) * 3 + 2] * y;
        __syncthreads();
    }
    if (h == 0) {
        out[n * 3 + 0] = a0 * (1.f / NGg);
        out[n * 3 + 1] = a1 * (1.f / NGg);
        out[n * 3 + 2] = a2 * (1.f / NGg);
    }
}

// ---------------- bf16x3 tensor-core GEMM (≈fp32 accuracy) ---------------------
constexpr int BM = 128, BN = 128, BK = 32;
constexpr int ASTRIDE = BK + 8;      // 40 bf16/row -> conflict-free ldmatrix
constexpr int BSTRIDE = BN + 8;      // 136 bf16/row -> conflict-free ldmatrix(.trans)

__device__ __forceinline__ void mma_bf16(float* d, const uint32_t* a, const uint32_t* b) {
    asm volatile(
        "mma.sync.aligned.m16n8k16.row.col.f32.bf16.bf16.f32 "
        "{%0,%1,%2,%3}, {%4,%5,%6,%7}, {%8,%9}, {%0,%1,%2,%3};\n"
        : "+f"(d[0]), "+f"(d[1]), "+f"(d[2]), "+f"(d[3])
        : "r"(a[0]), "r"(a[1]), "r"(a[2]), "r"(a[3]), "r"(b[0]), "r"(b[1]));
}

__device__ __forceinline__ void mma_tf32(float* d, const float* a, const float* b) {
    asm volatile(
        "mma.sync.aligned.m16n8k8.row.col.f32.tf32.tf32.f32 "
        "{%0,%1,%2,%3}, {%4,%5,%6,%7}, {%8,%9}, {%0,%1,%2,%3};\n"
        : "+f"(d[0]), "+f"(d[1]), "+f"(d[2]), "+f"(d[3])
        : "r"(__float_as_uint(a[0])), "r"(__float_as_uint(a[1])),
          "r"(__float_as_uint(a[2])), "r"(__float_as_uint(a[3])),
          "r"(__float_as_uint(b[0])), "r"(__float_as_uint(b[1])));
}

__device__ __forceinline__ void ldm_x4(uint32_t* r, const __nv_bfloat16* p) {
    uint32_t addr = (uint32_t)__cvta_generic_to_shared(p);
    asm volatile("ldmatrix.sync.aligned.m8n8.x4.shared.b16 {%0,%1,%2,%3}, [%4];"
                 : "=r"(r[0]), "=r"(r[1]), "=r"(r[2]), "=r"(r[3]) : "r"(addr));
}

__device__ __forceinline__ void ldm_x2t(uint32_t* r, const __nv_bfloat16* p) {
    uint32_t addr = (uint32_t)__cvta_generic_to_shared(p);
    asm volatile("ldmatrix.sync.aligned.m8n8.x2.trans.shared.b16 {%0,%1}, [%2];"
                 : "=r"(r[0]), "=r"(r[1]) : "r"(addr));
}

__device__ __forceinline__ void split_bf16(float v, __nv_bfloat16& hi, __nv_bfloat16& lo) {
    hi = __float2bfloat16_rn(v);
    lo = __float2bfloat16_rn(v - __bfloat162float(hi));
}

template <bool GELU, bool ACCUM>
__global__ void __launch_bounds__(256, 2) gemm_bf16x3(
    const float* __restrict__ A, const float* __restrict__ Bw,
    const float* __restrict__ bias, float* __restrict__ C,
    int M, int N, int K) {
    __shared__ __nv_bfloat16 As1[BM][ASTRIDE];
    __shared__ __nv_bfloat16 As2[BM][ASTRIDE];
    __shared__ __nv_bfloat16 Bs1[BK][BSTRIDE];
    __shared__ __nv_bfloat16 Bs2[BK][BSTRIDE];

    const int tid  = threadIdx.x;
    const int lane = tid & 31;
    const int warp = tid >> 5;
    const int wm = warp & 1;
    const int wn = warp >> 1;
    const int br = blockIdx.x * BM;
    const int bc = blockIdx.y * BN;
    const int gid = lane >> 2;
    const int qid = lane & 3;

    float acc[4][4][4];
#pragma unroll
    for (int mt = 0; mt < 4; mt++)
#pragma unroll
        for (int nt = 0; nt < 4; nt++)
#pragma unroll
            for (int j = 0; j < 4; j++) acc[mt][nt][j] = 0.f;

    const int aRow = ((lane >> 3) & 1) * 8 + (lane & 7);
    const int aKof = (lane >> 4) * 8;
    const int bK   = lane & 15;

    const int ktiles = (K + BK - 1) / BK;
    for (int kt = 0; kt < ktiles; kt++) {
        const int k0 = kt * BK;
#pragma unroll
        for (int it = 0; it < 4; it++) {
            int f = it * 256 + tid;
            int row = f >> 3, kq = (f & 7) * 4;
            float4 v = make_float4(0.f, 0.f, 0.f, 0.f);
            int gr = br + row;
            if (gr < M && (k0 + kq) < K)
                v = *reinterpret_cast<const float4*>(&A[(size_t)gr * K + k0 + kq]);
            __nv_bfloat16 h0, h1, h2, h3, l0, l1, l2, l3;
            split_bf16(v.x, h0, l0); split_bf16(v.y, h1, l1);
            split_bf16(v.z, h2, l2); split_bf16(v.w, h3, l3);
            *reinterpret_cast<__nv_bfloat162*>(&As1[row][kq])     = __nv_bfloat162(h0, h1);
            *reinterpret_cast<__nv_bfloat162*>(&As1[row][kq + 2]) = __nv_bfloat162(h2, h3);
            *reinterpret_cast<__nv_bfloat162*>(&As2[row][kq])     = __nv_bfloat162(l0, l1);
            *reinterpret_cast<__nv_bfloat162*>(&As2[row][kq + 2]) = __nv_bfloat162(l2, l3);
        }
#pragma unroll
        for (int it = 0; it < 4; it++) {
            int f = it * 256 + tid;
            int krow = f >> 5, n4 = (f & 31) * 4;
            float4 v = make_float4(0.f, 0.f, 0.f, 0.f);
            if ((k0 + krow) < K)
                v = *reinterpret_cast<const float4*>(&Bw[(size_t)(k0 + krow) * N + bc + n4]);
            __nv_bfloat16 h0, h1, h2, h3, l0, l1, l2, l3;
            split_bf16(v.x, h0, l0); split_bf16(v.y, h1, l1);
            split_bf16(v.z, h2, l2); split_bf16(v.w, h3, l3);
            *reinterpret_cast<__nv_bfloat162*>(&Bs1[krow][n4])     = __nv_bfloat162(h0, h1);
            *reinterpret_cast<__nv_bfloat162*>(&Bs1[krow][n4 + 2]) = __nv_bfloat162(h2, h3);
            *reinterpret_cast<__nv_bfloat162*>(&Bs2[krow][n4])     = __nv_bfloat162(l0, l1);
            *reinterpret_cast<__nv_bfloat162*>(&Bs2[krow][n4 + 2]) = __nv_bfloat162(l2, l3);
        }
        __syncthreads();

#pragma unroll
        for (int ks = 0; ks < 2; ks++) {
            const int kk = ks * 16;
            uint32_t bb[4][2], bs[4][2];
#pragma unroll
            for (int nt = 0; nt < 4; nt++) {
                const int n0 = wn * 32 + nt * 8;
                ldm_x2t(bb[nt], &Bs1[kk + bK][n0]);
                ldm_x2t(bs[nt], &Bs2[kk + bK][n0]);
            }
#pragma unroll
            for (int mt = 0; mt < 4; mt++) {
                const int r0 = wm * 64 + mt * 16 + aRow;
                uint32_t ah[4], al[4];
                ldm_x4(ah, &As1[r0][kk + aKof]);
                ldm_x4(al, &As2[r0][kk + aKof]);
#pragma unroll
                for (int nt = 0; nt < 4; nt++) {
                    mma_bf16(acc[mt][nt], al, bb[nt]);
                    mma_bf16(acc[mt][nt], ah, bs[nt]);
                    mma_bf16(acc[mt][nt], ah, bb[nt]);
                }
            }
        }
        __syncthreads();
    }

#pragma unroll
    for (int nt = 0; nt < 4; nt++) {
        const int c = bc + wn * 32 + nt * 8 + qid * 2;
        float b0 = 0.f, b1 = 0.f;
        if (bias) { b0 = bias[c]; b1 = bias[c + 1]; }
#pragma unroll
        for (int mt = 0; mt < 4; mt++) {
            int r0 = br + wm * 64 + mt * 16 + gid;
#pragma unroll
            for (int half = 0; half < 2; half++) {
                int r = r0 + half * 8;
                if (r >= M) continue;
                float v0 = acc[mt][nt][half * 2 + 0] + b0;
                float v1 = acc[mt][nt][half * 2 + 1] + b1;
                if (GELU) { v0 = gelu_f(v0); v1 = gelu_f(v1); }
                float2* p = reinterpret_cast<float2*>(&C[(size_t)r * N + c]);
                if (ACCUM) {
                    float2 o = *p;
                    o.x += v0; o.y += v1;
                    *p = o;
                } else {
                    *p = make_float2(v0, v1);
                }
            }
        }
    }
}

// ---------------- shared helpers for smem-A fused kernels -----------------------
constexpr int A2S = 136;
constexpr int BTILE = BK * BSTRIDE;

__device__ __forceinline__ void split_store_B(__nv_bfloat16* B1, __nv_bfloat16* B2,
                                              int tid, const float4* v) {
#pragma unroll
    for (int it = 0; it < 4; it++) {
        int f = it * 256 + tid;
        int krow = f >> 5, n4 = (f & 31) * 4;
        __nv_bfloat16 h0, h1, h2, h3, l0, l1, l2, l3;
        split_bf16(v[it].x, h0, l0); split_bf16(v[it].y, h1, l1);
        split_bf16(v[it].z, h2, l2); split_bf16(v[it].w, h3, l3);
        *reinterpret_cast<__nv_bfloat162*>(&B1[krow * BSTRIDE + n4])     = __nv_bfloat162(h0, h1);
        *reinterpret_cast<__nv_bfloat162*>(&B1[krow * BSTRIDE + n4 + 2]) = __nv_bfloat162(h2, h3);
        *reinterpret_cast<__nv_bfloat162*>(&B2[krow * BSTRIDE + n4])     = __nv_bfloat162(l0, l1);
        *reinterpret_cast<__nv_bfloat162*>(&B2[krow * BSTRIDE + n4 + 2]) = __nv_bfloat162(l2, l3);
    }
}

__device__ __forceinline__ void load_B_tile(const float* __restrict__ Bw, int ldb,
                                            int tid, int k0, float4* v) {
#pragma unroll
    for (int it = 0; it < 4; it++) {
        int f = it * 256 + tid;
        int krow = f >> 5, n4 = (f & 31) * 4;
        v[it] = *reinterpret_cast<const float4*>(&Bw[(size_t)(k0 + krow) * ldb + n4]);
    }
}

// ---------------- fully fused edge chain (tf32 mainloops) -----------------------
// features -> h1 -> basis (all smem, fp32/tf32) -> kern0, kern1 (fp16 out).
// A tile fp32 [128][132]: frag LDS bank = (4*gid + qid) mod 32 -> conflict-free.
constexpr int A4S = 132;
constexpr int BT4 = BK * A4S;                                      // floats/buffer
constexpr size_t FK_OFF_B = (size_t)BM * A4S * 4;                  // 67584
constexpr size_t FK_SMEM  = FK_OFF_B + (size_t)2 * BT4 * 4;        // 101376

__device__ __forceinline__ void tf32_store_B(float* B, int tid, const float4* v) {
#pragma unroll
    for (int it = 0; it < 4; it++) {
        int f = it * 256 + tid;
        int krow = f >> 5, n4 = (f & 31) * 4;
        float4 cv = make_float4(to_tf32(v[it].x), to_tf32(v[it].y),
                                to_tf32(v[it].z), to_tf32(v[it].w));
        *reinterpret_cast<float4*>(&B[krow * A4S + n4]) = cv;
    }
}

// one full K=128 tf32 mainloop vs row-major weights Bw [128][128]; B double-buffered
__device__ __forceinline__ void kt_mainloop(
    const float* __restrict__ As, float* __restrict__ BsBase,
    const float* __restrict__ Bw,
    int tid, int lane, int wm, int wn, float acc[4][4][4]) {
#pragma unroll
    for (int mt = 0; mt < 4; mt++)
#pragma unroll
        for (int nt = 0; nt < 4; nt++)
#pragma unroll
            for (int j = 0; j < 4; j++) acc[mt][nt][j] = 0.f;

    const int gid = lane >> 2;
    const int qid = lane & 3;

    float4 v[4];
    load_B_tile(Bw, Hh, tid, 0, v);
    tf32_store_B(BsBase, tid, v);
    __syncthreads();

#pragma unroll
    for (int kt = 0; kt < 4; kt++) {
        const int k0 = kt * BK;
        if (kt < 3) load_B_tile(Bw, Hh, tid, k0 + BK, v);
        const float* B = BsBase + (kt & 1) * BT4;
#pragma unroll
        for (int ks = 0; ks < 4; ks++) {
            const int kk = ks * 8;
            float bf[4][2];
#pragma unroll
            for (int nt = 0; nt < 4; nt++) {
                const int n0 = wn * 32 + nt * 8 + gid;
                bf[nt][0] = B[(kk + qid) * A4S + n0];
                bf[nt][1] = B[(kk + 4 + qid) * A4S + n0];
            }
#pragma unroll
            for (int mt = 0; mt < 4; mt++) {
                const int r0 = wm * 64 + mt * 16 + gid;
                const int ac = k0 + kk + qid;
                float af[4];
                af[0] = As[r0 * A4S + ac];
                af[1] = As[(r0 + 8) * A4S + ac];
                af[2] = As[r0 * A4S + ac + 4];
                af[3] = As[(r0 + 8) * A4S + ac + 4];
#pragma unroll
                for (int nt = 0; nt < 4; nt++)
                    mma_tf32(acc[mt][nt], af, bf[nt]);
            }
        }
        if (kt < 3) tf32_store_B(BsBase + ((kt + 1) & 1) * BT4, tid, v);
        __syncthreads();
    }
}

__global__ void __launch_bounds__(256, 2) k_basis_kern(
    const float* __restrict__ pos, const float* __restrict__ charges,
    const int* __restrict__ eidx,
    const float* __restrict__ W1, const float* __restrict__ b1,
    const float* __restrict__ W2, const float* __restrict__ b2,
    const float* __restrict__ Wc,     // [2][128][128]
    __half* __restrict__ kern0, __half* __restrict__ kern1, int M) {
    extern __shared__ char smraw[];
    float* As = reinterpret_cast<float*>(smraw);                   // [128][132] fp32
    float* Bs = reinterpret_cast<float*>(smraw + FK_OFF_B);        // 2x[32][132] fp32
    // phase-0/1 staging union (inside B region): EIP[1536], W1s[1536], b1s[128]
    float* EIP = Bs;
    float* W1s = EIP + BM * 12;
    float* b1s = W1s + 12 * Hh;

    const int tid  = threadIdx.x;
    const int lane = tid & 31;
    const int warp = tid >> 5;
    const int wm = warp & 1;
    const int wn = warp >> 1;
    const int br = blockIdx.x * BM;
    const int gid = lane >> 2;
    const int qid = lane & 3;

    // ---- phase 0: compute edge-invariant features in-kernel (one row/thread) ----
    for (int f = tid; f < 12 * Hh; f += 256) W1s[f] = W1[f];
    if (tid < Hh) b1s[tid] = b1[tid];
    if (tid < BM) {
        int row = br + tid;
        float f0 = 0.f, f1 = 0.f, f2 = 0.f;
        if (row < M) {
            int e = row / NGg;
            int k = row - e * NGg;
            int s = eidx[e], d = eidx[Ee + e];
            float rx = pos[s * 3 + 0] - pos[d * 3 + 0];
            float ry = pos[s * 3 + 1] - pos[d * 3 + 1];
            float rz = pos[s * 3 + 2] - pos[d * 3 + 2];
            const float* g = g_grid_node + (s * NGg + k) * 3;
            float inv1 = rx * g[0] + ry * g[1] + rz * g[2];
            float vx = rx - inv1 * g[0], vy = ry - inv1 * g[1], vz = rz - inv1 * g[2];
            float inv2 = sqrtf(vx * vx + vy * vy + vz * vz);
            f0 = inv1; f1 = inv2; f2 = charges[s] * charges[d];
        }
        float* o = &EIP[tid * 12];
        o[0] = f0;  o[1] = f1;  o[2] = f2;
        o[3] = f0 * f0; o[4]  = f0 * f1; o[5]  = f0 * f2;
        o[6] = f1 * f0; o[7]  = f1 * f1; o[8]  = f1 * f2;
        o[9] = f2 * f0; o[10] = f2 * f1; o[11] = f2 * f2;
    }
    __syncthreads();

    // ---- phase 1: h1 = gelu(eip@W1 + b1) -> As (tf32-rounded fp32, persistent) --
    {
        const int r  = tid >> 1;
        const int cb = (tid & 1) * 64;
        float e[12];
#pragma unroll
        for (int k = 0; k < 12; k++) e[k] = EIP[r * 12 + k];
#pragma unroll
        for (int c2 = 0; c2 < 64; c2 += 2) {
            int c = cb + c2;
            float a0 = 0.f, a1 = 0.f;
#pragma unroll
            for (int k = 0; k < 12; k++) {
                a0 = fmaf(e[k], W1s[k * Hh + c], a0);
                a1 = fmaf(e[k], W1s[k * Hh + c + 1], a1);
            }
            a0 = to_tf32(gelu_f(a0 + b1s[c]));
            a1 = to_tf32(gelu_f(a1 + b1s[c + 1]));
            *reinterpret_cast<float2*>(&As[r * A4S + c]) = make_float2(a0, a1);
        }
    }
    __syncthreads();   // staging reads done; B region free for Bs buffers

    float acc[4][4][4];

    // ---- phase 2: basis = gelu(h1 @ W2 + b2) -> back into As (smem only) ----
    kt_mainloop(As, Bs, W2, tid, lane, wm, wn, acc);
    {
#pragma unroll
        for (int nt = 0; nt < 4; nt++) {
            const int c = wn * 32 + nt * 8 + qid * 2;
            float bb0 = b2[c], bb1 = b2[c + 1];
#pragma unroll
            for (int mt = 0; mt < 4; mt++) {
                int rl = wm * 64 + mt * 16 + gid;
#pragma unroll
                for (int half = 0; half < 2; half++) {
                    int r = rl + half * 8;
                    float v0 = to_tf32(gelu_f(acc[mt][nt][half * 2 + 0] + bb0));
                    float v1 = to_tf32(gelu_f(acc[mt][nt][half * 2 + 1] + bb1));
                    *reinterpret_cast<float2*>(&As[r * A4S + c]) = make_float2(v0, v1);
                }
            }
        }
    }
    __syncthreads();

    // ---- phase 3: kern_l = basis @ W_conv[l], l = 0,1 (fp16 streaming stores) ----
#pragma unroll
    for (int l = 0; l < 2; l++) {
        kt_mainloop(As, Bs, Wc + (size_t)l * BDd * Hh, tid, lane, wm, wn, acc);
        __half* kern = l == 0 ? kern0 : kern1;
#pragma unroll
        for (int nt = 0; nt < 4; nt++) {
            const int c = wn * 32 + nt * 8 + qid * 2;
#pragma unroll
            for (int mt = 0; mt < 4; mt++) {
                int r0 = br + wm * 64 + mt * 16 + gid;
#pragma unroll
                for (int half = 0; half < 2; half++) {
                    int r = r0 + half * 8;
                    if (r >= M) continue;
                    __half2 hv = __floats2half2_rn(acc[mt][nt][half * 2 + 0],
                                                   acc[mt][nt][half * 2 + 1]);
                    __stcs(reinterpret_cast<unsigned int*>(&kern[(size_t)r * Hh + c]),
                           *reinterpret_cast<unsigned int*>(&hv));
                }
            }
        }
    }
}

// ---------------- fused FF block: x += W_ff2 @ gelu(W_ff1 @ x2)  -----------------
// BM=64 rows/block; hidden (512) processed in 4 chunks of 128; h never leaves smem.
constexpr int FBM = 64;
constexpr size_t FF_OFF_AX1 = 0;
constexpr size_t FF_OFF_AX2 = FF_OFF_AX1 + (size_t)FBM * A2S * 2;   // 17408
constexpr size_t FF_OFF_AH1 = FF_OFF_AX2 + (size_t)FBM * A2S * 2;   // 34816
constexpr size_t FF_OFF_AH2 = FF_OFF_AH1 + (size_t)FBM * A2S * 2;   // 52224
constexpr size_t FF_OFF_B1  = FF_OFF_AH2 + (size_t)FBM * A2S * 2;   // 69632 (2 bufs)
constexpr size_t FF_OFF_B2  = FF_OFF_B1 + (size_t)2 * BTILE * 2;    // 87040 (2 bufs)
constexpr size_t FF_SMEM    = FF_OFF_B2 + (size_t)2 * BTILE * 2;    // 104448

// K=128 mainloop, 64-row A in smem, warp tile 32x32. CLEAR selects init vs accum.
template <bool CLEAR>
__device__ __forceinline__ void ff_mainloop(
    const __nv_bfloat16* __restrict__ A1, const __nv_bfloat16* __restrict__ A2,
    __nv_bfloat16* Bs1, __nv_bfloat16* Bs2,
    const float* __restrict__ Bw, int ldb,
    int tid, int wm, int wn, int aRow, int aKof, int bKl,
    float acc[2][4][4]) {
    if (CLEAR) {
#pragma unroll
        for (int mt = 0; mt < 2; mt++)
#pragma unroll
            for (int nt = 0; nt < 4; nt++)
#pragma unroll
                for (int j = 0; j < 4; j++) acc[mt][nt][j] = 0.f;
    }
    float4 v[4];
    load_B_tile(Bw, ldb, tid, 0, v);
    split_store_B(Bs1, Bs2, tid, v);
    __syncthreads();

#pragma unroll
    for (int kt = 0; kt < 4; kt++) {
        const int k0 = kt * BK;
        if (kt < 3) load_B_tile(Bw, ldb, tid, k0 + BK, v);
        const __nv_bfloat16* B1 = Bs1 + (kt & 1) * BTILE;
        const __nv_bfloat16* B2 = Bs2 + (kt & 1) * BTILE;
#pragma unroll
        for (int ks = 0; ks < 2; ks++) {
            const int kk = ks * 16;
            uint32_t bb[4][2], bs[4][2];
#pragma unroll
            for (int nt = 0; nt < 4; nt++) {
                const int n0 = wn * 32 + nt * 8;
                ldm_x2t(bb[nt], &B1[(kk + bKl) * BSTRIDE + n0]);
                ldm_x2t(bs[nt], &B2[(kk + bKl) * BSTRIDE + n0]);
            }
#pragma unroll
            for (int mt = 0; mt < 2; mt++) {
                const int r0 = wm * 32 + mt * 16 + aRow;
                uint32_t ah[4], al[4];
                ldm_x4(ah, &A1[r0 * A2S + k0 + kk + aKof]);
                ldm_x4(al, &A2[r0 * A2S + k0 + kk + aKof]);
#pragma unroll
                for (int nt = 0; nt < 4; nt++) {
                    mma_bf16(acc[mt][nt], al, bb[nt]);
                    mma_bf16(acc[mt][nt], ah, bs[nt]);
                    mma_bf16(acc[mt][nt], ah, bb[nt]);
                }
            }
        }
        if (kt < 3) split_store_B(Bs1 + ((kt + 1) & 1) * BTILE,
                                  Bs2 + ((kt + 1) & 1) * BTILE, tid, v);
        __syncthreads();
    }
}

__global__ void __launch_bounds__(256, 2) k_ff_fused(
    const float* __restrict__ x2, const float* __restrict__ Wff1,
    const float* __restrict__ bff1, const float* __restrict__ Wff2,
    const float* __restrict__ bff2, float* __restrict__ x, int M) {
    extern __shared__ char smraw[];
    __nv_bfloat16* Ax1 = reinterpret_cast<__nv_bfloat16*>(smraw + FF_OFF_AX1);
    __nv_bfloat16* Ax2 = reinterpret_cast<__nv_bfloat16*>(smraw + FF_OFF_AX2);
    __nv_bfloat16* Ah1 = reinterpret_cast<__nv_bfloat16*>(smraw + FF_OFF_AH1);
    __nv_bfloat16* Ah2 = reinterpret_cast<__nv_bfloat16*>(smraw + FF_OFF_AH2);
    __nv_bfloat16* Bs1 = reinterpret_cast<__nv_bfloat16*>(smraw + FF_OFF_B1);
    __nv_bfloat16* Bs2 = reinterpret_cast<__nv_bfloat16*>(smraw + FF_OFF_B2);

    const int tid  = threadIdx.x;
    const int lane = tid & 31;
    const int warp = tid >> 5;
    const int wm = warp & 1;             // 2 warps along M (32 rows each)
    const int wn = warp >> 1;            // 4 warps along N (32 cols each)
    const int br = blockIdx.x * FBM;
    const int gid = lane >> 2;
    const int qid = lane & 3;
    const int aRow = ((lane >> 3) & 1) * 8 + (lane & 7);
    const int aKof = (lane >> 4) * 8;
    const int bKl  = lane & 15;

    // stage x2 tile (64 x 128 fp32) -> split bf16 Ax
#pragma unroll
    for (int it = 0; it < 8; it++) {
        int f = it * 256 + tid;
        int row = f >> 5, kq = (f & 31) * 4;
        float4 v = make_float4(0.f, 0.f, 0.f, 0.f);
        int gr = br + row;
        if (gr < M)
            v = *reinterpret_cast<const float4*>(&x2[(size_t)gr * Hh + kq]);
        __nv_bfloat16 h0, h1, h2, h3, l0, l1, l2, l3;
        split_bf16(v.x, h0, l0); split_bf16(v.y, h1, l1);
        split_bf16(v.z, h2, l2); split_bf16(v.w, h3, l3);
        *reinterpret_cast<__nv_bfloat162*>(&Ax1[row * A2S + kq])     = __nv_bfloat162(h0, h1);
        *reinterpret_cast<__nv_bfloat162*>(&Ax1[row * A2S + kq + 2]) = __nv_bfloat162(h2, h3);
        *reinterpret_cast<__nv_bfloat162*>(&Ax2[row * A2S + kq])     = __nv_bfloat162(l0, l1);
        *reinterpret_cast<__nv_bfloat162*>(&Ax2[row * A2S + kq + 2]) = __nv_bfloat162(l2, l3);
    }
    __syncthreads();

    float acc1[2][4][4];
    float acc2[2][4][4];
#pragma unroll
    for (int mt = 0; mt < 2; mt++)
#pragma unroll
        for (int nt = 0; nt < 4; nt++)
#pragma unroll
            for (int j = 0; j < 4; j++) acc2[mt][nt][j] = 0.f;

#pragma unroll
    for (int chunk = 0; chunk < 4; chunk++) {
        // h_chunk = gelu(x2 @ W_ff1[:, chunk*128 : +128] + b_ff1[chunk])
        ff_mainloop<true>(Ax1, Ax2, Bs1, Bs2, Wff1 + chunk * Hh, 4 * Hh,
                          tid, wm, wn, aRow, aKof, bKl, acc1);
#pragma unroll
        for (int nt = 0; nt < 4; nt++) {
            const int c = wn * 32 + nt * 8 + qid * 2;
            float bb0 = bff1[chunk * Hh + c], bb1 = bff1[chunk * Hh + c + 1];
#pragma unroll
            for (int mt = 0; mt < 2; mt++) {
                int rl = wm * 32 + mt * 16 + gid;
#pragma unroll
                for (int half = 0; half < 2; half++) {
                    int r = rl + half * 8;
                    float v0 = gelu_f(acc1[mt][nt][half * 2 + 0] + bb0);
                    float v1 = gelu_f(acc1[mt][nt][half * 2 + 1] + bb1);
                    __nv_bfloat16 h0, l0, h1, l1;
                    split_bf16(v0, h0, l0);
                    split_bf16(v1, h1, l1);
                    *reinterpret_cast<__nv_bfloat162*>(&Ah1[r * A2S + c]) = __nv_bfloat162(h0, h1);
                    *reinterpret_cast<__nv_bfloat162*>(&Ah2[r * A2S + c]) = __nv_bfloat162(l0, l1);
                }
            }
        }
        // acc2 += h_chunk @ W_ff2[chunk*128 : +128, :]
        ff_mainloop<false>(Ah1, Ah2, Bs1, Bs2, Wff2 + (size_t)chunk * Hh * Hh, Hh,
                           tid, wm, wn, aRow, aKof, bKl, acc2);
    }

    // epilogue: x += acc2 + b_ff2
#pragma unroll
    for (int nt = 0; nt < 4; nt++) {
        const int c = wn * 32 + nt * 8 + qid * 2;
        float bb0 = bff2[c], bb1 = bff2[c + 1];
#pragma unroll
        for (int mt = 0; mt < 2; mt++) {
            int r0 = br + wm * 32 + mt * 16 + gid;
#pragma unroll
            for (int half = 0; half < 2; half++) {
                int r = r0 + half * 8;
                if (r >= M) continue;
                float2* p = reinterpret_cast<float2*>(&x[(size_t)r * Hh + c]);
                float2 o = *p;
                o.x += acc2[mt][nt][half * 2 + 0] + bb0;
                o.y += acc2[mt][nt][half * 2 + 1] + bb1;
                *p = o;
            }
        }
    }
}

// ---------------- host launch ----------------------------------------------------
static void launch_gemm(const float* A, const float* W, const float* bias, float* C,
                        int M, int N, int K, bool gelu_act, bool accum) {
    dim3 grid((M + BM - 1) / BM, N / BN);
    if (gelu_act)   gemm_bf16x3<true, false><<<grid, 256>>>(A, W, bias, C, M, N, K);
    else if (accum) gemm_bf16x3<false, true><<<grid, 256>>>(A, W, bias, C, M, N, K);
    else            gemm_bf16x3<false, false><<<grid, 256>>>(A, W, bias, C, M, N, K);
}

extern "C" void kernel_launch(void* const* d_in, const int* in_sizes, int n_in,
                              void* d_out, int out_size) {
    const float* pos      = (const float*)d_in[0];
    const float* vel      = (const float*)d_in[1];
    const float* charges  = (const float*)d_in[2];
    const int*   batch    = (const int*)d_in[3];
    const int*   eidx     = (const int*)d_in[4];
    const float* grid0    = (const float*)d_in[5];
    const float* R        = (const float*)d_in[6];
    const float* W_basis1 = (const float*)d_in[7];
    const float* b_basis1 = (const float*)d_in[8];
    const float* W_basis2 = (const float*)d_in[9];
    const float* b_basis2 = (const float*)d_in[10];
    const float* W_fbasis1 = (const float*)d_in[11];
    const float* b_fbasis1 = (const float*)d_in[12];
    const float* W_fbasis2 = (const float*)d_in[13];
    const float* b_fbasis2 = (const float*)d_in[14];
    const float* W_embed  = (const float*)d_in[15];
    const float* W_conv   = (const float*)d_in[16];
    const float* W_fiber  = (const float*)d_in[17];
    const float* b_conv   = (const float*)d_in[18];
    const float* ln_gamma = (const float*)d_in[19];
    const float* ln_beta  = (const float*)d_in[20];
    const float* W_ff1    = (const float*)d_in[21];
    const float* b_ff1    = (const float*)d_in[22];
    const float* W_ff2    = (const float*)d_in[23];
    const float* b_ff2    = (const float*)d_in[24];
    const float* W_ro1    = (const float*)d_in[25];
    const float* b_ro1    = (const float*)d_in[26];
    const float* W_ro2    = (const float*)d_in[27];
    const float* b_ro2    = (const float*)d_in[28];
    float* out = (float*)d_out;

    float *x, *x2, *ro, *fip, *fh1, *fbasis, *fk;
    __half *kern0, *kern1;
    cudaGetSymbolAddress((void**)&kern0, g_kern0);
    cudaGetSymbolAddress((void**)&kern1, g_kern1);
    cudaGetSymbolAddress((void**)&x,     g_x);
    cudaGetSymbolAddress((void**)&x2,    g_x2);
    cudaGetSymbolAddress((void**)&ro,    g_ro);
    cudaGetSymbolAddress((void**)&fip,   g_fipoly);
    cudaGetSymbolAddress((void**)&fh1,   g_fh1);
    cudaGetSymbolAddress((void**)&fbasis,g_fbasis);
    cudaGetSymbolAddress((void**)&fk,    g_fk);

    static bool attr_done = false;
    if (!attr_done) {
        cudaFuncSetAttribute(k_basis_kern, cudaFuncAttributeMaxDynamicSharedMemorySize,
                             (int)FK_SMEM);
        cudaFuncSetAttribute(k_ff_fused, cudaFuncAttributeMaxDynamicSharedMemorySize,
                             (int)FF_SMEM);
        attr_done = true;
    }

    // init + graph statistics + rotated grids
    k_init<<<(Nn + 255) / 256, 256>>>();
    k_gsum<<<(Nn + 255) / 256, 256>>>(pos, batch);
    k_grid_node<<<(Nn * NGg + 255) / 256, 256>>>(batch, grid0, R);

    // CSR by destination (built once, reused by both layers)
    k_count<<<(Ee + 255) / 256, 256>>>(eidx);
    k_scan<<<1, 1024>>>();
    k_fill<<<(Ee + 255) / 256, 256>>>(eidx);

    // edge chain fully fused: features -> h1 -> basis (all smem) -> kern0, kern1
    k_basis_kern<<<(EROWS + BM - 1) / BM, 256, FK_SMEM>>>(
        pos, charges, eidx, W_basis1, b_basis1, W_basis2, b_basis2, W_conv,
        kern0, kern1, EROWS);

    // fiber basis MLP: 144 rows
    k_fipoly<<<1, 256>>>(grid0);
    k_small_gemm<<<(NGg * NGg * Hh + 255) / 256, 256>>>(fip, W_fbasis1, b_fbasis1, fh1,
                                                        NGg * NGg, Hh, 2, 1);
    k_small_gemm<<<(NGg * NGg * BDd + 255) / 256, 256>>>(fh1, W_fbasis2, b_fbasis2, fbasis,
                                                         NGg * NGg, BDd, Hh, 1);

    // node embedding
    k_embed<<<NROWS, Hh>>>(pos, vel, charges, batch, W_embed);

    for (int l = 0; l < Ll; l++) {
        // fk = fiber_basis @ W_fiber[l]
        k_small_gemm<<<(NGg * NGg * Hh + 255) / 256, 256>>>(
            fbasis, W_fiber + (size_t)l * BDd * Hh, nullptr, fk, NGg * NGg, Hh, BDd, 0);
        // fused: x1 = gather-sum(kern_l * x[src] -> dst); x2 = LN(fiber(x1))
        k_gather_fiber_ln<<<Nn, Hh>>>(eidx, l == 0 ? kern0 : kern1, b_conv + l * Hh,
                                      ln_gamma + l * Hh, ln_beta + l * Hh);
        // fused FF: x += W_ff2 @ gelu(W_ff1 @ x2)   (hidden never leaves smem)
        k_ff_fused<<<(NROWS + FBM - 1) / FBM, 256, FF_SMEM>>>(
            x2, W_ff1 + (size_t)l * Hh * 4 * Hh, b_ff1 + l * 4 * Hh,
            W_ff2 + (size_t)l * 4 * Hh * Hh, b_ff2 + l * Hh, x, NROWS);
    }

    // readout
    launch_gemm(x, W_ro1, b_ro1, ro, NROWS, Hh, Hh, true, false);
    k_output<<<Nn, Hh>>>(W_ro2, b_ro2, out);
}